// round 1
// baseline (speedup 1.0000x reference)
#include <cuda_runtime.h>
#include <cuda_bf16.h>
#include <cstdint>

// Problem constants (fixed by the dataset)
#define BATCH 2
#define SEQ   2048
#define DMODEL 1024
#define NHEAD 16
#define DHEAD 64
#define QKVDIM (3 * NHEAD * DHEAD)   // 3072
#define ROWS  (BATCH * SEQ)          // 4096

// Scratch (allocation-free rule: __device__ globals)
__device__ float g_qkv[(size_t)ROWS * QKVDIM];       // [b*s, 3072]
__device__ float g_attn[(size_t)ROWS * DMODEL];      // [b*s, 1024] attn output (pre-proj)

// ---------------------------------------------------------------------------
// Tiled fp32 SGEMM with bias: C[M,N] = A[M,K] @ B[K,N] + bias[N]
// BM=128, BN=128, BK=8, 256 threads, 8x8 per-thread microtile.
// Requires M%128==0, N%128==0, K%8==0 (true for all our shapes).
// ---------------------------------------------------------------------------
#define BM 128
#define BN 128
#define BK 8
#define TM 8
#define TN 8

__global__ __launch_bounds__(256) void sgemm_bias(
    const float* __restrict__ A, const float* __restrict__ B,
    const float* __restrict__ bias, float* __restrict__ C,
    int M, int N, int K)
{
    __shared__ float As[BK][BM];
    __shared__ float Bs[BK][BN];

    const int tid  = threadIdx.x;
    const int cRow = blockIdx.y * BM;
    const int cCol = blockIdx.x * BN;

    // A tile load: 128 rows x 8 cols -> one float4 per thread
    const int aRow = tid >> 1;            // 0..127
    const int aCol = (tid & 1) * 4;       // 0 or 4
    // B tile load: 8 rows x 128 cols -> one float4 per thread
    const int bRow = tid >> 5;            // 0..7
    const int bCol = (tid & 31) * 4;      // 0..124

    const int tx = tid & 15;              // 0..15 -> column group
    const int ty = tid >> 4;              // 0..15 -> row group

    float acc[TM][TN];
    #pragma unroll
    for (int i = 0; i < TM; i++)
        #pragma unroll
        for (int j = 0; j < TN; j++)
            acc[i][j] = 0.0f;

    const float* Aptr = A + (size_t)cRow * K;
    const float* Bptr = B + cCol;

    for (int k0 = 0; k0 < K; k0 += BK) {
        float4 a4 = *(const float4*)(Aptr + (size_t)aRow * K + k0 + aCol);
        As[aCol + 0][aRow] = a4.x;
        As[aCol + 1][aRow] = a4.y;
        As[aCol + 2][aRow] = a4.z;
        As[aCol + 3][aRow] = a4.w;

        float4 b4 = *(const float4*)(Bptr + (size_t)(k0 + bRow) * N + bCol);
        *(float4*)&Bs[bRow][bCol] = b4;

        __syncthreads();

        #pragma unroll
        for (int kk = 0; kk < BK; kk++) {
            float ra[TM], rb[TN];
            float4 ra0 = *(const float4*)&As[kk][ty * TM];
            float4 ra1 = *(const float4*)&As[kk][ty * TM + 4];
            ra[0]=ra0.x; ra[1]=ra0.y; ra[2]=ra0.z; ra[3]=ra0.w;
            ra[4]=ra1.x; ra[5]=ra1.y; ra[6]=ra1.z; ra[7]=ra1.w;
            float4 rb0 = *(const float4*)&Bs[kk][tx * TN];
            float4 rb1 = *(const float4*)&Bs[kk][tx * TN + 4];
            rb[0]=rb0.x; rb[1]=rb0.y; rb[2]=rb0.z; rb[3]=rb0.w;
            rb[4]=rb1.x; rb[5]=rb1.y; rb[6]=rb1.z; rb[7]=rb1.w;
            #pragma unroll
            for (int i = 0; i < TM; i++)
                #pragma unroll
                for (int j = 0; j < TN; j++)
                    acc[i][j] = fmaf(ra[i], rb[j], acc[i][j]);
        }
        __syncthreads();
    }

    #pragma unroll
    for (int i = 0; i < TM; i++) {
        const int row = cRow + ty * TM + i;
        #pragma unroll
        for (int j = 0; j < TN; j += 4) {
            const int col = cCol + tx * TN + j;
            float4 o;
            o.x = acc[i][j + 0] + bias[col + 0];
            o.y = acc[i][j + 1] + bias[col + 1];
            o.z = acc[i][j + 2] + bias[col + 2];
            o.w = acc[i][j + 3] + bias[col + 3];
            *(float4*)(C + (size_t)row * N + col) = o;
        }
    }
}

// ---------------------------------------------------------------------------
// Causal attention, flash-style online softmax.
// qkv layout: [b, s, 3072] with q = [0,1024), k = [1024,2048), v = [2048,3072),
// each head h occupying 64 contiguous floats.
// Grid: (B*H, SEQ/8). Block: 256 threads = 8 warps; warp w handles query row
// q = blockIdx.y*8 + w. K/V streamed through 64x64 smem tiles.
// Output written to g_attn as [b, s, H*DH] so the proj GEMM reads it row-major.
// ---------------------------------------------------------------------------
__global__ __launch_bounds__(256) void attn_causal(
    const float* __restrict__ qkv, float* __restrict__ attn_out)
{
    __shared__ float Ks[64][64];
    __shared__ float Vs[64][64];

    const int bh   = blockIdx.x;
    const int b    = bh / NHEAD;
    const int h    = bh % NHEAD;
    const int warp = threadIdx.x >> 5;
    const int lane = threadIdx.x & 31;
    const int q    = blockIdx.y * 8 + warp;

    const float* base  = qkv + (size_t)b * SEQ * QKVDIM;
    const float* qptr  = base + (size_t)q * QKVDIM + h * DHEAD;
    const float* kbase = base + NHEAD * DHEAD + h * DHEAD;          // +1024
    const float* vbase = base + 2 * NHEAD * DHEAD + h * DHEAD;      // +2048

    const float q0 = qptr[lane];
    const float q1 = qptr[lane + 32];

    float m = -1e30f, l = 0.0f, acc0 = 0.0f, acc1 = 0.0f;
    const int qmax = blockIdx.y * 8 + 7;       // last query row in this block
    const float scale = 0.125f;                // 1/sqrt(64)

    for (int kt = 0; kt <= qmax; kt += 64) {
        __syncthreads();
        // cooperative load of 64 keys + 64 values (64x64 fp32 each)
        #pragma unroll 4
        for (int i = threadIdx.x; i < 64 * 64; i += 256) {
            const int kr = i >> 6;
            const int d  = i & 63;
            Ks[kr][d] = kbase[(size_t)(kt + kr) * QKVDIM + d];
            Vs[kr][d] = vbase[(size_t)(kt + kr) * QKVDIM + d];
        }
        __syncthreads();

        const int kend = min(64, q - kt + 1);   // causal bound (may be <=0)
        for (int kk = 0; kk < kend; kk++) {
            float s = q0 * Ks[kk][lane] + q1 * Ks[kk][lane + 32];
            s += __shfl_xor_sync(0xffffffffu, s, 16);
            s += __shfl_xor_sync(0xffffffffu, s, 8);
            s += __shfl_xor_sync(0xffffffffu, s, 4);
            s += __shfl_xor_sync(0xffffffffu, s, 2);
            s += __shfl_xor_sync(0xffffffffu, s, 1);
            s *= scale;

            const float mnew = fmaxf(m, s);
            const float corr = __expf(m - mnew);
            const float p    = __expf(s - mnew);
            l    = l * corr + p;
            acc0 = acc0 * corr + p * Vs[kk][lane];
            acc1 = acc1 * corr + p * Vs[kk][lane + 32];
            m = mnew;
        }
    }

    const float inv = 1.0f / l;
    float* out = attn_out + ((size_t)b * SEQ + q) * DMODEL + h * DHEAD;
    out[lane]      = acc0 * inv;
    out[lane + 32] = acc1 * inv;
}

// ---------------------------------------------------------------------------
// kernel_launch
// Inputs (reference signature order):
//   d_in[0] hidden_states [2,2048,1024] f32
//   d_in[1] attention_mask [1,1,2048,2048] f32 (exact causal; handled structurally)
//   d_in[2] Wqkv [1024,3072] f32
//   d_in[3] bqkv [3072] f32
//   d_in[4] Wproj [1024,1024] f32
//   d_in[5] bproj [1024] f32
// Output: [2,2048,1024] f32
// ---------------------------------------------------------------------------
extern "C" void kernel_launch(void* const* d_in, const int* in_sizes, int n_in,
                              void* d_out, int out_size)
{
    const float* hidden = (const float*)d_in[0];
    const float* Wqkv   = (const float*)d_in[2];
    const float* bqkv   = (const float*)d_in[3];
    const float* Wproj  = (const float*)d_in[4];
    const float* bproj  = (const float*)d_in[5];
    float* out = (float*)d_out;

    float* qkv;  cudaGetSymbolAddress((void**)&qkv,  g_qkv);
    float* attn; cudaGetSymbolAddress((void**)&attn, g_attn);

    // 1) QKV projection: [4096,1024] @ [1024,3072] + bqkv
    {
        dim3 grid(QKVDIM / BN, ROWS / BM);
        sgemm_bias<<<grid, 256>>>(hidden, Wqkv, bqkv, qkv, ROWS, QKVDIM, DMODEL);
    }

    // 2) Causal attention per (b,h)
    {
        dim3 grid(BATCH * NHEAD, SEQ / 8);
        attn_causal<<<grid, 256>>>(qkv, attn);
    }

    // 3) Output projection: [4096,1024] @ [1024,1024] + bproj
    {
        dim3 grid(DMODEL / BN, ROWS / BM);
        sgemm_bias<<<grid, 256>>>(attn, Wproj, bproj, out, ROWS, DMODEL, DMODEL);
    }
}

// round 2
// speedup vs baseline: 2.6179x; 2.6179x over previous
#include <cuda_runtime.h>
#include <cuda_bf16.h>
#include <cstdint>

// Problem constants (fixed by the dataset)
#define BATCH 2
#define SEQ   2048
#define DMODEL 1024
#define NHEAD 16
#define DHEAD 64
#define QKVDIM (3 * NHEAD * DHEAD)   // 3072
#define ROWS  (BATCH * SEQ)          // 4096

// Scratch (allocation-free rule: __device__ globals)
__device__ float g_qkv[(size_t)ROWS * QKVDIM];       // [b*s, 3072]
__device__ float g_attn[(size_t)ROWS * DMODEL];      // [b*s, 1024] attn output (pre-proj)

// ---------------------------------------------------------------------------
// Tiled fp32 SGEMM with bias: C[M,N] = A[M,K] @ B[K,N] + bias[N]
// ---------------------------------------------------------------------------
#define BM 128
#define BN 128
#define BK 8
#define TM 8
#define TN 8

__global__ __launch_bounds__(256) void sgemm_bias(
    const float* __restrict__ A, const float* __restrict__ B,
    const float* __restrict__ bias, float* __restrict__ C,
    int M, int N, int K)
{
    __shared__ float As[BK][BM];
    __shared__ float Bs[BK][BN];

    const int tid  = threadIdx.x;
    const int cRow = blockIdx.y * BM;
    const int cCol = blockIdx.x * BN;

    const int aRow = tid >> 1;
    const int aCol = (tid & 1) * 4;
    const int bRow = tid >> 5;
    const int bCol = (tid & 31) * 4;

    const int tx = tid & 15;
    const int ty = tid >> 4;

    float acc[TM][TN];
    #pragma unroll
    for (int i = 0; i < TM; i++)
        #pragma unroll
        for (int j = 0; j < TN; j++)
            acc[i][j] = 0.0f;

    const float* Aptr = A + (size_t)cRow * K;
    const float* Bptr = B + cCol;

    for (int k0 = 0; k0 < K; k0 += BK) {
        float4 a4 = *(const float4*)(Aptr + (size_t)aRow * K + k0 + aCol);
        As[aCol + 0][aRow] = a4.x;
        As[aCol + 1][aRow] = a4.y;
        As[aCol + 2][aRow] = a4.z;
        As[aCol + 3][aRow] = a4.w;

        float4 b4 = *(const float4*)(Bptr + (size_t)(k0 + bRow) * N + bCol);
        *(float4*)&Bs[bRow][bCol] = b4;

        __syncthreads();

        #pragma unroll
        for (int kk = 0; kk < BK; kk++) {
            float ra[TM], rb[TN];
            float4 ra0 = *(const float4*)&As[kk][ty * TM];
            float4 ra1 = *(const float4*)&As[kk][ty * TM + 4];
            ra[0]=ra0.x; ra[1]=ra0.y; ra[2]=ra0.z; ra[3]=ra0.w;
            ra[4]=ra1.x; ra[5]=ra1.y; ra[6]=ra1.z; ra[7]=ra1.w;
            float4 rb0 = *(const float4*)&Bs[kk][tx * TN];
            float4 rb1 = *(const float4*)&Bs[kk][tx * TN + 4];
            rb[0]=rb0.x; rb[1]=rb0.y; rb[2]=rb0.z; rb[3]=rb0.w;
            rb[4]=rb1.x; rb[5]=rb1.y; rb[6]=rb1.z; rb[7]=rb1.w;
            #pragma unroll
            for (int i = 0; i < TM; i++)
                #pragma unroll
                for (int j = 0; j < TN; j++)
                    acc[i][j] = fmaf(ra[i], rb[j], acc[i][j]);
        }
        __syncthreads();
    }

    #pragma unroll
    for (int i = 0; i < TM; i++) {
        const int row = cRow + ty * TM + i;
        #pragma unroll
        for (int j = 0; j < TN; j += 4) {
            const int col = cCol + tx * TN + j;
            float4 o;
            o.x = acc[i][j + 0] + bias[col + 0];
            o.y = acc[i][j + 1] + bias[col + 1];
            o.z = acc[i][j + 2] + bias[col + 2];
            o.w = acc[i][j + 3] + bias[col + 3];
            *(float4*)(C + (size_t)row * N + col) = o;
        }
    }
}

// ---------------------------------------------------------------------------
// Flash attention, register-tiled fp32.
// One CTA handles (b, h, qtile of 128 queries). Key tiles of 128.
// 256 threads = 16x16 grid. S-GEMM microtile 8x8; PV microtile 8x4.
//
// smem (dynamic, ~166KB):
//   Qs[64][132]   Q tile transposed [d][q], pre-scaled by 1/8
//   Ks[64][132]   K tile transposed [d][k]
//   Vs[128][68]   V tile [k][d]
//   Ps[128][132]  probabilities [q][k]
// ---------------------------------------------------------------------------
#define AQ 128
#define AK 128
#define QS_LD 132   // row stride (words) for Qs/Ks/Ps
#define VS_LD 68

#define SM_QS 0
#define SM_KS (64 * QS_LD)
#define SM_VS (SM_KS + 64 * QS_LD)
#define SM_PS (SM_VS + AK * VS_LD)
#define SM_TOTAL_FLOATS (SM_PS + AQ * QS_LD)

__global__ __launch_bounds__(256, 1) void attn_flash(
    const float* __restrict__ qkv, float* __restrict__ attn_out)
{
    extern __shared__ float sm[];
    float* Qs = sm + SM_QS;
    float* Ks = sm + SM_KS;
    float* Vs = sm + SM_VS;
    float* Ps = sm + SM_PS;

    const int bid = blockIdx.x;
    const int qt  = 15 - (bid >> 5);        // heavy q-tiles scheduled first
    const int bh  = bid & 31;
    const int b   = bh >> 4;
    const int h   = bh & 15;

    const int tid = threadIdx.x;
    const int tx  = tid & 15;
    const int ty  = tid >> 4;

    const float* base  = qkv + (size_t)b * SEQ * QKVDIM;
    const float* qbase = base + h * DHEAD;                       // q section
    const float* kbase = base + NHEAD * DHEAD + h * DHEAD;       // k section
    const float* vbase = base + 2 * NHEAD * DHEAD + h * DHEAD;   // v section

    // Load Q tile transposed, pre-scaled: Qs[d][q] = Q[qt*128+q][d] / 8
    #pragma unroll
    for (int it = 0; it < 8; it++) {
        const int idx = tid + it * 256;          // 0..2047
        const int q   = idx >> 4;                // 0..127
        const int dc  = (idx & 15) * 4;          // 0..60
        float4 g = *(const float4*)(qbase + (size_t)(qt * AQ + q) * QKVDIM + dc);
        Qs[(dc + 0) * QS_LD + q] = g.x * 0.125f;
        Qs[(dc + 1) * QS_LD + q] = g.y * 0.125f;
        Qs[(dc + 2) * QS_LD + q] = g.z * 0.125f;
        Qs[(dc + 3) * QS_LD + q] = g.w * 0.125f;
    }

    float m[8], l[8], o[8][4];
    #pragma unroll
    for (int i = 0; i < 8; i++) {
        m[i] = -1e30f; l[i] = 0.0f;
        #pragma unroll
        for (int j = 0; j < 4; j++) o[i][j] = 0.0f;
    }

    for (int kd = 0; kd <= qt; kd++) {
        const int kt = kd * AK;
        __syncthreads();   // previous PV done before overwriting K/V

        // Load K transposed, V straight
        #pragma unroll
        for (int it = 0; it < 8; it++) {
            const int idx = tid + it * 256;
            const int k   = idx >> 4;
            const int dc  = (idx & 15) * 4;
            float4 gk = *(const float4*)(kbase + (size_t)(kt + k) * QKVDIM + dc);
            Ks[(dc + 0) * QS_LD + k] = gk.x;
            Ks[(dc + 1) * QS_LD + k] = gk.y;
            Ks[(dc + 2) * QS_LD + k] = gk.z;
            Ks[(dc + 3) * QS_LD + k] = gk.w;
            float4 gv = *(const float4*)(vbase + (size_t)(kt + k) * QKVDIM + dc);
            *(float4*)(Vs + k * VS_LD + dc) = gv;
        }
        __syncthreads();

        // S = Q @ K^T  (128x128, inner d=64), microtile 8x8
        float s[8][8];
        #pragma unroll
        for (int i = 0; i < 8; i++)
            #pragma unroll
            for (int j = 0; j < 8; j++) s[i][j] = 0.0f;

        #pragma unroll 4
        for (int kk = 0; kk < 64; kk++) {
            float ra[8], rb[8];
            float4 a0 = *(const float4*)(Qs + kk * QS_LD + ty * 8);
            float4 a1 = *(const float4*)(Qs + kk * QS_LD + ty * 8 + 4);
            ra[0]=a0.x; ra[1]=a0.y; ra[2]=a0.z; ra[3]=a0.w;
            ra[4]=a1.x; ra[5]=a1.y; ra[6]=a1.z; ra[7]=a1.w;
            float4 b0 = *(const float4*)(Ks + kk * QS_LD + tx * 8);
            float4 b1 = *(const float4*)(Ks + kk * QS_LD + tx * 8 + 4);
            rb[0]=b0.x; rb[1]=b0.y; rb[2]=b0.z; rb[3]=b0.w;
            rb[4]=b1.x; rb[5]=b1.y; rb[6]=b1.z; rb[7]=b1.w;
            #pragma unroll
            for (int i = 0; i < 8; i++)
                #pragma unroll
                for (int j = 0; j < 8; j++)
                    s[i][j] = fmaf(ra[i], rb[j], s[i][j]);
        }

        // Causal mask (diagonal tile only)
        if (kd == qt) {
            #pragma unroll
            for (int i = 0; i < 8; i++) {
                const int qr = ty * 8 + i;
                #pragma unroll
                for (int j = 0; j < 8; j++) {
                    const int kc = tx * 8 + j;
                    if (kc > qr) s[i][j] = -1e30f;
                }
            }
        }

        // Online softmax: row groups are 16 consecutive lanes (xor 1,2,4,8)
        #pragma unroll
        for (int i = 0; i < 8; i++) {
            float rmax = s[i][0];
            #pragma unroll
            for (int j = 1; j < 8; j++) rmax = fmaxf(rmax, s[i][j]);
            rmax = fmaxf(rmax, __shfl_xor_sync(0xffffffffu, rmax, 1));
            rmax = fmaxf(rmax, __shfl_xor_sync(0xffffffffu, rmax, 2));
            rmax = fmaxf(rmax, __shfl_xor_sync(0xffffffffu, rmax, 4));
            rmax = fmaxf(rmax, __shfl_xor_sync(0xffffffffu, rmax, 8));

            const float mnew = fmaxf(m[i], rmax);
            const float corr = __expf(m[i] - mnew);
            m[i] = mnew;

            float p[8], psum = 0.0f;
            #pragma unroll
            for (int j = 0; j < 8; j++) {
                p[j] = __expf(s[i][j] - mnew);
                psum += p[j];
            }
            psum += __shfl_xor_sync(0xffffffffu, psum, 1);
            psum += __shfl_xor_sync(0xffffffffu, psum, 2);
            psum += __shfl_xor_sync(0xffffffffu, psum, 4);
            psum += __shfl_xor_sync(0xffffffffu, psum, 8);

            l[i] = l[i] * corr + psum;
            #pragma unroll
            for (int j = 0; j < 4; j++) o[i][j] *= corr;

            // store P row chunk
            float4 p0 = make_float4(p[0], p[1], p[2], p[3]);
            float4 p1 = make_float4(p[4], p[5], p[6], p[7]);
            *(float4*)(Ps + (ty * 8 + i) * QS_LD + tx * 8)     = p0;
            *(float4*)(Ps + (ty * 8 + i) * QS_LD + tx * 8 + 4) = p1;
        }
        __syncthreads();

        // O += P @ V  (128x64, inner k=128), microtile 8x4
        #pragma unroll 2
        for (int kk = 0; kk < AK; kk++) {
            float ra[8];
            #pragma unroll
            for (int i = 0; i < 8; i++)
                ra[i] = Ps[(ty * 8 + i) * QS_LD + kk];   // broadcast across tx
            float4 vb = *(const float4*)(Vs + kk * VS_LD + tx * 4);
            float rb[4] = {vb.x, vb.y, vb.z, vb.w};
            #pragma unroll
            for (int i = 0; i < 8; i++)
                #pragma unroll
                for (int j = 0; j < 4; j++)
                    o[i][j] = fmaf(ra[i], rb[j], o[i][j]);
        }
    }

    // Epilogue: normalize and write to [b, s, H*DH]
    #pragma unroll
    for (int i = 0; i < 8; i++) {
        const float inv = 1.0f / l[i];
        const int qr = qt * AQ + ty * 8 + i;
        float4 w;
        w.x = o[i][0] * inv; w.y = o[i][1] * inv;
        w.z = o[i][2] * inv; w.w = o[i][3] * inv;
        *(float4*)(attn_out + ((size_t)b * SEQ + qr) * DMODEL + h * DHEAD + tx * 4) = w;
    }
}

// ---------------------------------------------------------------------------
// kernel_launch
// ---------------------------------------------------------------------------
extern "C" void kernel_launch(void* const* d_in, const int* in_sizes, int n_in,
                              void* d_out, int out_size)
{
    const float* hidden = (const float*)d_in[0];
    const float* Wqkv   = (const float*)d_in[2];
    const float* bqkv   = (const float*)d_in[3];
    const float* Wproj  = (const float*)d_in[4];
    const float* bproj  = (const float*)d_in[5];
    float* out = (float*)d_out;

    float* qkv;  cudaGetSymbolAddress((void**)&qkv,  g_qkv);
    float* attn; cudaGetSymbolAddress((void**)&attn, g_attn);

    // 1) QKV projection: [4096,1024] @ [1024,3072] + bqkv
    {
        dim3 grid(QKVDIM / BN, ROWS / BM);
        sgemm_bias<<<grid, 256>>>(hidden, Wqkv, bqkv, qkv, ROWS, QKVDIM, DMODEL);
    }

    // 2) Flash causal attention
    {
        static bool attr_set = false;
        const int smem_bytes = SM_TOTAL_FLOATS * sizeof(float);
        if (!attr_set) {
            cudaFuncSetAttribute(attn_flash,
                                 cudaFuncAttributeMaxDynamicSharedMemorySize,
                                 smem_bytes);
            attr_set = true;
        }
        attn_flash<<<512, 256, smem_bytes>>>(qkv, attn);
    }

    // 3) Output projection: [4096,1024] @ [1024,1024] + bproj
    {
        dim3 grid(DMODEL / BN, ROWS / BM);
        sgemm_bias<<<grid, 256>>>(attn, Wproj, bproj, out, ROWS, DMODEL, DMODEL);
    }
}

// round 4
// speedup vs baseline: 4.1231x; 1.5749x over previous
#include <cuda_runtime.h>
#include <cuda_bf16.h>
#include <cstdint>

// Problem constants (fixed by the dataset)
#define BATCH 2
#define SEQ   2048
#define DMODEL 1024
#define NHEAD 16
#define DHEAD 64
#define QKVDIM (3 * NHEAD * DHEAD)   // 3072
#define ROWS  (BATCH * SEQ)          // 4096

// Scratch (allocation-free rule: __device__ globals)
__device__ float g_qkv[(size_t)ROWS * QKVDIM];        // [b*s, 3072]
__device__ float g_attn[(size_t)ROWS * DMODEL];       // [b*s, 1024]
__device__ float g_WqkvT[(size_t)QKVDIM * DMODEL];    // [3072, 1024]
__device__ float g_WprojT[(size_t)DMODEL * DMODEL];   // [1024, 1024]

// ===========================================================================
// Helpers
// ===========================================================================
__device__ __forceinline__ uint32_t smem_u32(const void* p) {
    uint32_t a;
    asm("{ .reg .u64 t; cvta.to.shared.u64 t, %1; cvt.u32.u64 %0, t; }"
        : "=r"(a) : "l"(p));
    return a;
}

__device__ __forceinline__ void ldsm_x4(uint32_t& r0, uint32_t& r1,
                                        uint32_t& r2, uint32_t& r3,
                                        uint32_t addr) {
    asm volatile("ldmatrix.sync.aligned.m8n8.x4.shared.b16 {%0,%1,%2,%3}, [%4];"
                 : "=r"(r0), "=r"(r1), "=r"(r2), "=r"(r3) : "r"(addr));
}

__device__ __forceinline__ void mma_bf16(float& c0, float& c1, float& c2, float& c3,
                                         uint32_t a0, uint32_t a1, uint32_t a2, uint32_t a3,
                                         uint32_t b0, uint32_t b1) {
    asm volatile(
        "mma.sync.aligned.m16n8k16.row.col.f32.bf16.bf16.f32 "
        "{%0,%1,%2,%3}, {%4,%5,%6,%7}, {%8,%9}, {%0,%1,%2,%3};"
        : "+f"(c0), "+f"(c1), "+f"(c2), "+f"(c3)
        : "r"(a0), "r"(a1), "r"(a2), "r"(a3), "r"(b0), "r"(b1));
}

// Split fp32 -> bf16 hi/lo pairs (4 elements -> 8B hi + 8B lo)
__device__ __forceinline__ void split4(float4 v, uint2& h8, uint2& l8) {
    __nv_bfloat16 hx = __float2bfloat16(v.x);
    __nv_bfloat16 hy = __float2bfloat16(v.y);
    __nv_bfloat16 hz = __float2bfloat16(v.z);
    __nv_bfloat16 hw = __float2bfloat16(v.w);
    __nv_bfloat16 lx = __float2bfloat16(v.x - __bfloat162float(hx));
    __nv_bfloat16 ly = __float2bfloat16(v.y - __bfloat162float(hy));
    __nv_bfloat16 lz = __float2bfloat16(v.z - __bfloat162float(hz));
    __nv_bfloat16 lw = __float2bfloat16(v.w - __bfloat162float(hw));
    __nv_bfloat162 a; a.x = hx; a.y = hy;
    __nv_bfloat162 b; b.x = hz; b.y = hw;
    __nv_bfloat162 c; c.x = lx; c.y = ly;
    __nv_bfloat162 d; d.x = lz; d.y = lw;
    h8.x = *reinterpret_cast<uint32_t*>(&a);
    h8.y = *reinterpret_cast<uint32_t*>(&b);
    l8.x = *reinterpret_cast<uint32_t*>(&c);
    l8.y = *reinterpret_cast<uint32_t*>(&d);
}

// smem tile layout: 128 rows x 32 bf16 cols, 64B rows, xor-swizzled 16B segs.
// byte offset for element (r, c):
__device__ __forceinline__ uint32_t tile_off(int r, int c) {
    return (uint32_t)(r * 64 + (((((c >> 3) & 3) ^ ((r >> 1) & 3))) << 4)
                      + ((c & 7) << 1));
}

// ===========================================================================
// Weight transpose: in [K][N] fp32 -> out [N][K] fp32
// ===========================================================================
__global__ __launch_bounds__(256) void transpose_k(
    const float* __restrict__ in, float* __restrict__ out, int K, int N)
{
    __shared__ float t[32][33];
    const int nb = blockIdx.x * 32;
    const int kb = blockIdx.y * 32;
    const int x = threadIdx.x & 31;
    const int y = threadIdx.x >> 5;
    #pragma unroll
    for (int i = 0; i < 32; i += 8)
        t[y + i][x] = in[(size_t)(kb + y + i) * N + nb + x];
    __syncthreads();
    #pragma unroll
    for (int i = 0; i < 32; i += 8)
        out[(size_t)(nb + y + i) * K + kb + x] = t[x][y + i];
}

// ===========================================================================
// Split-bf16 tensor-core GEMM (mma.sync path, works on sm_103 base target):
//   C[M,N] = A[M,K] @ Bt[N,K]^T + bias[N]
// CTA tile 128x128, BK=32, 256 threads = 8 warps (4m x 2n), warp tile 32x64.
// Double-buffered smem; global loads register-staged to overlap with MMA.
// ===========================================================================
#define GBM 128
#define GBN 128
#define GBK 32
#define T_A_HI 0
#define T_A_LO 8192
#define T_B_HI 16384
#define T_B_LO 24576
#define T_BUF  32768
#define GEMM_SMEM (2 * T_BUF)

__global__ __launch_bounds__(256, 1)
void gemm_tc(const float* __restrict__ A, const float* __restrict__ Bt,
             const float* __restrict__ bias, float* __restrict__ C,
             int M, int N, int K)
{
    extern __shared__ char smg[];
    const uint32_t smb = smem_u32(smg);

    const int tid  = threadIdx.x;
    const int wid  = tid >> 5;
    const int lane = tid & 31;
    const int wm   = wid & 3;        // 0..3 -> m offset 32*wm
    const int wn   = wid >> 2;       // 0..1 -> n offset 64*wn
    const int m0 = blockIdx.y * GBM;
    const int n0 = blockIdx.x * GBN;

    const int NCH = K / GBK;

    // per-thread global load coords (4 float4 for A, 4 for B per chunk)
    // f4 index i = tid + it*256; row = i>>3, col4 = (i&7)*4
    float4 ar[4], br[4];

    auto load_regs = [&](int c) {
        const int k0 = c * GBK;
        #pragma unroll
        for (int it = 0; it < 4; it++) {
            const int i = tid + it * 256;
            const int r = i >> 3, c4 = (i & 7) * 4;
            ar[it] = *(const float4*)(A  + (size_t)(m0 + r) * K + k0 + c4);
            br[it] = *(const float4*)(Bt + (size_t)(n0 + r) * K + k0 + c4);
        }
    };

    auto store_buf = [&](int b) {
        char* base = smg + b * T_BUF;
        #pragma unroll
        for (int it = 0; it < 4; it++) {
            const int i = tid + it * 256;
            const int r = i >> 3, c4 = (i & 7) * 4;
            const uint32_t off = tile_off(r, c4);
            uint2 h8, l8;
            split4(ar[it], h8, l8);
            *(uint2*)(base + T_A_HI + off) = h8;
            *(uint2*)(base + T_A_LO + off) = l8;
            split4(br[it], h8, l8);
            *(uint2*)(base + T_B_HI + off) = h8;
            *(uint2*)(base + T_B_LO + off) = l8;
        }
    };

    float acc[2][8][4];
    #pragma unroll
    for (int mt = 0; mt < 2; mt++)
        #pragma unroll
        for (int nt = 0; nt < 8; nt++)
            #pragma unroll
            for (int j = 0; j < 4; j++)
                acc[mt][nt][j] = 0.0f;

    // ldmatrix per-lane address pieces
    const int mat = lane >> 3;
    const int l7  = lane & 7;

    load_regs(0);
    store_buf(0);
    __syncthreads();

    for (int c = 0; c < NCH; c++) {
        const int b = c & 1;
        if (c + 1 < NCH) load_regs(c + 1);   // LDGs in flight during MMA phase

        const uint32_t aHi = smb + b * T_BUF + T_A_HI;
        const uint32_t aLo = smb + b * T_BUF + T_A_LO;
        const uint32_t bHi = smb + b * T_BUF + T_B_HI;
        const uint32_t bLo = smb + b * T_BUF + T_B_LO;

        #pragma unroll
        for (int ks = 0; ks < 2; ks++) {
            const int kb = ks * 16;

            // A fragments: 2 m-tiles, hi+lo
            uint32_t ah[2][4], al[2][4];
            #pragma unroll
            for (int mt = 0; mt < 2; mt++) {
                const int r  = wm * 32 + mt * 16 + ((mat & 1) << 3) + l7;
                const int kc = kb + ((mat >> 1) << 3);
                const uint32_t off = (uint32_t)(r * 64
                    + (((((kc >> 3) & 3) ^ ((r >> 1) & 3))) << 4));
                ldsm_x4(ah[mt][0], ah[mt][1], ah[mt][2], ah[mt][3], aHi + off);
                ldsm_x4(al[mt][0], al[mt][1], al[mt][2], al[mt][3], aLo + off);
            }

            // B fragments: 8 n-tiles (pairs via x4), hi+lo
            uint32_t bh[8][2], bl[8][2];
            #pragma unroll
            for (int p = 0; p < 4; p++) {
                const int r  = wn * 64 + p * 16 + ((mat >> 1) << 3) + l7;
                const int kc = kb + ((mat & 1) << 3);
                const uint32_t off = (uint32_t)(r * 64
                    + (((((kc >> 3) & 3) ^ ((r >> 1) & 3))) << 4));
                ldsm_x4(bh[2*p][0], bh[2*p][1], bh[2*p+1][0], bh[2*p+1][1], bHi + off);
                ldsm_x4(bl[2*p][0], bl[2*p][1], bl[2*p+1][0], bl[2*p+1][1], bLo + off);
            }

            #pragma unroll
            for (int mt = 0; mt < 2; mt++)
                #pragma unroll
                for (int nt = 0; nt < 8; nt++) {
                    mma_bf16(acc[mt][nt][0], acc[mt][nt][1], acc[mt][nt][2], acc[mt][nt][3],
                             ah[mt][0], ah[mt][1], ah[mt][2], ah[mt][3],
                             bh[nt][0], bh[nt][1]);
                    mma_bf16(acc[mt][nt][0], acc[mt][nt][1], acc[mt][nt][2], acc[mt][nt][3],
                             ah[mt][0], ah[mt][1], ah[mt][2], ah[mt][3],
                             bl[nt][0], bl[nt][1]);
                    mma_bf16(acc[mt][nt][0], acc[mt][nt][1], acc[mt][nt][2], acc[mt][nt][3],
                             al[mt][0], al[mt][1], al[mt][2], al[mt][3],
                             bh[nt][0], bh[nt][1]);
                }
        }

        __syncthreads();            // everyone done reading buf b
        if (c + 1 < NCH) {
            store_buf(b ^ 1);       // fill other buffer for next iter
            __syncthreads();
        }
    }

    // Epilogue: c-frag layout: lane l -> row l>>2 (+8), col (l&3)*2 (+1)
    const int er = lane >> 2;
    const int ec = (lane & 3) * 2;
    #pragma unroll
    for (int mt = 0; mt < 2; mt++) {
        #pragma unroll
        for (int nt = 0; nt < 8; nt++) {
            const int col = n0 + wn * 64 + nt * 8 + ec;
            const float b0 = bias[col], b1 = bias[col + 1];
            const int row0 = m0 + wm * 32 + mt * 16 + er;
            float2 v0 = make_float2(acc[mt][nt][0] + b0, acc[mt][nt][1] + b1);
            float2 v1 = make_float2(acc[mt][nt][2] + b0, acc[mt][nt][3] + b1);
            *(float2*)(C + (size_t)row0 * N + col)       = v0;
            *(float2*)(C + (size_t)(row0 + 8) * N + col) = v1;
        }
    }
}

// ===========================================================================
// Flash attention, register-tiled fp32 (unchanged — ~460us)
// ===========================================================================
#define AQ 128
#define AK 128
#define QS_LD 132
#define VS_LD 68
#define SM_QS 0
#define SM_KS (64 * QS_LD)
#define SM_VS (SM_KS + 64 * QS_LD)
#define SM_PS (SM_VS + AK * VS_LD)
#define SM_TOTAL_FLOATS (SM_PS + AQ * QS_LD)

__global__ __launch_bounds__(256, 1) void attn_flash(
    const float* __restrict__ qkv, float* __restrict__ attn_out)
{
    extern __shared__ float smf[];
    float* Qs = smf + SM_QS;
    float* Ks = smf + SM_KS;
    float* Vs = smf + SM_VS;
    float* Ps = smf + SM_PS;

    const int bid = blockIdx.x;
    const int qt  = 15 - (bid >> 5);
    const int bh  = bid & 31;
    const int b   = bh >> 4;
    const int h   = bh & 15;

    const int tid = threadIdx.x;
    const int tx  = tid & 15;
    const int ty  = tid >> 4;

    const float* base  = qkv + (size_t)b * SEQ * QKVDIM;
    const float* qbase = base + h * DHEAD;
    const float* kbase = base + NHEAD * DHEAD + h * DHEAD;
    const float* vbase = base + 2 * NHEAD * DHEAD + h * DHEAD;

    #pragma unroll
    for (int it = 0; it < 8; it++) {
        const int idx = tid + it * 256;
        const int q   = idx >> 4;
        const int dc  = (idx & 15) * 4;
        float4 g = *(const float4*)(qbase + (size_t)(qt * AQ + q) * QKVDIM + dc);
        Qs[(dc + 0) * QS_LD + q] = g.x * 0.125f;
        Qs[(dc + 1) * QS_LD + q] = g.y * 0.125f;
        Qs[(dc + 2) * QS_LD + q] = g.z * 0.125f;
        Qs[(dc + 3) * QS_LD + q] = g.w * 0.125f;
    }

    float m[8], l[8], o[8][4];
    #pragma unroll
    for (int i = 0; i < 8; i++) {
        m[i] = -1e30f; l[i] = 0.0f;
        #pragma unroll
        for (int j = 0; j < 4; j++) o[i][j] = 0.0f;
    }

    for (int kd = 0; kd <= qt; kd++) {
        const int kt = kd * AK;
        __syncthreads();
        #pragma unroll
        for (int it = 0; it < 8; it++) {
            const int idx = tid + it * 256;
            const int k   = idx >> 4;
            const int dc  = (idx & 15) * 4;
            float4 gk = *(const float4*)(kbase + (size_t)(kt + k) * QKVDIM + dc);
            Ks[(dc + 0) * QS_LD + k] = gk.x;
            Ks[(dc + 1) * QS_LD + k] = gk.y;
            Ks[(dc + 2) * QS_LD + k] = gk.z;
            Ks[(dc + 3) * QS_LD + k] = gk.w;
            float4 gv = *(const float4*)(vbase + (size_t)(kt + k) * QKVDIM + dc);
            *(float4*)(Vs + k * VS_LD + dc) = gv;
        }
        __syncthreads();

        float s[8][8];
        #pragma unroll
        for (int i = 0; i < 8; i++)
            #pragma unroll
            for (int j = 0; j < 8; j++) s[i][j] = 0.0f;

        #pragma unroll 4
        for (int kk = 0; kk < 64; kk++) {
            float ra[8], rb[8];
            float4 a0 = *(const float4*)(Qs + kk * QS_LD + ty * 8);
            float4 a1 = *(const float4*)(Qs + kk * QS_LD + ty * 8 + 4);
            ra[0]=a0.x; ra[1]=a0.y; ra[2]=a0.z; ra[3]=a0.w;
            ra[4]=a1.x; ra[5]=a1.y; ra[6]=a1.z; ra[7]=a1.w;
            float4 b0 = *(const float4*)(Ks + kk * QS_LD + tx * 8);
            float4 b1 = *(const float4*)(Ks + kk * QS_LD + tx * 8 + 4);
            rb[0]=b0.x; rb[1]=b0.y; rb[2]=b0.z; rb[3]=b0.w;
            rb[4]=b1.x; rb[5]=b1.y; rb[6]=b1.z; rb[7]=b1.w;
            #pragma unroll
            for (int i = 0; i < 8; i++)
                #pragma unroll
                for (int j = 0; j < 8; j++)
                    s[i][j] = fmaf(ra[i], rb[j], s[i][j]);
        }

        if (kd == qt) {
            #pragma unroll
            for (int i = 0; i < 8; i++) {
                const int qr = ty * 8 + i;
                #pragma unroll
                for (int j = 0; j < 8; j++) {
                    const int kc = tx * 8 + j;
                    if (kc > qr) s[i][j] = -1e30f;
                }
            }
        }

        #pragma unroll
        for (int i = 0; i < 8; i++) {
            float rmax = s[i][0];
            #pragma unroll
            for (int j = 1; j < 8; j++) rmax = fmaxf(rmax, s[i][j]);
            rmax = fmaxf(rmax, __shfl_xor_sync(0xffffffffu, rmax, 1));
            rmax = fmaxf(rmax, __shfl_xor_sync(0xffffffffu, rmax, 2));
            rmax = fmaxf(rmax, __shfl_xor_sync(0xffffffffu, rmax, 4));
            rmax = fmaxf(rmax, __shfl_xor_sync(0xffffffffu, rmax, 8));

            const float mnew = fmaxf(m[i], rmax);
            const float corr = __expf(m[i] - mnew);
            m[i] = mnew;

            float p[8], psum = 0.0f;
            #pragma unroll
            for (int j = 0; j < 8; j++) {
                p[j] = __expf(s[i][j] - mnew);
                psum += p[j];
            }
            psum += __shfl_xor_sync(0xffffffffu, psum, 1);
            psum += __shfl_xor_sync(0xffffffffu, psum, 2);
            psum += __shfl_xor_sync(0xffffffffu, psum, 4);
            psum += __shfl_xor_sync(0xffffffffu, psum, 8);

            l[i] = l[i] * corr + psum;
            #pragma unroll
            for (int j = 0; j < 4; j++) o[i][j] *= corr;

            float4 p0 = make_float4(p[0], p[1], p[2], p[3]);
            float4 p1 = make_float4(p[4], p[5], p[6], p[7]);
            *(float4*)(Ps + (ty * 8 + i) * QS_LD + tx * 8)     = p0;
            *(float4*)(Ps + (ty * 8 + i) * QS_LD + tx * 8 + 4) = p1;
        }
        __syncthreads();

        #pragma unroll 2
        for (int kk = 0; kk < AK; kk++) {
            float ra[8];
            #pragma unroll
            for (int i = 0; i < 8; i++)
                ra[i] = Ps[(ty * 8 + i) * QS_LD + kk];
            float4 vb = *(const float4*)(Vs + kk * VS_LD + tx * 4);
            float rb[4] = {vb.x, vb.y, vb.z, vb.w};
            #pragma unroll
            for (int i = 0; i < 8; i++)
                #pragma unroll
                for (int j = 0; j < 4; j++)
                    o[i][j] = fmaf(ra[i], rb[j], o[i][j]);
        }
    }

    #pragma unroll
    for (int i = 0; i < 8; i++) {
        const float inv = 1.0f / l[i];
        const int qr = qt * AQ + ty * 8 + i;
        float4 w;
        w.x = o[i][0] * inv; w.y = o[i][1] * inv;
        w.z = o[i][2] * inv; w.w = o[i][3] * inv;
        *(float4*)(attn_out + ((size_t)b * SEQ + qr) * DMODEL + h * DHEAD + tx * 4) = w;
    }
}

// ===========================================================================
// kernel_launch
// ===========================================================================
extern "C" void kernel_launch(void* const* d_in, const int* in_sizes, int n_in,
                              void* d_out, int out_size)
{
    const float* hidden = (const float*)d_in[0];
    const float* Wqkv   = (const float*)d_in[2];
    const float* bqkv   = (const float*)d_in[3];
    const float* Wproj  = (const float*)d_in[4];
    const float* bproj  = (const float*)d_in[5];
    float* out = (float*)d_out;

    float* qkv;    cudaGetSymbolAddress((void**)&qkv,    g_qkv);
    float* attn;   cudaGetSymbolAddress((void**)&attn,   g_attn);
    float* WqkvT;  cudaGetSymbolAddress((void**)&WqkvT,  g_WqkvT);
    float* WprojT; cudaGetSymbolAddress((void**)&WprojT, g_WprojT);

    static bool attr_set = false;
    if (!attr_set) {
        cudaFuncSetAttribute(gemm_tc, cudaFuncAttributeMaxDynamicSharedMemorySize,
                             GEMM_SMEM);
        cudaFuncSetAttribute(attn_flash, cudaFuncAttributeMaxDynamicSharedMemorySize,
                             SM_TOTAL_FLOATS * (int)sizeof(float));
        attr_set = true;
    }

    // 0) Transpose weights: [K,N] -> [N,K]
    {
        dim3 g1(QKVDIM / 32, DMODEL / 32);
        transpose_k<<<g1, 256>>>(Wqkv, WqkvT, DMODEL, QKVDIM);
        dim3 g2(DMODEL / 32, DMODEL / 32);
        transpose_k<<<g2, 256>>>(Wproj, WprojT, DMODEL, DMODEL);
    }

    // 1) QKV projection: [4096,1024] @ [1024,3072] + bqkv
    {
        dim3 grid(QKVDIM / GBN, ROWS / GBM);   // (24, 32)
        gemm_tc<<<grid, 256, GEMM_SMEM>>>(hidden, WqkvT, bqkv, qkv,
                                          ROWS, QKVDIM, DMODEL);
    }

    // 2) Flash causal attention
    attn_flash<<<512, 256, SM_TOTAL_FLOATS * sizeof(float)>>>(qkv, attn);

    // 3) Output projection: [4096,1024] @ [1024,1024] + bproj
    {
        dim3 grid(DMODEL / GBN, ROWS / GBM);   // (8, 32)
        gemm_tc<<<grid, 256, GEMM_SMEM>>>(attn, WprojT, bproj, out,
                                          ROWS, DMODEL, DMODEL);
    }
}

// round 5
// speedup vs baseline: 6.6140x; 1.6041x over previous
#include <cuda_runtime.h>
#include <cuda_bf16.h>
#include <cuda_fp16.h>
#include <cstdint>

// Problem constants (fixed by the dataset)
#define BATCH 2
#define SEQ   2048
#define DMODEL 1024
#define NHEAD 16
#define DHEAD 64
#define QKVDIM (3 * NHEAD * DHEAD)   // 3072
#define ROWS  (BATCH * SEQ)          // 4096

// Scratch (allocation-free rule: __device__ globals)
__device__ float g_qkv[(size_t)ROWS * QKVDIM];        // [b*s, 3072]
__device__ float g_attn[(size_t)ROWS * DMODEL];       // [b*s, 1024]
__device__ float g_WqkvT[(size_t)QKVDIM * DMODEL];    // [3072, 1024]
__device__ float g_WprojT[(size_t)DMODEL * DMODEL];   // [1024, 1024]

// ===========================================================================
// Helpers
// ===========================================================================
__device__ __forceinline__ uint32_t smem_u32(const void* p) {
    uint32_t a;
    asm("{ .reg .u64 t; cvta.to.shared.u64 t, %1; cvt.u32.u64 %0, t; }"
        : "=r"(a) : "l"(p));
    return a;
}

__device__ __forceinline__ void ldsm_x4(uint32_t& r0, uint32_t& r1,
                                        uint32_t& r2, uint32_t& r3,
                                        uint32_t addr) {
    asm volatile("ldmatrix.sync.aligned.m8n8.x4.shared.b16 {%0,%1,%2,%3}, [%4];"
                 : "=r"(r0), "=r"(r1), "=r"(r2), "=r"(r3) : "r"(addr));
}

__device__ __forceinline__ void ldsm_x4_t(uint32_t& r0, uint32_t& r1,
                                          uint32_t& r2, uint32_t& r3,
                                          uint32_t addr) {
    asm volatile("ldmatrix.sync.aligned.m8n8.x4.trans.shared.b16 {%0,%1,%2,%3}, [%4];"
                 : "=r"(r0), "=r"(r1), "=r"(r2), "=r"(r3) : "r"(addr));
}

__device__ __forceinline__ void mma_bf16(float& c0, float& c1, float& c2, float& c3,
                                         uint32_t a0, uint32_t a1, uint32_t a2, uint32_t a3,
                                         uint32_t b0, uint32_t b1) {
    asm volatile(
        "mma.sync.aligned.m16n8k16.row.col.f32.bf16.bf16.f32 "
        "{%0,%1,%2,%3}, {%4,%5,%6,%7}, {%8,%9}, {%0,%1,%2,%3};"
        : "+f"(c0), "+f"(c1), "+f"(c2), "+f"(c3)
        : "r"(a0), "r"(a1), "r"(a2), "r"(a3), "r"(b0), "r"(b1));
}

__device__ __forceinline__ void mma_f16(float& c0, float& c1, float& c2, float& c3,
                                        uint32_t a0, uint32_t a1, uint32_t a2, uint32_t a3,
                                        uint32_t b0, uint32_t b1) {
    asm volatile(
        "mma.sync.aligned.m16n8k16.row.col.f32.f16.f16.f32 "
        "{%0,%1,%2,%3}, {%4,%5,%6,%7}, {%8,%9}, {%0,%1,%2,%3};"
        : "+f"(c0), "+f"(c1), "+f"(c2), "+f"(c3)
        : "r"(a0), "r"(a1), "r"(a2), "r"(a3), "r"(b0), "r"(b1));
}

__device__ __forceinline__ float ex2f(float x) {
    float y;
    asm("ex2.approx.f32 %0, %1;" : "=f"(y) : "f"(x));
    return y;
}

// pack two f32 -> f16x2 {lo, hi}
__device__ __forceinline__ uint32_t pack_h2(float lo, float hi) {
    uint32_t d;
    asm("cvt.rn.f16x2.f32 %0, %1, %2;" : "=r"(d) : "f"(hi), "f"(lo));
    return d;
}
__device__ __forceinline__ float2 unpack_h2(uint32_t u) {
    __half2 hh = *reinterpret_cast<__half2*>(&u);
    return __half22float2(hh);
}

// fp32x4 -> fp16 hi/lo split (each uint2 = 4 fp16)
__device__ __forceinline__ void split4h(float4 v, uint2& h8, uint2& l8) {
    uint32_t h0 = pack_h2(v.x, v.y), h1 = pack_h2(v.z, v.w);
    float2 b0 = unpack_h2(h0), b1 = unpack_h2(h1);
    uint32_t l0 = pack_h2(v.x - b0.x, v.y - b0.y);
    uint32_t l1 = pack_h2(v.z - b1.x, v.w - b1.y);
    h8 = make_uint2(h0, h1);
    l8 = make_uint2(l0, l1);
}

// Split fp32 -> bf16 hi/lo pairs (for GEMM kernel)
__device__ __forceinline__ void split4(float4 v, uint2& h8, uint2& l8) {
    __nv_bfloat16 hx = __float2bfloat16(v.x);
    __nv_bfloat16 hy = __float2bfloat16(v.y);
    __nv_bfloat16 hz = __float2bfloat16(v.z);
    __nv_bfloat16 hw = __float2bfloat16(v.w);
    __nv_bfloat16 lx = __float2bfloat16(v.x - __bfloat162float(hx));
    __nv_bfloat16 ly = __float2bfloat16(v.y - __bfloat162float(hy));
    __nv_bfloat16 lz = __float2bfloat16(v.z - __bfloat162float(hz));
    __nv_bfloat16 lw = __float2bfloat16(v.w - __bfloat162float(hw));
    __nv_bfloat162 a; a.x = hx; a.y = hy;
    __nv_bfloat162 b; b.x = hz; b.y = hw;
    __nv_bfloat162 c; c.x = lx; c.y = ly;
    __nv_bfloat162 d; d.x = lz; d.y = lw;
    h8.x = *reinterpret_cast<uint32_t*>(&a);
    h8.y = *reinterpret_cast<uint32_t*>(&b);
    l8.x = *reinterpret_cast<uint32_t*>(&c);
    l8.y = *reinterpret_cast<uint32_t*>(&d);
}

// GEMM smem tile layout: 128 rows x 32 bf16 cols, 64B rows, xor-swizzled 16B segs
__device__ __forceinline__ uint32_t tile_off(int r, int c) {
    return (uint32_t)(r * 64 + (((((c >> 3) & 3) ^ ((r >> 1) & 3))) << 4)
                      + ((c & 7) << 1));
}

// ===========================================================================
// Weight transpose: in [K][N] fp32 -> out [N][K] fp32
// ===========================================================================
__global__ __launch_bounds__(256) void transpose_k(
    const float* __restrict__ in, float* __restrict__ out, int K, int N)
{
    __shared__ float t[32][33];
    const int nb = blockIdx.x * 32;
    const int kb = blockIdx.y * 32;
    const int x = threadIdx.x & 31;
    const int y = threadIdx.x >> 5;
    #pragma unroll
    for (int i = 0; i < 32; i += 8)
        t[y + i][x] = in[(size_t)(kb + y + i) * N + nb + x];
    __syncthreads();
    #pragma unroll
    for (int i = 0; i < 32; i += 8)
        out[(size_t)(nb + y + i) * K + kb + x] = t[x][y + i];
}

// ===========================================================================
// Split-bf16 tensor-core GEMM (unchanged from R4 — passing at ~375us total)
// ===========================================================================
#define GBM 128
#define GBN 128
#define GBK 32
#define T_A_HI 0
#define T_A_LO 8192
#define T_B_HI 16384
#define T_B_LO 24576
#define T_BUF  32768
#define GEMM_SMEM (2 * T_BUF)

__global__ __launch_bounds__(256, 1)
void gemm_tc(const float* __restrict__ A, const float* __restrict__ Bt,
             const float* __restrict__ bias, float* __restrict__ C,
             int M, int N, int K)
{
    extern __shared__ char smg[];
    const uint32_t smb = smem_u32(smg);

    const int tid  = threadIdx.x;
    const int wid  = tid >> 5;
    const int lane = tid & 31;
    const int wm   = wid & 3;
    const int wn   = wid >> 2;
    const int m0 = blockIdx.y * GBM;
    const int n0 = blockIdx.x * GBN;

    const int NCH = K / GBK;

    float4 ar[4], br[4];

    auto load_regs = [&](int c) {
        const int k0 = c * GBK;
        #pragma unroll
        for (int it = 0; it < 4; it++) {
            const int i = tid + it * 256;
            const int r = i >> 3, c4 = (i & 7) * 4;
            ar[it] = *(const float4*)(A  + (size_t)(m0 + r) * K + k0 + c4);
            br[it] = *(const float4*)(Bt + (size_t)(n0 + r) * K + k0 + c4);
        }
    };

    auto store_buf = [&](int b) {
        char* base = smg + b * T_BUF;
        #pragma unroll
        for (int it = 0; it < 4; it++) {
            const int i = tid + it * 256;
            const int r = i >> 3, c4 = (i & 7) * 4;
            const uint32_t off = tile_off(r, c4);
            uint2 h8, l8;
            split4(ar[it], h8, l8);
            *(uint2*)(base + T_A_HI + off) = h8;
            *(uint2*)(base + T_A_LO + off) = l8;
            split4(br[it], h8, l8);
            *(uint2*)(base + T_B_HI + off) = h8;
            *(uint2*)(base + T_B_LO + off) = l8;
        }
    };

    float acc[2][8][4];
    #pragma unroll
    for (int mt = 0; mt < 2; mt++)
        #pragma unroll
        for (int nt = 0; nt < 8; nt++)
            #pragma unroll
            for (int j = 0; j < 4; j++)
                acc[mt][nt][j] = 0.0f;

    const int mat = lane >> 3;
    const int l7  = lane & 7;

    load_regs(0);
    store_buf(0);
    __syncthreads();

    for (int c = 0; c < NCH; c++) {
        const int b = c & 1;
        if (c + 1 < NCH) load_regs(c + 1);

        const uint32_t aHi = smb + b * T_BUF + T_A_HI;
        const uint32_t aLo = smb + b * T_BUF + T_A_LO;
        const uint32_t bHi = smb + b * T_BUF + T_B_HI;
        const uint32_t bLo = smb + b * T_BUF + T_B_LO;

        #pragma unroll
        for (int ks = 0; ks < 2; ks++) {
            const int kb = ks * 16;

            uint32_t ah[2][4], al[2][4];
            #pragma unroll
            for (int mt = 0; mt < 2; mt++) {
                const int r  = wm * 32 + mt * 16 + ((mat & 1) << 3) + l7;
                const int kc = kb + ((mat >> 1) << 3);
                const uint32_t off = (uint32_t)(r * 64
                    + (((((kc >> 3) & 3) ^ ((r >> 1) & 3))) << 4));
                ldsm_x4(ah[mt][0], ah[mt][1], ah[mt][2], ah[mt][3], aHi + off);
                ldsm_x4(al[mt][0], al[mt][1], al[mt][2], al[mt][3], aLo + off);
            }

            uint32_t bh[8][2], bl[8][2];
            #pragma unroll
            for (int p = 0; p < 4; p++) {
                const int r  = wn * 64 + p * 16 + ((mat >> 1) << 3) + l7;
                const int kc = kb + ((mat & 1) << 3);
                const uint32_t off = (uint32_t)(r * 64
                    + (((((kc >> 3) & 3) ^ ((r >> 1) & 3))) << 4));
                ldsm_x4(bh[2*p][0], bh[2*p][1], bh[2*p+1][0], bh[2*p+1][1], bHi + off);
                ldsm_x4(bl[2*p][0], bl[2*p][1], bl[2*p+1][0], bl[2*p+1][1], bLo + off);
            }

            #pragma unroll
            for (int mt = 0; mt < 2; mt++)
                #pragma unroll
                for (int nt = 0; nt < 8; nt++) {
                    mma_bf16(acc[mt][nt][0], acc[mt][nt][1], acc[mt][nt][2], acc[mt][nt][3],
                             ah[mt][0], ah[mt][1], ah[mt][2], ah[mt][3],
                             bh[nt][0], bh[nt][1]);
                    mma_bf16(acc[mt][nt][0], acc[mt][nt][1], acc[mt][nt][2], acc[mt][nt][3],
                             ah[mt][0], ah[mt][1], ah[mt][2], ah[mt][3],
                             bl[nt][0], bl[nt][1]);
                    mma_bf16(acc[mt][nt][0], acc[mt][nt][1], acc[mt][nt][2], acc[mt][nt][3],
                             al[mt][0], al[mt][1], al[mt][2], al[mt][3],
                             bh[nt][0], bh[nt][1]);
                }
        }

        __syncthreads();
        if (c + 1 < NCH) {
            store_buf(b ^ 1);
            __syncthreads();
        }
    }

    const int er = lane >> 2;
    const int ec = (lane & 3) * 2;
    #pragma unroll
    for (int mt = 0; mt < 2; mt++) {
        #pragma unroll
        for (int nt = 0; nt < 8; nt++) {
            const int col = n0 + wn * 64 + nt * 8 + ec;
            const float b0 = bias[col], b1 = bias[col + 1];
            const int row0 = m0 + wm * 32 + mt * 16 + er;
            float2 v0 = make_float2(acc[mt][nt][0] + b0, acc[mt][nt][1] + b1);
            float2 v1 = make_float2(acc[mt][nt][2] + b0, acc[mt][nt][3] + b1);
            *(float2*)(C + (size_t)row0 * N + col)       = v0;
            *(float2*)(C + (size_t)(row0 + 8) * N + col) = v1;
        }
    }
}

// ===========================================================================
// Tensor-core flash attention (mma.sync fp16, split-K / split-P / split-V)
//
// CTA = (b, h, qtile 128). Key tiles 128. 8 warps = 4m x 2n.
// S = Qf16 . (Kh + Kl)^T   (2 products; log2-domain, Q pre-scaled by .125*log2e)
// PV = Ph.Vh + Pl.Vh + Ph.Vl (3 products; P from in-register c->a conversion)
// Each n-warp accumulates O over its 64-key slice; slices summed at the end.
//
// smem: Q 16K | KH 16K | KL 16K | VH 16K | VL 16K | rmax 1K | rsum 1K | Ored 32K
// ===========================================================================
#define ATT_Q    0
#define ATT_KH   16384
#define ATT_KL   32768
#define ATT_VH   49152
#define ATT_VL   65536
#define ATT_RMAX 81920
#define ATT_RSUM 82944
#define ATT_ORED 83968
#define ATT_SMEM (83968 + 32768)

__global__ __launch_bounds__(256, 1) void attn_mma(
    const float* __restrict__ qkv, float* __restrict__ attn_out)
{
    extern __shared__ char sma[];
    const uint32_t smb = smem_u32(sma);
    float* redmax = (float*)(sma + ATT_RMAX);
    float* redsum = (float*)(sma + ATT_RSUM);
    float* ored   = (float*)(sma + ATT_ORED);

    const int bid = blockIdx.x;
    const int qt  = 15 - (bid >> 5);          // heavy q-tiles first
    const int bh  = bid & 31;
    const int b   = bh >> 4;
    const int h   = bh & 15;

    const int tid  = threadIdx.x;
    const int wid  = tid >> 5;
    const int lane = tid & 31;
    const int wm   = wid & 3;                 // m-warp: rows wm*32
    const int wn   = wid >> 2;                // n-warp: keys wn*64
    const int mat  = lane >> 3;
    const int l7   = lane & 7;
    const int er   = lane >> 2;
    const int ec   = (lane & 3) * 2;

    const float* base = qkv + (size_t)b * SEQ * QKVDIM;
    const float* qg = base + h * DHEAD;
    const float* kg = base + NHEAD * DHEAD + h * DHEAD;
    const float* vg = base + 2 * NHEAD * DHEAD + h * DHEAD;

    // ---- Load Q tile -> fp16 smem (scaled to log2 domain) ----
    const float qsc = 0.125f * 1.44269504088896340736f;
    #pragma unroll
    for (int it = 0; it < 8; it++) {
        const int t = tid + it * 256;          // 2048 tasks: 128 rows x 16 f4
        const int r = t >> 4, g = t & 15;
        float4 v = *(const float4*)(qg + (size_t)(qt * 128 + r) * QKVDIM + g * 4);
        uint2 h8;
        h8.x = pack_h2(v.x * qsc, v.y * qsc);
        h8.y = pack_h2(v.z * qsc, v.w * qsc);
        const uint32_t cb = (uint32_t)(g * 8);
        const uint32_t sw = (uint32_t)(r * 128) + (cb ^ (((uint32_t)(r & 7)) << 4));
        *(uint2*)(sma + ATT_Q + sw) = h8;
    }
    __syncthreads();

    // ---- Load Q A-fragments (persistent in registers) ----
    uint32_t qa[2][4][4];
    #pragma unroll
    for (int mt = 0; mt < 2; mt++) {
        #pragma unroll
        for (int k16 = 0; k16 < 4; k16++) {
            const int r  = wm * 32 + mt * 16 + ((mat & 1) << 3) + l7;
            const uint32_t cb = (uint32_t)((k16 * 16 + ((mat >> 1) << 3)) * 2);
            const uint32_t sw = (uint32_t)(r * 128) + (cb ^ (((uint32_t)(r & 7)) << 4));
            ldsm_x4(qa[mt][k16][0], qa[mt][k16][1], qa[mt][k16][2], qa[mt][k16][3],
                    smb + ATT_Q + sw);
        }
    }

    // State
    float mst[2][2], lst[2][2], oa[2][8][4];
    #pragma unroll
    for (int mt = 0; mt < 2; mt++)
        #pragma unroll
        for (int h2 = 0; h2 < 2; h2++) { mst[mt][h2] = -1e30f; lst[mt][h2] = 0.0f; }
    #pragma unroll
    for (int mt = 0; mt < 2; mt++)
        #pragma unroll
        for (int nt = 0; nt < 8; nt++)
            #pragma unroll
            for (int j = 0; j < 4; j++) oa[mt][nt][j] = 0.0f;

    for (int kd = 0; kd <= qt; kd++) {
        __syncthreads();   // previous tile's ldsm reads complete

        // ---- Load K (split) and V (split) tiles into fp16 smem ----
        #pragma unroll
        for (int it = 0; it < 8; it++) {
            const int t = tid + it * 256;
            const int r = t >> 4, g = t & 15;
            const uint32_t cb = (uint32_t)(g * 8);
            const uint32_t sw = (uint32_t)(r * 128) + (cb ^ (((uint32_t)(r & 7)) << 4));
            float4 kv = *(const float4*)(kg + (size_t)(kd * 128 + r) * QKVDIM + g * 4);
            uint2 h8, l8;
            split4h(kv, h8, l8);
            *(uint2*)(sma + ATT_KH + sw) = h8;
            *(uint2*)(sma + ATT_KL + sw) = l8;
            float4 vv = *(const float4*)(vg + (size_t)(kd * 128 + r) * QKVDIM + g * 4);
            split4h(vv, h8, l8);
            *(uint2*)(sma + ATT_VH + sw) = h8;
            *(uint2*)(sma + ATT_VL + sw) = l8;
        }
        __syncthreads();

        // ---- S = Q @ K^T (warp slice: 32 q x 64 k), 2 products ----
        float sc[2][8][4];
        #pragma unroll
        for (int mt = 0; mt < 2; mt++)
            #pragma unroll
            for (int nt = 0; nt < 8; nt++)
                #pragma unroll
                for (int j = 0; j < 4; j++) sc[mt][nt][j] = 0.0f;

        #pragma unroll
        for (int k16 = 0; k16 < 4; k16++) {
            uint32_t bf[8][2];
            #pragma unroll
            for (int p = 0; p < 4; p++) {
                const int r = wn * 64 + p * 16 + ((mat >> 1) << 3) + l7;
                const uint32_t cb = (uint32_t)((k16 * 16 + ((mat & 1) << 3)) * 2);
                const uint32_t sw = (uint32_t)(r * 128) + (cb ^ (((uint32_t)(r & 7)) << 4));
                ldsm_x4(bf[2*p][0], bf[2*p][1], bf[2*p+1][0], bf[2*p+1][1],
                        smb + ATT_KH + sw);
            }
            #pragma unroll
            for (int mt = 0; mt < 2; mt++)
                #pragma unroll
                for (int nt = 0; nt < 8; nt++)
                    mma_f16(sc[mt][nt][0], sc[mt][nt][1], sc[mt][nt][2], sc[mt][nt][3],
                            qa[mt][k16][0], qa[mt][k16][1], qa[mt][k16][2], qa[mt][k16][3],
                            bf[nt][0], bf[nt][1]);
            // K lo
            #pragma unroll
            for (int p = 0; p < 4; p++) {
                const int r = wn * 64 + p * 16 + ((mat >> 1) << 3) + l7;
                const uint32_t cb = (uint32_t)((k16 * 16 + ((mat & 1) << 3)) * 2);
                const uint32_t sw = (uint32_t)(r * 128) + (cb ^ (((uint32_t)(r & 7)) << 4));
                ldsm_x4(bf[2*p][0], bf[2*p][1], bf[2*p+1][0], bf[2*p+1][1],
                        smb + ATT_KL + sw);
            }
            #pragma unroll
            for (int mt = 0; mt < 2; mt++)
                #pragma unroll
                for (int nt = 0; nt < 8; nt++)
                    mma_f16(sc[mt][nt][0], sc[mt][nt][1], sc[mt][nt][2], sc[mt][nt][3],
                            qa[mt][k16][0], qa[mt][k16][1], qa[mt][k16][2], qa[mt][k16][3],
                            bf[nt][0], bf[nt][1]);
        }

        // ---- Causal mask (diagonal tile only) ----
        if (kd == qt) {
            #pragma unroll
            for (int mt = 0; mt < 2; mt++)
                #pragma unroll
                for (int nt = 0; nt < 8; nt++)
                    #pragma unroll
                    for (int j = 0; j < 4; j++) {
                        const int row = wm * 32 + mt * 16 + (j >> 1) * 8 + er;
                        const int col = wn * 64 + nt * 8 + ec + (j & 1);
                        if (col > row) sc[mt][nt][j] = -1e30f;
                    }
        }

        // ---- Row max: local + shfl + cross-warp smem exchange ----
        float rmx[2][2];
        #pragma unroll
        for (int mt = 0; mt < 2; mt++)
            #pragma unroll
            for (int h2 = 0; h2 < 2; h2++) {
                float mx = -1e30f;
                #pragma unroll
                for (int nt = 0; nt < 8; nt++) {
                    mx = fmaxf(mx, sc[mt][nt][2*h2]);
                    mx = fmaxf(mx, sc[mt][nt][2*h2+1]);
                }
                mx = fmaxf(mx, __shfl_xor_sync(0xffffffffu, mx, 1));
                mx = fmaxf(mx, __shfl_xor_sync(0xffffffffu, mx, 2));
                rmx[mt][h2] = mx;
                if ((lane & 3) == 0)
                    redmax[wn * 128 + wm * 32 + mt * 16 + h2 * 8 + er] = mx;
            }
        __syncthreads();

        float corr[2][2];
        #pragma unroll
        for (int mt = 0; mt < 2; mt++)
            #pragma unroll
            for (int h2 = 0; h2 < 2; h2++) {
                const int row = wm * 32 + mt * 16 + h2 * 8 + er;
                const float g = fmaxf(redmax[row], redmax[128 + row]);
                const float mnew = fmaxf(mst[mt][h2], g);
                corr[mt][h2] = ex2f(mst[mt][h2] - mnew);
                mst[mt][h2] = mnew;
            }

        // ---- exp2 + row sums ----
        float psum[2][2] = {{0.0f, 0.0f}, {0.0f, 0.0f}};
        #pragma unroll
        for (int mt = 0; mt < 2; mt++)
            #pragma unroll
            for (int nt = 0; nt < 8; nt++)
                #pragma unroll
                for (int j = 0; j < 4; j++) {
                    const int h2 = j >> 1;
                    const float pv = ex2f(sc[mt][nt][j] - mst[mt][h2]);
                    sc[mt][nt][j] = pv;
                    psum[mt][h2] += pv;
                }
        #pragma unroll
        for (int mt = 0; mt < 2; mt++)
            #pragma unroll
            for (int h2 = 0; h2 < 2; h2++) {
                float s = psum[mt][h2];
                s += __shfl_xor_sync(0xffffffffu, s, 1);
                s += __shfl_xor_sync(0xffffffffu, s, 2);
                if ((lane & 3) == 0)
                    redsum[wn * 128 + wm * 32 + mt * 16 + h2 * 8 + er] = s;
            }
        __syncthreads();

        #pragma unroll
        for (int mt = 0; mt < 2; mt++)
            #pragma unroll
            for (int h2 = 0; h2 < 2; h2++) {
                const int row = wm * 32 + mt * 16 + h2 * 8 + er;
                lst[mt][h2] = lst[mt][h2] * corr[mt][h2]
                            + redsum[row] + redsum[128 + row];
            }
        #pragma unroll
        for (int mt = 0; mt < 2; mt++)
            #pragma unroll
            for (int nt = 0; nt < 8; nt++)
                #pragma unroll
                for (int j = 0; j < 4; j++)
                    oa[mt][nt][j] *= corr[mt][j >> 1];

        // ---- PV: P (c->a reg conversion, split) @ V (ldsm.trans, split) ----
        #pragma unroll
        for (int kt2 = 0; kt2 < 4; kt2++) {
            uint32_t ah[2][4], al[2][4];
            #pragma unroll
            for (int mt = 0; mt < 2; mt++) {
                #pragma unroll
                for (int q4 = 0; q4 < 4; q4++) {
                    const int nt = 2 * kt2 + (q4 >> 1);
                    const int j0 = (q4 & 1) * 2;
                    const float p0 = sc[mt][nt][j0], p1 = sc[mt][nt][j0 + 1];
                    const uint32_t hh = pack_h2(p0, p1);
                    const float2 bk = unpack_h2(hh);
                    ah[mt][q4] = hh;
                    al[mt][q4] = pack_h2(p0 - bk.x, p1 - bk.y);
                }
            }
            uint32_t bvh[8][2], bvl[8][2];
            #pragma unroll
            for (int ntp = 0; ntp < 4; ntp++) {
                const int r = wn * 64 + kt2 * 16 + ((mat & 1) << 3) + l7;
                const uint32_t cb = (uint32_t)((ntp * 16 + ((mat >> 1) << 3)) * 2);
                const uint32_t sw = (uint32_t)(r * 128) + (cb ^ (((uint32_t)(r & 7)) << 4));
                ldsm_x4_t(bvh[2*ntp][0], bvh[2*ntp][1], bvh[2*ntp+1][0], bvh[2*ntp+1][1],
                          smb + ATT_VH + sw);
                ldsm_x4_t(bvl[2*ntp][0], bvl[2*ntp][1], bvl[2*ntp+1][0], bvl[2*ntp+1][1],
                          smb + ATT_VL + sw);
            }
            #pragma unroll
            for (int mt = 0; mt < 2; mt++)
                #pragma unroll
                for (int nt = 0; nt < 8; nt++) {
                    mma_f16(oa[mt][nt][0], oa[mt][nt][1], oa[mt][nt][2], oa[mt][nt][3],
                            ah[mt][0], ah[mt][1], ah[mt][2], ah[mt][3],
                            bvh[nt][0], bvh[nt][1]);
                    mma_f16(oa[mt][nt][0], oa[mt][nt][1], oa[mt][nt][2], oa[mt][nt][3],
                            al[mt][0], al[mt][1], al[mt][2], al[mt][3],
                            bvh[nt][0], bvh[nt][1]);
                    mma_f16(oa[mt][nt][0], oa[mt][nt][1], oa[mt][nt][2], oa[mt][nt][3],
                            ah[mt][0], ah[mt][1], ah[mt][2], ah[mt][3],
                            bvl[nt][0], bvl[nt][1]);
                }
        }
    }

    // ---- Combine the two n-warps' partial O, normalize, write out ----
    __syncthreads();
    if (wn == 1) {
        #pragma unroll
        for (int mt = 0; mt < 2; mt++)
            #pragma unroll
            for (int nt = 0; nt < 8; nt++)
                #pragma unroll
                for (int h2 = 0; h2 < 2; h2++) {
                    const int row = wm * 32 + mt * 16 + h2 * 8 + er;
                    *(float2*)&ored[row * 64 + nt * 8 + ec] =
                        make_float2(oa[mt][nt][2*h2], oa[mt][nt][2*h2+1]);
                }
    }
    __syncthreads();
    if (wn == 0) {
        #pragma unroll
        for (int mt = 0; mt < 2; mt++)
            #pragma unroll
            for (int h2 = 0; h2 < 2; h2++) {
                const float inv = 1.0f / lst[mt][h2];
                const int row = wm * 32 + mt * 16 + h2 * 8 + er;
                const int qrow = qt * 128 + row;
                float* dst = attn_out + ((size_t)b * SEQ + qrow) * DMODEL + h * DHEAD;
                #pragma unroll
                for (int nt = 0; nt < 8; nt++) {
                    const float2 o2 = *(const float2*)&ored[row * 64 + nt * 8 + ec];
                    float2 w;
                    w.x = (oa[mt][nt][2*h2]     + o2.x) * inv;
                    w.y = (oa[mt][nt][2*h2 + 1] + o2.y) * inv;
                    *(float2*)(dst + nt * 8 + ec) = w;
                }
            }
    }
}

// ===========================================================================
// kernel_launch
// ===========================================================================
extern "C" void kernel_launch(void* const* d_in, const int* in_sizes, int n_in,
                              void* d_out, int out_size)
{
    const float* hidden = (const float*)d_in[0];
    const float* Wqkv   = (const float*)d_in[2];
    const float* bqkv   = (const float*)d_in[3];
    const float* Wproj  = (const float*)d_in[4];
    const float* bproj  = (const float*)d_in[5];
    float* out = (float*)d_out;

    float* qkv;    cudaGetSymbolAddress((void**)&qkv,    g_qkv);
    float* attn;   cudaGetSymbolAddress((void**)&attn,   g_attn);
    float* WqkvT;  cudaGetSymbolAddress((void**)&WqkvT,  g_WqkvT);
    float* WprojT; cudaGetSymbolAddress((void**)&WprojT, g_WprojT);

    static bool attr_set = false;
    if (!attr_set) {
        cudaFuncSetAttribute(gemm_tc, cudaFuncAttributeMaxDynamicSharedMemorySize,
                             GEMM_SMEM);
        cudaFuncSetAttribute(attn_mma, cudaFuncAttributeMaxDynamicSharedMemorySize,
                             ATT_SMEM);
        attr_set = true;
    }

    // 0) Transpose weights: [K,N] -> [N,K]
    {
        dim3 g1(QKVDIM / 32, DMODEL / 32);
        transpose_k<<<g1, 256>>>(Wqkv, WqkvT, DMODEL, QKVDIM);
        dim3 g2(DMODEL / 32, DMODEL / 32);
        transpose_k<<<g2, 256>>>(Wproj, WprojT, DMODEL, DMODEL);
    }

    // 1) QKV projection: [4096,1024] @ [1024,3072] + bqkv
    {
        dim3 grid(QKVDIM / GBN, ROWS / GBM);   // (24, 32)
        gemm_tc<<<grid, 256, GEMM_SMEM>>>(hidden, WqkvT, bqkv, qkv,
                                          ROWS, QKVDIM, DMODEL);
    }

    // 2) Tensor-core flash causal attention
    attn_mma<<<512, 256, ATT_SMEM>>>(qkv, attn);

    // 3) Output projection: [4096,1024] @ [1024,1024] + bproj
    {
        dim3 grid(DMODEL / GBN, ROWS / GBM);   // (8, 32)
        gemm_tc<<<grid, 256, GEMM_SMEM>>>(attn, WprojT, bproj, out,
                                          ROWS, DMODEL, DMODEL);
    }
}

// round 6
// speedup vs baseline: 8.0200x; 1.2126x over previous
#include <cuda_runtime.h>
#include <cuda_bf16.h>
#include <cuda_fp16.h>
#include <cstdint>

// Problem constants (fixed by the dataset)
#define BATCH 2
#define SEQ   2048
#define DMODEL 1024
#define NHEAD 16
#define DHEAD 64
#define QKVDIM (3 * NHEAD * DHEAD)   // 3072
#define ROWS  (BATCH * SEQ)          // 4096

// Scratch (allocation-free rule: __device__ globals)
__device__ float g_qkv[(size_t)ROWS * QKVDIM];        // [b*s, 3072]
__device__ float g_attn[(size_t)ROWS * DMODEL];       // [b*s, 1024]
__device__ __nv_bfloat16 g_Wh[(size_t)QKVDIM * DMODEL];  // weight^T hi
__device__ __nv_bfloat16 g_Wl[(size_t)QKVDIM * DMODEL];  // weight^T lo
__device__ __nv_bfloat16 g_Ah[(size_t)ROWS * DMODEL];    // activation hi
__device__ __nv_bfloat16 g_Al[(size_t)ROWS * DMODEL];    // activation lo

// ===========================================================================
// Helpers
// ===========================================================================
__device__ __forceinline__ uint32_t smem_u32(const void* p) {
    uint32_t a;
    asm("{ .reg .u64 t; cvta.to.shared.u64 t, %1; cvt.u32.u64 %0, t; }"
        : "=r"(a) : "l"(p));
    return a;
}

__device__ __forceinline__ void cp_async16(uint32_t dst, const void* src) {
    asm volatile("cp.async.cg.shared.global [%0], [%1], 16;"
                 :: "r"(dst), "l"(src) : "memory");
}
__device__ __forceinline__ void cp_commit() {
    asm volatile("cp.async.commit_group;" ::: "memory");
}
template <int N>
__device__ __forceinline__ void cp_wait() {
    asm volatile("cp.async.wait_group %0;" :: "n"(N) : "memory");
}

__device__ __forceinline__ void ldsm_x4(uint32_t& r0, uint32_t& r1,
                                        uint32_t& r2, uint32_t& r3,
                                        uint32_t addr) {
    asm volatile("ldmatrix.sync.aligned.m8n8.x4.shared.b16 {%0,%1,%2,%3}, [%4];"
                 : "=r"(r0), "=r"(r1), "=r"(r2), "=r"(r3) : "r"(addr));
}

__device__ __forceinline__ void ldsm_x4_t(uint32_t& r0, uint32_t& r1,
                                          uint32_t& r2, uint32_t& r3,
                                          uint32_t addr) {
    asm volatile("ldmatrix.sync.aligned.m8n8.x4.trans.shared.b16 {%0,%1,%2,%3}, [%4];"
                 : "=r"(r0), "=r"(r1), "=r"(r2), "=r"(r3) : "r"(addr));
}

__device__ __forceinline__ void mma_bf16(float& c0, float& c1, float& c2, float& c3,
                                         uint32_t a0, uint32_t a1, uint32_t a2, uint32_t a3,
                                         uint32_t b0, uint32_t b1) {
    asm volatile(
        "mma.sync.aligned.m16n8k16.row.col.f32.bf16.bf16.f32 "
        "{%0,%1,%2,%3}, {%4,%5,%6,%7}, {%8,%9}, {%0,%1,%2,%3};"
        : "+f"(c0), "+f"(c1), "+f"(c2), "+f"(c3)
        : "r"(a0), "r"(a1), "r"(a2), "r"(a3), "r"(b0), "r"(b1));
}

__device__ __forceinline__ void mma_f16(float& c0, float& c1, float& c2, float& c3,
                                        uint32_t a0, uint32_t a1, uint32_t a2, uint32_t a3,
                                        uint32_t b0, uint32_t b1) {
    asm volatile(
        "mma.sync.aligned.m16n8k16.row.col.f32.f16.f16.f32 "
        "{%0,%1,%2,%3}, {%4,%5,%6,%7}, {%8,%9}, {%0,%1,%2,%3};"
        : "+f"(c0), "+f"(c1), "+f"(c2), "+f"(c3)
        : "r"(a0), "r"(a1), "r"(a2), "r"(a3), "r"(b0), "r"(b1));
}

__device__ __forceinline__ float ex2f(float x) {
    float y;
    asm("ex2.approx.f32 %0, %1;" : "=f"(y) : "f"(x));
    return y;
}

__device__ __forceinline__ uint32_t pack_h2(float lo, float hi) {
    uint32_t d;
    asm("cvt.rn.f16x2.f32 %0, %1, %2;" : "=r"(d) : "f"(hi), "f"(lo));
    return d;
}
__device__ __forceinline__ float2 unpack_h2(uint32_t u) {
    __half2 hh = *reinterpret_cast<__half2*>(&u);
    return __half22float2(hh);
}

// fp32x4 -> fp16 hi/lo split
__device__ __forceinline__ void split4h(float4 v, uint2& h8, uint2& l8) {
    uint32_t h0 = pack_h2(v.x, v.y), h1 = pack_h2(v.z, v.w);
    float2 b0 = unpack_h2(h0), b1 = unpack_h2(h1);
    uint32_t l0 = pack_h2(v.x - b0.x, v.y - b0.y);
    uint32_t l1 = pack_h2(v.z - b1.x, v.w - b1.y);
    h8 = make_uint2(h0, h1);
    l8 = make_uint2(l0, l1);
}

// fp32x4 -> bf16 hi/lo split
__device__ __forceinline__ void split4(float4 v, uint2& h8, uint2& l8) {
    __nv_bfloat16 hx = __float2bfloat16(v.x);
    __nv_bfloat16 hy = __float2bfloat16(v.y);
    __nv_bfloat16 hz = __float2bfloat16(v.z);
    __nv_bfloat16 hw = __float2bfloat16(v.w);
    __nv_bfloat16 lx = __float2bfloat16(v.x - __bfloat162float(hx));
    __nv_bfloat16 ly = __float2bfloat16(v.y - __bfloat162float(hy));
    __nv_bfloat16 lz = __float2bfloat16(v.z - __bfloat162float(hz));
    __nv_bfloat16 lw = __float2bfloat16(v.w - __bfloat162float(hw));
    __nv_bfloat162 a; a.x = hx; a.y = hy;
    __nv_bfloat162 b; b.x = hz; b.y = hw;
    __nv_bfloat162 c; c.x = lx; c.y = ly;
    __nv_bfloat162 d; d.x = lz; d.y = lw;
    h8.x = *reinterpret_cast<uint32_t*>(&a);
    h8.y = *reinterpret_cast<uint32_t*>(&b);
    l8.x = *reinterpret_cast<uint32_t*>(&c);
    l8.y = *reinterpret_cast<uint32_t*>(&d);
}

// GEMM smem tile: 128 rows x 32 bf16 cols, 64B rows, xor-swizzled 16B segs
__device__ __forceinline__ uint32_t tile_off(int r, int c) {
    return (uint32_t)(r * 64 + (((((c >> 3) & 3) ^ ((r >> 1) & 3))) << 4)
                      + ((c & 7) << 1));
}

// ===========================================================================
// Pre-processing: weight transpose+split, activation split (bf16 hi/lo)
// ===========================================================================
__global__ __launch_bounds__(256) void transpose_split(
    const float* __restrict__ in, __nv_bfloat16* __restrict__ Wh,
    __nv_bfloat16* __restrict__ Wl, int K, int N)
{
    __shared__ float t[32][33];
    const int nb = blockIdx.x * 32;
    const int kb = blockIdx.y * 32;
    const int x = threadIdx.x & 31;
    const int y = threadIdx.x >> 5;
    #pragma unroll
    for (int i = 0; i < 32; i += 8)
        t[y + i][x] = in[(size_t)(kb + y + i) * N + nb + x];
    __syncthreads();
    #pragma unroll
    for (int i = 0; i < 32; i += 8) {
        const float v = t[x][y + i];
        const __nv_bfloat16 hi = __float2bfloat16(v);
        const __nv_bfloat16 lo = __float2bfloat16(v - __bfloat162float(hi));
        const size_t o = (size_t)(nb + y + i) * K + kb + x;
        Wh[o] = hi;
        Wl[o] = lo;
    }
}

__global__ __launch_bounds__(256) void split_rows(
    const float* __restrict__ A, __nv_bfloat16* __restrict__ Ah,
    __nv_bfloat16* __restrict__ Al, int total4)
{
    const int i = blockIdx.x * 256 + threadIdx.x;
    if (i < total4) {
        float4 v = ((const float4*)A)[i];
        uint2 h8, l8;
        split4(v, h8, l8);
        *(uint2*)(Ah + (size_t)i * 4) = h8;
        *(uint2*)(Al + (size_t)i * 4) = l8;
    }
}

// ===========================================================================
// bf16 split tensor-core GEMM (pre-split operands):
//   C[M,N] = (Ah+Al)[M,K] @ (Bh+Bl)[N,K]^T + bias[N]
// CTA tile 128x128, BK=32, 8 warps (4m x 2n), cp.async double buffer,
// 2 CTAs/SM (64KB smem, <=128 regs).
// ===========================================================================
#define GBM 128
#define GBN 128
#define GBK 32
#define SB_AH 0
#define SB_AL 8192
#define SB_BH 16384
#define SB_BL 24576
#define SB_BUF 32768
#define GEMM_SMEM (2 * SB_BUF)

__global__ __launch_bounds__(256, 2)
void gemm_bf16(const __nv_bfloat16* __restrict__ Ah, const __nv_bfloat16* __restrict__ Al,
               const __nv_bfloat16* __restrict__ Bh, const __nv_bfloat16* __restrict__ Bl,
               const float* __restrict__ bias, float* __restrict__ C,
               int M, int N, int K)
{
    extern __shared__ char smg[];
    const uint32_t smb = smem_u32(smg);

    const int tid  = threadIdx.x;
    const int wid  = tid >> 5;
    const int lane = tid & 31;
    const int wm   = wid & 3;
    const int wn   = wid >> 2;
    const int m0 = blockIdx.y * GBM;
    const int n0 = blockIdx.x * GBN;
    const int NCH = K / GBK;

    const int mat = lane >> 3;
    const int l7  = lane & 7;

    auto load_chunk = [&](int c, int b) {
        const int k0 = c * GBK;
        const uint32_t dst = smb + b * SB_BUF;
        #pragma unroll
        for (int t = 0; t < 2; t++) {
            const int j = tid + t * 256;         // 0..511
            const int r = j >> 2, c8 = (j & 3) * 8;
            const uint32_t off = tile_off(r, c8);
            const size_t ga = (size_t)(m0 + r) * K + k0 + c8;
            const size_t gb = (size_t)(n0 + r) * K + k0 + c8;
            cp_async16(dst + SB_AH + off, Ah + ga);
            cp_async16(dst + SB_AL + off, Al + ga);
            cp_async16(dst + SB_BH + off, Bh + gb);
            cp_async16(dst + SB_BL + off, Bl + gb);
        }
        cp_commit();
    };

    float acc[2][8][4];
    #pragma unroll
    for (int mt = 0; mt < 2; mt++)
        #pragma unroll
        for (int nt = 0; nt < 8; nt++)
            #pragma unroll
            for (int j = 0; j < 4; j++)
                acc[mt][nt][j] = 0.0f;

    load_chunk(0, 0);

    for (int c = 0; c < NCH; c++) {
        const int b = c & 1;
        if (c + 1 < NCH) { load_chunk(c + 1, b ^ 1); cp_wait<1>(); }
        else             { cp_wait<0>(); }
        __syncthreads();

        const uint32_t aHi = smb + b * SB_BUF + SB_AH;
        const uint32_t aLo = smb + b * SB_BUF + SB_AL;
        const uint32_t bHi = smb + b * SB_BUF + SB_BH;
        const uint32_t bLo = smb + b * SB_BUF + SB_BL;

        #pragma unroll
        for (int ks = 0; ks < 2; ks++) {
            const int kb = ks * 16;

            uint32_t ah[2][4], al[2][4];
            #pragma unroll
            for (int mt = 0; mt < 2; mt++) {
                const int r  = wm * 32 + mt * 16 + ((mat & 1) << 3) + l7;
                const int kc = kb + ((mat >> 1) << 3);
                const uint32_t off = (uint32_t)(r * 64
                    + (((((kc >> 3) & 3) ^ ((r >> 1) & 3))) << 4));
                ldsm_x4(ah[mt][0], ah[mt][1], ah[mt][2], ah[mt][3], aHi + off);
                ldsm_x4(al[mt][0], al[mt][1], al[mt][2], al[mt][3], aLo + off);
            }

            #pragma unroll
            for (int ph = 0; ph < 2; ph++) {
                uint32_t bh[4][2], bl[4][2];
                #pragma unroll
                for (int p = 0; p < 2; p++) {
                    const int r  = wn * 64 + (ph * 2 + p) * 16 + ((mat >> 1) << 3) + l7;
                    const int kc = kb + ((mat & 1) << 3);
                    const uint32_t off = (uint32_t)(r * 64
                        + (((((kc >> 3) & 3) ^ ((r >> 1) & 3))) << 4));
                    ldsm_x4(bh[2*p][0], bh[2*p][1], bh[2*p+1][0], bh[2*p+1][1], bHi + off);
                    ldsm_x4(bl[2*p][0], bl[2*p][1], bl[2*p+1][0], bl[2*p+1][1], bLo + off);
                }
                #pragma unroll
                for (int mt = 0; mt < 2; mt++)
                    #pragma unroll
                    for (int q = 0; q < 4; q++) {
                        const int nt = ph * 4 + q;
                        mma_bf16(acc[mt][nt][0], acc[mt][nt][1], acc[mt][nt][2], acc[mt][nt][3],
                                 ah[mt][0], ah[mt][1], ah[mt][2], ah[mt][3],
                                 bh[q][0], bh[q][1]);
                        mma_bf16(acc[mt][nt][0], acc[mt][nt][1], acc[mt][nt][2], acc[mt][nt][3],
                                 ah[mt][0], ah[mt][1], ah[mt][2], ah[mt][3],
                                 bl[q][0], bl[q][1]);
                        mma_bf16(acc[mt][nt][0], acc[mt][nt][1], acc[mt][nt][2], acc[mt][nt][3],
                                 al[mt][0], al[mt][1], al[mt][2], al[mt][3],
                                 bh[q][0], bh[q][1]);
                    }
            }
        }
        __syncthreads();
    }

    // Epilogue
    const int er = lane >> 2;
    const int ec = (lane & 3) * 2;
    #pragma unroll
    for (int mt = 0; mt < 2; mt++) {
        #pragma unroll
        for (int nt = 0; nt < 8; nt++) {
            const int col = n0 + wn * 64 + nt * 8 + ec;
            const float b0 = bias[col], b1 = bias[col + 1];
            const int row0 = m0 + wm * 32 + mt * 16 + er;
            float2 v0 = make_float2(acc[mt][nt][0] + b0, acc[mt][nt][1] + b1);
            float2 v1 = make_float2(acc[mt][nt][2] + b0, acc[mt][nt][3] + b1);
            *(float2*)(C + (size_t)row0 * N + col)       = v0;
            *(float2*)(C + (size_t)(row0 + 8) * N + col) = v1;
        }
    }
}

// ===========================================================================
// Tensor-core flash attention (unchanged from R5 — 147us, rel_err 1.9e-4)
// ===========================================================================
#define ATT_Q    0
#define ATT_KH   16384
#define ATT_KL   32768
#define ATT_VH   49152
#define ATT_VL   65536
#define ATT_RMAX 81920
#define ATT_RSUM 82944
#define ATT_ORED 83968
#define ATT_SMEM (83968 + 32768)

__global__ __launch_bounds__(256, 1) void attn_mma(
    const float* __restrict__ qkv, float* __restrict__ attn_out)
{
    extern __shared__ char sma[];
    const uint32_t smb = smem_u32(sma);
    float* redmax = (float*)(sma + ATT_RMAX);
    float* redsum = (float*)(sma + ATT_RSUM);
    float* ored   = (float*)(sma + ATT_ORED);

    const int bid = blockIdx.x;
    const int qt  = 15 - (bid >> 5);
    const int bh  = bid & 31;
    const int b   = bh >> 4;
    const int h   = bh & 15;

    const int tid  = threadIdx.x;
    const int wid  = tid >> 5;
    const int lane = tid & 31;
    const int wm   = wid & 3;
    const int wn   = wid >> 2;
    const int mat  = lane >> 3;
    const int l7   = lane & 7;
    const int er   = lane >> 2;
    const int ec   = (lane & 3) * 2;

    const float* base = qkv + (size_t)b * SEQ * QKVDIM;
    const float* qg = base + h * DHEAD;
    const float* kg = base + NHEAD * DHEAD + h * DHEAD;
    const float* vg = base + 2 * NHEAD * DHEAD + h * DHEAD;

    const float qsc = 0.125f * 1.44269504088896340736f;
    #pragma unroll
    for (int it = 0; it < 8; it++) {
        const int t = tid + it * 256;
        const int r = t >> 4, g = t & 15;
        float4 v = *(const float4*)(qg + (size_t)(qt * 128 + r) * QKVDIM + g * 4);
        uint2 h8;
        h8.x = pack_h2(v.x * qsc, v.y * qsc);
        h8.y = pack_h2(v.z * qsc, v.w * qsc);
        const uint32_t cb = (uint32_t)(g * 8);
        const uint32_t sw = (uint32_t)(r * 128) + (cb ^ (((uint32_t)(r & 7)) << 4));
        *(uint2*)(sma + ATT_Q + sw) = h8;
    }
    __syncthreads();

    uint32_t qa[2][4][4];
    #pragma unroll
    for (int mt = 0; mt < 2; mt++) {
        #pragma unroll
        for (int k16 = 0; k16 < 4; k16++) {
            const int r  = wm * 32 + mt * 16 + ((mat & 1) << 3) + l7;
            const uint32_t cb = (uint32_t)((k16 * 16 + ((mat >> 1) << 3)) * 2);
            const uint32_t sw = (uint32_t)(r * 128) + (cb ^ (((uint32_t)(r & 7)) << 4));
            ldsm_x4(qa[mt][k16][0], qa[mt][k16][1], qa[mt][k16][2], qa[mt][k16][3],
                    smb + ATT_Q + sw);
        }
    }

    float mst[2][2], lst[2][2], oa[2][8][4];
    #pragma unroll
    for (int mt = 0; mt < 2; mt++)
        #pragma unroll
        for (int h2 = 0; h2 < 2; h2++) { mst[mt][h2] = -1e30f; lst[mt][h2] = 0.0f; }
    #pragma unroll
    for (int mt = 0; mt < 2; mt++)
        #pragma unroll
        for (int nt = 0; nt < 8; nt++)
            #pragma unroll
            for (int j = 0; j < 4; j++) oa[mt][nt][j] = 0.0f;

    for (int kd = 0; kd <= qt; kd++) {
        __syncthreads();

        #pragma unroll
        for (int it = 0; it < 8; it++) {
            const int t = tid + it * 256;
            const int r = t >> 4, g = t & 15;
            const uint32_t cb = (uint32_t)(g * 8);
            const uint32_t sw = (uint32_t)(r * 128) + (cb ^ (((uint32_t)(r & 7)) << 4));
            float4 kv = *(const float4*)(kg + (size_t)(kd * 128 + r) * QKVDIM + g * 4);
            uint2 h8, l8;
            split4h(kv, h8, l8);
            *(uint2*)(sma + ATT_KH + sw) = h8;
            *(uint2*)(sma + ATT_KL + sw) = l8;
            float4 vv = *(const float4*)(vg + (size_t)(kd * 128 + r) * QKVDIM + g * 4);
            split4h(vv, h8, l8);
            *(uint2*)(sma + ATT_VH + sw) = h8;
            *(uint2*)(sma + ATT_VL + sw) = l8;
        }
        __syncthreads();

        float sc[2][8][4];
        #pragma unroll
        for (int mt = 0; mt < 2; mt++)
            #pragma unroll
            for (int nt = 0; nt < 8; nt++)
                #pragma unroll
                for (int j = 0; j < 4; j++) sc[mt][nt][j] = 0.0f;

        #pragma unroll
        for (int k16 = 0; k16 < 4; k16++) {
            uint32_t bf[8][2];
            #pragma unroll
            for (int p = 0; p < 4; p++) {
                const int r = wn * 64 + p * 16 + ((mat >> 1) << 3) + l7;
                const uint32_t cb = (uint32_t)((k16 * 16 + ((mat & 1) << 3)) * 2);
                const uint32_t sw = (uint32_t)(r * 128) + (cb ^ (((uint32_t)(r & 7)) << 4));
                ldsm_x4(bf[2*p][0], bf[2*p][1], bf[2*p+1][0], bf[2*p+1][1],
                        smb + ATT_KH + sw);
            }
            #pragma unroll
            for (int mt = 0; mt < 2; mt++)
                #pragma unroll
                for (int nt = 0; nt < 8; nt++)
                    mma_f16(sc[mt][nt][0], sc[mt][nt][1], sc[mt][nt][2], sc[mt][nt][3],
                            qa[mt][k16][0], qa[mt][k16][1], qa[mt][k16][2], qa[mt][k16][3],
                            bf[nt][0], bf[nt][1]);
            #pragma unroll
            for (int p = 0; p < 4; p++) {
                const int r = wn * 64 + p * 16 + ((mat >> 1) << 3) + l7;
                const uint32_t cb = (uint32_t)((k16 * 16 + ((mat & 1) << 3)) * 2);
                const uint32_t sw = (uint32_t)(r * 128) + (cb ^ (((uint32_t)(r & 7)) << 4));
                ldsm_x4(bf[2*p][0], bf[2*p][1], bf[2*p+1][0], bf[2*p+1][1],
                        smb + ATT_KL + sw);
            }
            #pragma unroll
            for (int mt = 0; mt < 2; mt++)
                #pragma unroll
                for (int nt = 0; nt < 8; nt++)
                    mma_f16(sc[mt][nt][0], sc[mt][nt][1], sc[mt][nt][2], sc[mt][nt][3],
                            qa[mt][k16][0], qa[mt][k16][1], qa[mt][k16][2], qa[mt][k16][3],
                            bf[nt][0], bf[nt][1]);
        }

        if (kd == qt) {
            #pragma unroll
            for (int mt = 0; mt < 2; mt++)
                #pragma unroll
                for (int nt = 0; nt < 8; nt++)
                    #pragma unroll
                    for (int j = 0; j < 4; j++) {
                        const int row = wm * 32 + mt * 16 + (j >> 1) * 8 + er;
                        const int col = wn * 64 + nt * 8 + ec + (j & 1);
                        if (col > row) sc[mt][nt][j] = -1e30f;
                    }
        }

        #pragma unroll
        for (int mt = 0; mt < 2; mt++)
            #pragma unroll
            for (int h2 = 0; h2 < 2; h2++) {
                float mx = -1e30f;
                #pragma unroll
                for (int nt = 0; nt < 8; nt++) {
                    mx = fmaxf(mx, sc[mt][nt][2*h2]);
                    mx = fmaxf(mx, sc[mt][nt][2*h2+1]);
                }
                mx = fmaxf(mx, __shfl_xor_sync(0xffffffffu, mx, 1));
                mx = fmaxf(mx, __shfl_xor_sync(0xffffffffu, mx, 2));
                if ((lane & 3) == 0)
                    redmax[wn * 128 + wm * 32 + mt * 16 + h2 * 8 + er] = mx;
            }
        __syncthreads();

        float corr[2][2];
        #pragma unroll
        for (int mt = 0; mt < 2; mt++)
            #pragma unroll
            for (int h2 = 0; h2 < 2; h2++) {
                const int row = wm * 32 + mt * 16 + h2 * 8 + er;
                const float g = fmaxf(redmax[row], redmax[128 + row]);
                const float mnew = fmaxf(mst[mt][h2], g);
                corr[mt][h2] = ex2f(mst[mt][h2] - mnew);
                mst[mt][h2] = mnew;
            }

        float psum[2][2] = {{0.0f, 0.0f}, {0.0f, 0.0f}};
        #pragma unroll
        for (int mt = 0; mt < 2; mt++)
            #pragma unroll
            for (int nt = 0; nt < 8; nt++)
                #pragma unroll
                for (int j = 0; j < 4; j++) {
                    const int h2 = j >> 1;
                    const float pv = ex2f(sc[mt][nt][j] - mst[mt][h2]);
                    sc[mt][nt][j] = pv;
                    psum[mt][h2] += pv;
                }
        #pragma unroll
        for (int mt = 0; mt < 2; mt++)
            #pragma unroll
            for (int h2 = 0; h2 < 2; h2++) {
                float s = psum[mt][h2];
                s += __shfl_xor_sync(0xffffffffu, s, 1);
                s += __shfl_xor_sync(0xffffffffu, s, 2);
                if ((lane & 3) == 0)
                    redsum[wn * 128 + wm * 32 + mt * 16 + h2 * 8 + er] = s;
            }
        __syncthreads();

        #pragma unroll
        for (int mt = 0; mt < 2; mt++)
            #pragma unroll
            for (int h2 = 0; h2 < 2; h2++) {
                const int row = wm * 32 + mt * 16 + h2 * 8 + er;
                lst[mt][h2] = lst[mt][h2] * corr[mt][h2]
                            + redsum[row] + redsum[128 + row];
            }
        #pragma unroll
        for (int mt = 0; mt < 2; mt++)
            #pragma unroll
            for (int nt = 0; nt < 8; nt++)
                #pragma unroll
                for (int j = 0; j < 4; j++)
                    oa[mt][nt][j] *= corr[mt][j >> 1];

        #pragma unroll
        for (int kt2 = 0; kt2 < 4; kt2++) {
            uint32_t ah[2][4], al[2][4];
            #pragma unroll
            for (int mt = 0; mt < 2; mt++) {
                #pragma unroll
                for (int q4 = 0; q4 < 4; q4++) {
                    const int nt = 2 * kt2 + (q4 >> 1);
                    const int j0 = (q4 & 1) * 2;
                    const float p0 = sc[mt][nt][j0], p1 = sc[mt][nt][j0 + 1];
                    const uint32_t hh = pack_h2(p0, p1);
                    const float2 bk = unpack_h2(hh);
                    ah[mt][q4] = hh;
                    al[mt][q4] = pack_h2(p0 - bk.x, p1 - bk.y);
                }
            }
            uint32_t bvh[8][2], bvl[8][2];
            #pragma unroll
            for (int ntp = 0; ntp < 4; ntp++) {
                const int r = wn * 64 + kt2 * 16 + ((mat & 1) << 3) + l7;
                const uint32_t cb = (uint32_t)((ntp * 16 + ((mat >> 1) << 3)) * 2);
                const uint32_t sw = (uint32_t)(r * 128) + (cb ^ (((uint32_t)(r & 7)) << 4));
                ldsm_x4_t(bvh[2*ntp][0], bvh[2*ntp][1], bvh[2*ntp+1][0], bvh[2*ntp+1][1],
                          smb + ATT_VH + sw);
                ldsm_x4_t(bvl[2*ntp][0], bvl[2*ntp][1], bvl[2*ntp+1][0], bvl[2*ntp+1][1],
                          smb + ATT_VL + sw);
            }
            #pragma unroll
            for (int mt = 0; mt < 2; mt++)
                #pragma unroll
                for (int nt = 0; nt < 8; nt++) {
                    mma_f16(oa[mt][nt][0], oa[mt][nt][1], oa[mt][nt][2], oa[mt][nt][3],
                            ah[mt][0], ah[mt][1], ah[mt][2], ah[mt][3],
                            bvh[nt][0], bvh[nt][1]);
                    mma_f16(oa[mt][nt][0], oa[mt][nt][1], oa[mt][nt][2], oa[mt][nt][3],
                            al[mt][0], al[mt][1], al[mt][2], al[mt][3],
                            bvh[nt][0], bvh[nt][1]);
                    mma_f16(oa[mt][nt][0], oa[mt][nt][1], oa[mt][nt][2], oa[mt][nt][3],
                            ah[mt][0], ah[mt][1], ah[mt][2], ah[mt][3],
                            bvl[nt][0], bvl[nt][1]);
                }
        }
    }

    __syncthreads();
    if (wn == 1) {
        #pragma unroll
        for (int mt = 0; mt < 2; mt++)
            #pragma unroll
            for (int nt = 0; nt < 8; nt++)
                #pragma unroll
                for (int h2 = 0; h2 < 2; h2++) {
                    const int row = wm * 32 + mt * 16 + h2 * 8 + er;
                    *(float2*)&ored[row * 64 + nt * 8 + ec] =
                        make_float2(oa[mt][nt][2*h2], oa[mt][nt][2*h2+1]);
                }
    }
    __syncthreads();
    if (wn == 0) {
        #pragma unroll
        for (int mt = 0; mt < 2; mt++)
            #pragma unroll
            for (int h2 = 0; h2 < 2; h2++) {
                const float inv = 1.0f / lst[mt][h2];
                const int row = wm * 32 + mt * 16 + h2 * 8 + er;
                const int qrow = qt * 128 + row;
                float* dst = attn_out + ((size_t)b * SEQ + qrow) * DMODEL + h * DHEAD;
                #pragma unroll
                for (int nt = 0; nt < 8; nt++) {
                    const float2 o2 = *(const float2*)&ored[row * 64 + nt * 8 + ec];
                    float2 w;
                    w.x = (oa[mt][nt][2*h2]     + o2.x) * inv;
                    w.y = (oa[mt][nt][2*h2 + 1] + o2.y) * inv;
                    *(float2*)(dst + nt * 8 + ec) = w;
                }
            }
    }
}

// ===========================================================================
// kernel_launch
// ===========================================================================
extern "C" void kernel_launch(void* const* d_in, const int* in_sizes, int n_in,
                              void* d_out, int out_size)
{
    const float* hidden = (const float*)d_in[0];
    const float* Wqkv   = (const float*)d_in[2];
    const float* bqkv   = (const float*)d_in[3];
    const float* Wproj  = (const float*)d_in[4];
    const float* bproj  = (const float*)d_in[5];
    float* out = (float*)d_out;

    float* qkv;   cudaGetSymbolAddress((void**)&qkv,   g_qkv);
    float* attn;  cudaGetSymbolAddress((void**)&attn,  g_attn);
    __nv_bfloat16 *Wh, *Wl, *Ah, *Al;
    cudaGetSymbolAddress((void**)&Wh, g_Wh);
    cudaGetSymbolAddress((void**)&Wl, g_Wl);
    cudaGetSymbolAddress((void**)&Ah, g_Ah);
    cudaGetSymbolAddress((void**)&Al, g_Al);

    static bool attr_set = false;
    if (!attr_set) {
        cudaFuncSetAttribute(gemm_bf16, cudaFuncAttributeMaxDynamicSharedMemorySize,
                             GEMM_SMEM);
        cudaFuncSetAttribute(attn_mma, cudaFuncAttributeMaxDynamicSharedMemorySize,
                             ATT_SMEM);
        attr_set = true;
    }

    const int act4 = ROWS * DMODEL / 4;   // float4 count for activations

    // ---- QKV projection ----
    {
        dim3 gw(QKVDIM / 32, DMODEL / 32);
        transpose_split<<<gw, 256>>>(Wqkv, Wh, Wl, DMODEL, QKVDIM);
        split_rows<<<(act4 + 255) / 256, 256>>>(hidden, Ah, Al, act4);
        dim3 grid(QKVDIM / GBN, ROWS / GBM);   // (24, 32)
        gemm_bf16<<<grid, 256, GEMM_SMEM>>>(Ah, Al, Wh, Wl, bqkv, qkv,
                                            ROWS, QKVDIM, DMODEL);
    }

    // ---- Flash causal attention (tensor cores) ----
    attn_mma<<<512, 256, ATT_SMEM>>>(qkv, attn);

    // ---- Output projection ----
    {
        dim3 gw(DMODEL / 32, DMODEL / 32);
        transpose_split<<<gw, 256>>>(Wproj, Wh, Wl, DMODEL, DMODEL);
        split_rows<<<(act4 + 255) / 256, 256>>>(attn, Ah, Al, act4);
        dim3 grid(DMODEL / GBN, ROWS / GBM);   // (8, 32)
        gemm_bf16<<<grid, 256, GEMM_SMEM>>>(Ah, Al, Wh, Wl, bproj, out,
                                            ROWS, DMODEL, DMODEL);
    }
}

// round 7
// speedup vs baseline: 8.2620x; 1.0302x over previous
#include <cuda_runtime.h>
#include <cuda_bf16.h>
#include <cuda_fp16.h>
#include <cstdint>

// Problem constants (fixed by the dataset)
#define BATCH 2
#define SEQ   2048
#define DMODEL 1024
#define NHEAD 16
#define DHEAD 64
#define QKVDIM (3 * NHEAD * DHEAD)   // 3072
#define ROWS  (BATCH * SEQ)          // 4096

#define QSCALE (0.125f * 1.44269504088896340736f)   // 1/sqrt(64) * log2(e)

// Scratch (allocation-free rule: __device__ globals)
__device__ __nv_bfloat16 g_Wh[(size_t)QKVDIM * DMODEL];  // weight^T hi
__device__ __nv_bfloat16 g_Wl[(size_t)QKVDIM * DMODEL];  // weight^T lo
__device__ __nv_bfloat16 g_Ah[(size_t)ROWS * DMODEL];    // activation hi (gemm input)
__device__ __nv_bfloat16 g_Al[(size_t)ROWS * DMODEL];    // activation lo
__device__ __half g_Q [(size_t)ROWS * DMODEL];           // q, fp16, pre-scaled
__device__ __half g_Kh[(size_t)ROWS * DMODEL];           // k hi fp16
__device__ __half g_Kl[(size_t)ROWS * DMODEL];           // k lo fp16
__device__ __half g_Vh[(size_t)ROWS * DMODEL];           // v hi fp16
__device__ __half g_Vl[(size_t)ROWS * DMODEL];           // v lo fp16

// ===========================================================================
// Helpers
// ===========================================================================
__device__ __forceinline__ uint32_t smem_u32(const void* p) {
    uint32_t a;
    asm("{ .reg .u64 t; cvta.to.shared.u64 t, %1; cvt.u32.u64 %0, t; }"
        : "=r"(a) : "l"(p));
    return a;
}

__device__ __forceinline__ void cp_async16(uint32_t dst, const void* src) {
    asm volatile("cp.async.cg.shared.global [%0], [%1], 16;"
                 :: "r"(dst), "l"(src) : "memory");
}
__device__ __forceinline__ void cp_commit() {
    asm volatile("cp.async.commit_group;" ::: "memory");
}
template <int N>
__device__ __forceinline__ void cp_wait() {
    asm volatile("cp.async.wait_group %0;" :: "n"(N) : "memory");
}

__device__ __forceinline__ void ldsm_x4(uint32_t& r0, uint32_t& r1,
                                        uint32_t& r2, uint32_t& r3,
                                        uint32_t addr) {
    asm volatile("ldmatrix.sync.aligned.m8n8.x4.shared.b16 {%0,%1,%2,%3}, [%4];"
                 : "=r"(r0), "=r"(r1), "=r"(r2), "=r"(r3) : "r"(addr));
}

__device__ __forceinline__ void ldsm_x4_t(uint32_t& r0, uint32_t& r1,
                                          uint32_t& r2, uint32_t& r3,
                                          uint32_t addr) {
    asm volatile("ldmatrix.sync.aligned.m8n8.x4.trans.shared.b16 {%0,%1,%2,%3}, [%4];"
                 : "=r"(r0), "=r"(r1), "=r"(r2), "=r"(r3) : "r"(addr));
}

__device__ __forceinline__ void mma_bf16(float& c0, float& c1, float& c2, float& c3,
                                         uint32_t a0, uint32_t a1, uint32_t a2, uint32_t a3,
                                         uint32_t b0, uint32_t b1) {
    asm volatile(
        "mma.sync.aligned.m16n8k16.row.col.f32.bf16.bf16.f32 "
        "{%0,%1,%2,%3}, {%4,%5,%6,%7}, {%8,%9}, {%0,%1,%2,%3};"
        : "+f"(c0), "+f"(c1), "+f"(c2), "+f"(c3)
        : "r"(a0), "r"(a1), "r"(a2), "r"(a3), "r"(b0), "r"(b1));
}

__device__ __forceinline__ void mma_f16(float& c0, float& c1, float& c2, float& c3,
                                        uint32_t a0, uint32_t a1, uint32_t a2, uint32_t a3,
                                        uint32_t b0, uint32_t b1) {
    asm volatile(
        "mma.sync.aligned.m16n8k16.row.col.f32.f16.f16.f32 "
        "{%0,%1,%2,%3}, {%4,%5,%6,%7}, {%8,%9}, {%0,%1,%2,%3};"
        : "+f"(c0), "+f"(c1), "+f"(c2), "+f"(c3)
        : "r"(a0), "r"(a1), "r"(a2), "r"(a3), "r"(b0), "r"(b1));
}

__device__ __forceinline__ float ex2f(float x) {
    float y;
    asm("ex2.approx.f32 %0, %1;" : "=f"(y) : "f"(x));
    return y;
}

__device__ __forceinline__ uint32_t pack_h2(float lo, float hi) {
    uint32_t d;
    asm("cvt.rn.f16x2.f32 %0, %1, %2;" : "=r"(d) : "f"(hi), "f"(lo));
    return d;
}
__device__ __forceinline__ float2 unpack_h2(uint32_t u) {
    __half2 hh = *reinterpret_cast<__half2*>(&u);
    return __half22float2(hh);
}

// fp32x4 -> bf16 hi/lo split
__device__ __forceinline__ void split4(float4 v, uint2& h8, uint2& l8) {
    __nv_bfloat16 hx = __float2bfloat16(v.x);
    __nv_bfloat16 hy = __float2bfloat16(v.y);
    __nv_bfloat16 hz = __float2bfloat16(v.z);
    __nv_bfloat16 hw = __float2bfloat16(v.w);
    __nv_bfloat16 lx = __float2bfloat16(v.x - __bfloat162float(hx));
    __nv_bfloat16 ly = __float2bfloat16(v.y - __bfloat162float(hy));
    __nv_bfloat16 lz = __float2bfloat16(v.z - __bfloat162float(hz));
    __nv_bfloat16 lw = __float2bfloat16(v.w - __bfloat162float(hw));
    __nv_bfloat162 a; a.x = hx; a.y = hy;
    __nv_bfloat162 b; b.x = hz; b.y = hw;
    __nv_bfloat162 c; c.x = lx; c.y = ly;
    __nv_bfloat162 d; d.x = lz; d.y = lw;
    h8.x = *reinterpret_cast<uint32_t*>(&a);
    h8.y = *reinterpret_cast<uint32_t*>(&b);
    l8.x = *reinterpret_cast<uint32_t*>(&c);
    l8.y = *reinterpret_cast<uint32_t*>(&d);
}

// GEMM smem tile: 128 rows x 32 bf16 cols, 64B rows, xor-swizzled 16B segs
__device__ __forceinline__ uint32_t tile_off(int r, int c) {
    return (uint32_t)(r * 64 + (((((c >> 3) & 3) ^ ((r >> 1) & 3))) << 4)
                      + ((c & 7) << 1));
}

// ===========================================================================
// Pre-processing
// ===========================================================================
__global__ __launch_bounds__(256) void transpose_split(
    const float* __restrict__ in, __nv_bfloat16* __restrict__ Wh,
    __nv_bfloat16* __restrict__ Wl, int K, int N)
{
    __shared__ float t[32][33];
    const int nb = blockIdx.x * 32;
    const int kb = blockIdx.y * 32;
    const int x = threadIdx.x & 31;
    const int y = threadIdx.x >> 5;
    #pragma unroll
    for (int i = 0; i < 32; i += 8)
        t[y + i][x] = in[(size_t)(kb + y + i) * N + nb + x];
    __syncthreads();
    #pragma unroll
    for (int i = 0; i < 32; i += 8) {
        const float v = t[x][y + i];
        const __nv_bfloat16 hi = __float2bfloat16(v);
        const __nv_bfloat16 lo = __float2bfloat16(v - __bfloat162float(hi));
        const size_t o = (size_t)(nb + y + i) * K + kb + x;
        Wh[o] = hi;
        Wl[o] = lo;
    }
}

__global__ __launch_bounds__(256) void split_rows(
    const float* __restrict__ A, __nv_bfloat16* __restrict__ Ah,
    __nv_bfloat16* __restrict__ Al, int total4)
{
    const int i = blockIdx.x * 256 + threadIdx.x;
    if (i < total4) {
        float4 v = ((const float4*)A)[i];
        uint2 h8, l8;
        split4(v, h8, l8);
        *(uint2*)(Ah + (size_t)i * 4) = h8;
        *(uint2*)(Al + (size_t)i * 4) = l8;
    }
}

// ===========================================================================
// bf16 split tensor-core GEMM.
// mode 0: C = fp32 out + bias.
// mode 1: QKV epilogue — q section -> g_Q (fp16, pre-scaled by QSCALE),
//         k section -> g_Kh/g_Kl (fp16 hi/lo), v section -> g_Vh/g_Vl.
// ===========================================================================
#define GBM 128
#define GBN 128
#define GBK 32
#define SB_AH 0
#define SB_AL 8192
#define SB_BH 16384
#define SB_BL 24576
#define SB_BUF 32768
#define GEMM_SMEM (2 * SB_BUF)

__global__ __launch_bounds__(256, 2)
void gemm_bf16(const __nv_bfloat16* __restrict__ Ah, const __nv_bfloat16* __restrict__ Al,
               const __nv_bfloat16* __restrict__ Bh, const __nv_bfloat16* __restrict__ Bl,
               const float* __restrict__ bias, float* __restrict__ C,
               int M, int N, int K, int mode,
               __half* __restrict__ Qo,
               __half* __restrict__ Kho, __half* __restrict__ Klo,
               __half* __restrict__ Vho, __half* __restrict__ Vlo)
{
    extern __shared__ char smg[];
    const uint32_t smb = smem_u32(smg);

    const int tid  = threadIdx.x;
    const int wid  = tid >> 5;
    const int lane = tid & 31;
    const int wm   = wid & 3;
    const int wn   = wid >> 2;
    const int m0 = blockIdx.y * GBM;
    const int n0 = blockIdx.x * GBN;
    const int NCH = K / GBK;

    const int mat = lane >> 3;
    const int l7  = lane & 7;

    auto load_chunk = [&](int c, int b) {
        const int k0 = c * GBK;
        const uint32_t dst = smb + b * SB_BUF;
        #pragma unroll
        for (int t = 0; t < 2; t++) {
            const int j = tid + t * 256;
            const int r = j >> 2, c8 = (j & 3) * 8;
            const uint32_t off = tile_off(r, c8);
            const size_t ga = (size_t)(m0 + r) * K + k0 + c8;
            const size_t gb = (size_t)(n0 + r) * K + k0 + c8;
            cp_async16(dst + SB_AH + off, Ah + ga);
            cp_async16(dst + SB_AL + off, Al + ga);
            cp_async16(dst + SB_BH + off, Bh + gb);
            cp_async16(dst + SB_BL + off, Bl + gb);
        }
        cp_commit();
    };

    float acc[2][8][4];
    #pragma unroll
    for (int mt = 0; mt < 2; mt++)
        #pragma unroll
        for (int nt = 0; nt < 8; nt++)
            #pragma unroll
            for (int j = 0; j < 4; j++)
                acc[mt][nt][j] = 0.0f;

    load_chunk(0, 0);

    for (int c = 0; c < NCH; c++) {
        const int b = c & 1;
        if (c + 1 < NCH) { load_chunk(c + 1, b ^ 1); cp_wait<1>(); }
        else             { cp_wait<0>(); }
        __syncthreads();

        const uint32_t aHi = smb + b * SB_BUF + SB_AH;
        const uint32_t aLo = smb + b * SB_BUF + SB_AL;
        const uint32_t bHi = smb + b * SB_BUF + SB_BH;
        const uint32_t bLo = smb + b * SB_BUF + SB_BL;

        #pragma unroll
        for (int ks = 0; ks < 2; ks++) {
            const int kb = ks * 16;

            uint32_t ah[2][4], al[2][4];
            #pragma unroll
            for (int mt = 0; mt < 2; mt++) {
                const int r  = wm * 32 + mt * 16 + ((mat & 1) << 3) + l7;
                const int kc = kb + ((mat >> 1) << 3);
                const uint32_t off = (uint32_t)(r * 64
                    + (((((kc >> 3) & 3) ^ ((r >> 1) & 3))) << 4));
                ldsm_x4(ah[mt][0], ah[mt][1], ah[mt][2], ah[mt][3], aHi + off);
                ldsm_x4(al[mt][0], al[mt][1], al[mt][2], al[mt][3], aLo + off);
            }

            #pragma unroll
            for (int ph = 0; ph < 2; ph++) {
                uint32_t bh[4][2], bl[4][2];
                #pragma unroll
                for (int p = 0; p < 2; p++) {
                    const int r  = wn * 64 + (ph * 2 + p) * 16 + ((mat >> 1) << 3) + l7;
                    const int kc = kb + ((mat & 1) << 3);
                    const uint32_t off = (uint32_t)(r * 64
                        + (((((kc >> 3) & 3) ^ ((r >> 1) & 3))) << 4));
                    ldsm_x4(bh[2*p][0], bh[2*p][1], bh[2*p+1][0], bh[2*p+1][1], bHi + off);
                    ldsm_x4(bl[2*p][0], bl[2*p][1], bl[2*p+1][0], bl[2*p+1][1], bLo + off);
                }
                #pragma unroll
                for (int mt = 0; mt < 2; mt++)
                    #pragma unroll
                    for (int q = 0; q < 4; q++) {
                        const int nt = ph * 4 + q;
                        mma_bf16(acc[mt][nt][0], acc[mt][nt][1], acc[mt][nt][2], acc[mt][nt][3],
                                 ah[mt][0], ah[mt][1], ah[mt][2], ah[mt][3],
                                 bh[q][0], bh[q][1]);
                        mma_bf16(acc[mt][nt][0], acc[mt][nt][1], acc[mt][nt][2], acc[mt][nt][3],
                                 ah[mt][0], ah[mt][1], ah[mt][2], ah[mt][3],
                                 bl[q][0], bl[q][1]);
                        mma_bf16(acc[mt][nt][0], acc[mt][nt][1], acc[mt][nt][2], acc[mt][nt][3],
                                 al[mt][0], al[mt][1], al[mt][2], al[mt][3],
                                 bh[q][0], bh[q][1]);
                    }
            }
        }
        __syncthreads();
    }

    // Epilogue
    const int er = lane >> 2;
    const int ec = (lane & 3) * 2;
    if (mode == 0) {
        #pragma unroll
        for (int mt = 0; mt < 2; mt++) {
            #pragma unroll
            for (int nt = 0; nt < 8; nt++) {
                const int col = n0 + wn * 64 + nt * 8 + ec;
                const float b0 = bias[col], b1 = bias[col + 1];
                const int row0 = m0 + wm * 32 + mt * 16 + er;
                float2 v0 = make_float2(acc[mt][nt][0] + b0, acc[mt][nt][1] + b1);
                float2 v1 = make_float2(acc[mt][nt][2] + b0, acc[mt][nt][3] + b1);
                *(float2*)(C + (size_t)row0 * N + col)       = v0;
                *(float2*)(C + (size_t)(row0 + 8) * N + col) = v1;
            }
        }
    } else {
        const int sec = n0 >> 10;          // uniform per CTA (GBN=128 | 1024)
        #pragma unroll
        for (int mt = 0; mt < 2; mt++) {
            #pragma unroll
            for (int nt = 0; nt < 8; nt++) {
                const int col = n0 + wn * 64 + nt * 8 + ec;
                const int cloc = col & 1023;
                const float b0 = bias[col], b1 = bias[col + 1];
                const int row0 = m0 + wm * 32 + mt * 16 + er;
                const float x0 = acc[mt][nt][0] + b0, y0 = acc[mt][nt][1] + b1;
                const float x1 = acc[mt][nt][2] + b0, y1 = acc[mt][nt][3] + b1;
                if (sec == 0) {
                    *(uint32_t*)(Qo + (size_t)row0 * DMODEL + cloc)
                        = pack_h2(x0 * QSCALE, y0 * QSCALE);
                    *(uint32_t*)(Qo + (size_t)(row0 + 8) * DMODEL + cloc)
                        = pack_h2(x1 * QSCALE, y1 * QSCALE);
                } else {
                    __half* Hh = (sec == 1) ? Kho : Vho;
                    __half* Hl = (sec == 1) ? Klo : Vlo;
                    uint32_t hh0 = pack_h2(x0, y0);
                    float2 bk0 = unpack_h2(hh0);
                    uint32_t ll0 = pack_h2(x0 - bk0.x, y0 - bk0.y);
                    *(uint32_t*)(Hh + (size_t)row0 * DMODEL + cloc) = hh0;
                    *(uint32_t*)(Hl + (size_t)row0 * DMODEL + cloc) = ll0;
                    uint32_t hh1 = pack_h2(x1, y1);
                    float2 bk1 = unpack_h2(hh1);
                    uint32_t ll1 = pack_h2(x1 - bk1.x, y1 - bk1.y);
                    *(uint32_t*)(Hh + (size_t)(row0 + 8) * DMODEL + cloc) = hh1;
                    *(uint32_t*)(Hl + (size_t)(row0 + 8) * DMODEL + cloc) = ll1;
                }
            }
        }
    }
}

// ===========================================================================
// Tensor-core flash attention, pre-split fp16 inputs, cp.async double buffer.
// smem: Q 16K | stage0 64K (KH,KL,VH,VL) | stage1 64K | rmax 1K | rsum 1K
// O-reduction reuses stage0 after the mainloop.
// ===========================================================================
#define ATT_Q    0
#define ATT_ST   16384
#define ATT_STG  65536
#define ST_KH    0
#define ST_KL    16384
#define ST_VH    32768
#define ST_VL    49152
#define ATT_RMAX (ATT_ST + 2 * ATT_STG)     // 147456
#define ATT_RSUM (ATT_RMAX + 1024)
#define ATT_SMEM (ATT_RSUM + 1024)          // 149504

__global__ __launch_bounds__(256, 1) void attn_mma(
    const __half* __restrict__ Qg,
    const __half* __restrict__ Kh, const __half* __restrict__ Kl,
    const __half* __restrict__ Vh, const __half* __restrict__ Vl,
    __nv_bfloat16* __restrict__ Aho, __nv_bfloat16* __restrict__ Alo)
{
    extern __shared__ char sma[];
    const uint32_t smb = smem_u32(sma);
    float* redmax = (float*)(sma + ATT_RMAX);
    float* redsum = (float*)(sma + ATT_RSUM);

    const int bid = blockIdx.x;
    const int qt  = 15 - (bid >> 5);          // heavy q-tiles first
    const int bh  = bid & 31;
    const int b   = bh >> 4;
    const int h   = bh & 15;

    const int tid  = threadIdx.x;
    const int wid  = tid >> 5;
    const int lane = tid & 31;
    const int wm   = wid & 3;
    const int wn   = wid >> 2;
    const int mat  = lane >> 3;
    const int l7   = lane & 7;
    const int er   = lane >> 2;
    const int ec   = (lane & 3) * 2;

    const size_t rowbase = (size_t)b * SEQ;

    // ---- prefetch one K/V tile (pre-split fp16) into a stage ----
    auto prefetch = [&](int kd2, int st) {
        const uint32_t dst = smb + ATT_ST + st * ATT_STG;
        #pragma unroll
        for (int it = 0; it < 4; it++) {
            const int t = tid + it * 256;       // 1024 segs: 128 rows x 8
            const int r = t >> 3, g = t & 7;
            const uint32_t cb = (uint32_t)(g * 16);
            const uint32_t sw = (uint32_t)(r * 128) + (cb ^ (((uint32_t)(r & 7)) << 4));
            const size_t go = (rowbase + kd2 * 128 + r) * DMODEL + h * DHEAD + g * 8;
            cp_async16(dst + ST_KH + sw, Kh + go);
            cp_async16(dst + ST_KL + sw, Kl + go);
            cp_async16(dst + ST_VH + sw, Vh + go);
            cp_async16(dst + ST_VL + sw, Vl + go);
        }
        cp_commit();
    };

    // ---- Load Q tile (already fp16 + scaled) into smem ----
    #pragma unroll
    for (int it = 0; it < 4; it++) {
        const int t = tid + it * 256;
        const int r = t >> 3, g = t & 7;
        const uint32_t cb = (uint32_t)(g * 16);
        const uint32_t sw = (uint32_t)(r * 128) + (cb ^ (((uint32_t)(r & 7)) << 4));
        uint4 v = *(const uint4*)(Qg + (rowbase + qt * 128 + r) * DMODEL + h * DHEAD + g * 8);
        *(uint4*)(sma + ATT_Q + sw) = v;
    }
    prefetch(0, 0);
    __syncthreads();

    // ---- Q A-fragments (persistent) ----
    uint32_t qa[2][4][4];
    #pragma unroll
    for (int mt = 0; mt < 2; mt++) {
        #pragma unroll
        for (int k16 = 0; k16 < 4; k16++) {
            const int r  = wm * 32 + mt * 16 + ((mat & 1) << 3) + l7;
            const uint32_t cb = (uint32_t)((k16 * 16 + ((mat >> 1) << 3)) * 2);
            const uint32_t sw = (uint32_t)(r * 128) + (cb ^ (((uint32_t)(r & 7)) << 4));
            ldsm_x4(qa[mt][k16][0], qa[mt][k16][1], qa[mt][k16][2], qa[mt][k16][3],
                    smb + ATT_Q + sw);
        }
    }

    float mst[2][2], lst[2][2], oa[2][8][4];
    #pragma unroll
    for (int mt = 0; mt < 2; mt++)
        #pragma unroll
        for (int h2 = 0; h2 < 2; h2++) { mst[mt][h2] = -1e30f; lst[mt][h2] = 0.0f; }
    #pragma unroll
    for (int mt = 0; mt < 2; mt++)
        #pragma unroll
        for (int nt = 0; nt < 8; nt++)
            #pragma unroll
            for (int j = 0; j < 4; j++) oa[mt][nt][j] = 0.0f;

    for (int kd = 0; kd <= qt; kd++) {
        const int st = kd & 1;
        if (kd < qt) { prefetch(kd + 1, st ^ 1); cp_wait<1>(); }
        else         { cp_wait<0>(); }
        __syncthreads();

        const uint32_t stb = smb + ATT_ST + st * ATT_STG;

        // ---- S = Q @ K^T (2 products: Khi, Klo) ----
        float sc[2][8][4];
        #pragma unroll
        for (int mt = 0; mt < 2; mt++)
            #pragma unroll
            for (int nt = 0; nt < 8; nt++)
                #pragma unroll
                for (int j = 0; j < 4; j++) sc[mt][nt][j] = 0.0f;

        #pragma unroll
        for (int k16 = 0; k16 < 4; k16++) {
            uint32_t bf[8][2];
            #pragma unroll
            for (int p = 0; p < 4; p++) {
                const int r = wn * 64 + p * 16 + ((mat >> 1) << 3) + l7;
                const uint32_t cb = (uint32_t)((k16 * 16 + ((mat & 1) << 3)) * 2);
                const uint32_t sw = (uint32_t)(r * 128) + (cb ^ (((uint32_t)(r & 7)) << 4));
                ldsm_x4(bf[2*p][0], bf[2*p][1], bf[2*p+1][0], bf[2*p+1][1],
                        stb + ST_KH + sw);
            }
            #pragma unroll
            for (int mt = 0; mt < 2; mt++)
                #pragma unroll
                for (int nt = 0; nt < 8; nt++)
                    mma_f16(sc[mt][nt][0], sc[mt][nt][1], sc[mt][nt][2], sc[mt][nt][3],
                            qa[mt][k16][0], qa[mt][k16][1], qa[mt][k16][2], qa[mt][k16][3],
                            bf[nt][0], bf[nt][1]);
            #pragma unroll
            for (int p = 0; p < 4; p++) {
                const int r = wn * 64 + p * 16 + ((mat >> 1) << 3) + l7;
                const uint32_t cb = (uint32_t)((k16 * 16 + ((mat & 1) << 3)) * 2);
                const uint32_t sw = (uint32_t)(r * 128) + (cb ^ (((uint32_t)(r & 7)) << 4));
                ldsm_x4(bf[2*p][0], bf[2*p][1], bf[2*p+1][0], bf[2*p+1][1],
                        stb + ST_KL + sw);
            }
            #pragma unroll
            for (int mt = 0; mt < 2; mt++)
                #pragma unroll
                for (int nt = 0; nt < 8; nt++)
                    mma_f16(sc[mt][nt][0], sc[mt][nt][1], sc[mt][nt][2], sc[mt][nt][3],
                            qa[mt][k16][0], qa[mt][k16][1], qa[mt][k16][2], qa[mt][k16][3],
                            bf[nt][0], bf[nt][1]);
        }

        // ---- Causal mask (diagonal tile only) ----
        if (kd == qt) {
            #pragma unroll
            for (int mt = 0; mt < 2; mt++)
                #pragma unroll
                for (int nt = 0; nt < 8; nt++)
                    #pragma unroll
                    for (int j = 0; j < 4; j++) {
                        const int row = wm * 32 + mt * 16 + (j >> 1) * 8 + er;
                        const int col = wn * 64 + nt * 8 + ec + (j & 1);
                        if (col > row) sc[mt][nt][j] = -1e30f;
                    }
        }

        // ---- Row max ----
        #pragma unroll
        for (int mt = 0; mt < 2; mt++)
            #pragma unroll
            for (int h2 = 0; h2 < 2; h2++) {
                float mx = -1e30f;
                #pragma unroll
                for (int nt = 0; nt < 8; nt++) {
                    mx = fmaxf(mx, sc[mt][nt][2*h2]);
                    mx = fmaxf(mx, sc[mt][nt][2*h2+1]);
                }
                mx = fmaxf(mx, __shfl_xor_sync(0xffffffffu, mx, 1));
                mx = fmaxf(mx, __shfl_xor_sync(0xffffffffu, mx, 2));
                if ((lane & 3) == 0)
                    redmax[wn * 128 + wm * 32 + mt * 16 + h2 * 8 + er] = mx;
            }
        __syncthreads();

        float corr[2][2];
        #pragma unroll
        for (int mt = 0; mt < 2; mt++)
            #pragma unroll
            for (int h2 = 0; h2 < 2; h2++) {
                const int row = wm * 32 + mt * 16 + h2 * 8 + er;
                const float g = fmaxf(redmax[row], redmax[128 + row]);
                const float mnew = fmaxf(mst[mt][h2], g);
                corr[mt][h2] = ex2f(mst[mt][h2] - mnew);
                mst[mt][h2] = mnew;
            }

        // ---- exp2 + row sums ----
        float psum[2][2] = {{0.0f, 0.0f}, {0.0f, 0.0f}};
        #pragma unroll
        for (int mt = 0; mt < 2; mt++)
            #pragma unroll
            for (int nt = 0; nt < 8; nt++)
                #pragma unroll
                for (int j = 0; j < 4; j++) {
                    const int h2 = j >> 1;
                    const float pv = ex2f(sc[mt][nt][j] - mst[mt][h2]);
                    sc[mt][nt][j] = pv;
                    psum[mt][h2] += pv;
                }
        #pragma unroll
        for (int mt = 0; mt < 2; mt++)
            #pragma unroll
            for (int h2 = 0; h2 < 2; h2++) {
                float s = psum[mt][h2];
                s += __shfl_xor_sync(0xffffffffu, s, 1);
                s += __shfl_xor_sync(0xffffffffu, s, 2);
                if ((lane & 3) == 0)
                    redsum[wn * 128 + wm * 32 + mt * 16 + h2 * 8 + er] = s;
            }
        __syncthreads();

        #pragma unroll
        for (int mt = 0; mt < 2; mt++)
            #pragma unroll
            for (int h2 = 0; h2 < 2; h2++) {
                const int row = wm * 32 + mt * 16 + h2 * 8 + er;
                lst[mt][h2] = lst[mt][h2] * corr[mt][h2]
                            + redsum[row] + redsum[128 + row];
            }
        #pragma unroll
        for (int mt = 0; mt < 2; mt++)
            #pragma unroll
            for (int nt = 0; nt < 8; nt++)
                #pragma unroll
                for (int j = 0; j < 4; j++)
                    oa[mt][nt][j] *= corr[mt][j >> 1];

        // ---- PV (3 products: Ph.Vh, Pl.Vh, Ph.Vl) ----
        #pragma unroll
        for (int kt2 = 0; kt2 < 4; kt2++) {
            uint32_t ah[2][4], al[2][4];
            #pragma unroll
            for (int mt = 0; mt < 2; mt++) {
                #pragma unroll
                for (int q4 = 0; q4 < 4; q4++) {
                    const int nt = 2 * kt2 + (q4 >> 1);
                    const int j0 = (q4 & 1) * 2;
                    const float p0 = sc[mt][nt][j0], p1 = sc[mt][nt][j0 + 1];
                    const uint32_t hh = pack_h2(p0, p1);
                    const float2 bk = unpack_h2(hh);
                    ah[mt][q4] = hh;
                    al[mt][q4] = pack_h2(p0 - bk.x, p1 - bk.y);
                }
            }
            uint32_t bvh[8][2], bvl[8][2];
            #pragma unroll
            for (int ntp = 0; ntp < 4; ntp++) {
                const int r = wn * 64 + kt2 * 16 + ((mat & 1) << 3) + l7;
                const uint32_t cb = (uint32_t)((ntp * 16 + ((mat >> 1) << 3)) * 2);
                const uint32_t sw = (uint32_t)(r * 128) + (cb ^ (((uint32_t)(r & 7)) << 4));
                ldsm_x4_t(bvh[2*ntp][0], bvh[2*ntp][1], bvh[2*ntp+1][0], bvh[2*ntp+1][1],
                          stb + ST_VH + sw);
                ldsm_x4_t(bvl[2*ntp][0], bvl[2*ntp][1], bvl[2*ntp+1][0], bvl[2*ntp+1][1],
                          stb + ST_VL + sw);
            }
            #pragma unroll
            for (int mt = 0; mt < 2; mt++)
                #pragma unroll
                for (int nt = 0; nt < 8; nt++) {
                    mma_f16(oa[mt][nt][0], oa[mt][nt][1], oa[mt][nt][2], oa[mt][nt][3],
                            ah[mt][0], ah[mt][1], ah[mt][2], ah[mt][3],
                            bvh[nt][0], bvh[nt][1]);
                    mma_f16(oa[mt][nt][0], oa[mt][nt][1], oa[mt][nt][2], oa[mt][nt][3],
                            al[mt][0], al[mt][1], al[mt][2], al[mt][3],
                            bvh[nt][0], bvh[nt][1]);
                    mma_f16(oa[mt][nt][0], oa[mt][nt][1], oa[mt][nt][2], oa[mt][nt][3],
                            ah[mt][0], ah[mt][1], ah[mt][2], ah[mt][3],
                            bvl[nt][0], bvl[nt][1]);
                }
        }
        __syncthreads();   // protect stage st before next-iter prefetch
    }

    // ---- Combine n-warp partials (reuse stage0 smem), write bf16 hi/lo ----
    float* ored = (float*)(sma + ATT_ST);
    if (wn == 1) {
        #pragma unroll
        for (int mt = 0; mt < 2; mt++)
            #pragma unroll
            for (int nt = 0; nt < 8; nt++)
                #pragma unroll
                for (int h2 = 0; h2 < 2; h2++) {
                    const int row = wm * 32 + mt * 16 + h2 * 8 + er;
                    *(float2*)&ored[row * 64 + nt * 8 + ec] =
                        make_float2(oa[mt][nt][2*h2], oa[mt][nt][2*h2+1]);
                }
    }
    __syncthreads();
    if (wn == 0) {
        #pragma unroll
        for (int mt = 0; mt < 2; mt++)
            #pragma unroll
            for (int h2 = 0; h2 < 2; h2++) {
                const float inv = 1.0f / lst[mt][h2];
                const int row = wm * 32 + mt * 16 + h2 * 8 + er;
                const size_t go = (rowbase + qt * 128 + row) * DMODEL + h * DHEAD;
                #pragma unroll
                for (int nt = 0; nt < 8; nt++) {
                    const float2 o2 = *(const float2*)&ored[row * 64 + nt * 8 + ec];
                    const float wx = (oa[mt][nt][2*h2]     + o2.x) * inv;
                    const float wy = (oa[mt][nt][2*h2 + 1] + o2.y) * inv;
                    const __nv_bfloat16 hx = __float2bfloat16(wx);
                    const __nv_bfloat16 hy = __float2bfloat16(wy);
                    const __nv_bfloat16 lx = __float2bfloat16(wx - __bfloat162float(hx));
                    const __nv_bfloat16 ly = __float2bfloat16(wy - __bfloat162float(hy));
                    __nv_bfloat162 hp; hp.x = hx; hp.y = hy;
                    __nv_bfloat162 lp; lp.x = lx; lp.y = ly;
                    *(uint32_t*)(Aho + go + nt * 8 + ec) = *reinterpret_cast<uint32_t*>(&hp);
                    *(uint32_t*)(Alo + go + nt * 8 + ec) = *reinterpret_cast<uint32_t*>(&lp);
                }
            }
    }
}

// ===========================================================================
// kernel_launch
// ===========================================================================
extern "C" void kernel_launch(void* const* d_in, const int* in_sizes, int n_in,
                              void* d_out, int out_size)
{
    const float* hidden = (const float*)d_in[0];
    const float* Wqkv   = (const float*)d_in[2];
    const float* bqkv   = (const float*)d_in[3];
    const float* Wproj  = (const float*)d_in[4];
    const float* bproj  = (const float*)d_in[5];
    float* out = (float*)d_out;

    __nv_bfloat16 *Wh, *Wl, *Ah, *Al;
    __half *Q, *Kh, *Kl, *Vh, *Vl;
    cudaGetSymbolAddress((void**)&Wh, g_Wh);
    cudaGetSymbolAddress((void**)&Wl, g_Wl);
    cudaGetSymbolAddress((void**)&Ah, g_Ah);
    cudaGetSymbolAddress((void**)&Al, g_Al);
    cudaGetSymbolAddress((void**)&Q,  g_Q);
    cudaGetSymbolAddress((void**)&Kh, g_Kh);
    cudaGetSymbolAddress((void**)&Kl, g_Kl);
    cudaGetSymbolAddress((void**)&Vh, g_Vh);
    cudaGetSymbolAddress((void**)&Vl, g_Vl);

    static bool attr_set = false;
    if (!attr_set) {
        cudaFuncSetAttribute(gemm_bf16, cudaFuncAttributeMaxDynamicSharedMemorySize,
                             GEMM_SMEM);
        cudaFuncSetAttribute(attn_mma, cudaFuncAttributeMaxDynamicSharedMemorySize,
                             ATT_SMEM);
        attr_set = true;
    }

    const int act4 = ROWS * DMODEL / 4;

    // ---- QKV projection (epilogue emits attention-native fp16 buffers) ----
    {
        dim3 gw(QKVDIM / 32, DMODEL / 32);
        transpose_split<<<gw, 256>>>(Wqkv, Wh, Wl, DMODEL, QKVDIM);
        split_rows<<<(act4 + 255) / 256, 256>>>(hidden, Ah, Al, act4);
        dim3 grid(QKVDIM / GBN, ROWS / GBM);   // (24, 32)
        gemm_bf16<<<grid, 256, GEMM_SMEM>>>(Ah, Al, Wh, Wl, bqkv, nullptr,
                                            ROWS, QKVDIM, DMODEL, 1,
                                            Q, Kh, Kl, Vh, Vl);
    }

    // ---- Flash causal attention (writes bf16 hi/lo for proj) ----
    attn_mma<<<512, 256, ATT_SMEM>>>(Q, Kh, Kl, Vh, Vl, Ah, Al);

    // ---- Output projection ----
    {
        dim3 gw(DMODEL / 32, DMODEL / 32);
        transpose_split<<<gw, 256>>>(Wproj, Wh, Wl, DMODEL, DMODEL);
        dim3 grid(DMODEL / GBN, ROWS / GBM);   // (8, 32)
        gemm_bf16<<<grid, 256, GEMM_SMEM>>>(Ah, Al, Wh, Wl, bproj, out,
                                            ROWS, DMODEL, DMODEL, 0,
                                            nullptr, nullptr, nullptr, nullptr, nullptr);
    }
}

// round 8
// speedup vs baseline: 8.7983x; 1.0649x over previous
#include <cuda_runtime.h>
#include <cuda_bf16.h>
#include <cuda_fp16.h>
#include <cstdint>

// Problem constants (fixed by the dataset)
#define BATCH 2
#define SEQ   2048
#define DMODEL 1024
#define NHEAD 16
#define DHEAD 64
#define QKVDIM (3 * NHEAD * DHEAD)   // 3072
#define ROWS  (BATCH * SEQ)          // 4096

#define QSCALE (0.125f * 1.44269504088896340736f)   // 1/sqrt(64) * log2(e)

// Scratch (allocation-free rule: __device__ globals)
__device__ __nv_bfloat16 g_Wh[(size_t)QKVDIM * DMODEL];  // weight^T hi
__device__ __nv_bfloat16 g_Wl[(size_t)QKVDIM * DMODEL];  // weight^T lo
__device__ __nv_bfloat16 g_Ah[(size_t)ROWS * DMODEL];    // activation hi (gemm input)
__device__ __nv_bfloat16 g_Al[(size_t)ROWS * DMODEL];    // activation lo
__device__ __half g_Q [(size_t)ROWS * DMODEL];           // q, fp16, pre-scaled
__device__ __half g_Kh[(size_t)ROWS * DMODEL];           // k hi fp16
__device__ __half g_Kl[(size_t)ROWS * DMODEL];           // k lo fp16
__device__ __half g_Vh[(size_t)ROWS * DMODEL];           // v hi fp16

// ===========================================================================
// Helpers
// ===========================================================================
__device__ __forceinline__ uint32_t smem_u32(const void* p) {
    uint32_t a;
    asm("{ .reg .u64 t; cvta.to.shared.u64 t, %1; cvt.u32.u64 %0, t; }"
        : "=r"(a) : "l"(p));
    return a;
}

__device__ __forceinline__ void cp_async16(uint32_t dst, const void* src) {
    asm volatile("cp.async.cg.shared.global [%0], [%1], 16;"
                 :: "r"(dst), "l"(src) : "memory");
}
__device__ __forceinline__ void cp_commit() {
    asm volatile("cp.async.commit_group;" ::: "memory");
}
template <int N>
__device__ __forceinline__ void cp_wait() {
    asm volatile("cp.async.wait_group %0;" :: "n"(N) : "memory");
}

__device__ __forceinline__ void ldsm_x4(uint32_t& r0, uint32_t& r1,
                                        uint32_t& r2, uint32_t& r3,
                                        uint32_t addr) {
    asm volatile("ldmatrix.sync.aligned.m8n8.x4.shared.b16 {%0,%1,%2,%3}, [%4];"
                 : "=r"(r0), "=r"(r1), "=r"(r2), "=r"(r3) : "r"(addr));
}

__device__ __forceinline__ void ldsm_x4_t(uint32_t& r0, uint32_t& r1,
                                          uint32_t& r2, uint32_t& r3,
                                          uint32_t addr) {
    asm volatile("ldmatrix.sync.aligned.m8n8.x4.trans.shared.b16 {%0,%1,%2,%3}, [%4];"
                 : "=r"(r0), "=r"(r1), "=r"(r2), "=r"(r3) : "r"(addr));
}

__device__ __forceinline__ void mma_bf16(float& c0, float& c1, float& c2, float& c3,
                                         uint32_t a0, uint32_t a1, uint32_t a2, uint32_t a3,
                                         uint32_t b0, uint32_t b1) {
    asm volatile(
        "mma.sync.aligned.m16n8k16.row.col.f32.bf16.bf16.f32 "
        "{%0,%1,%2,%3}, {%4,%5,%6,%7}, {%8,%9}, {%0,%1,%2,%3};"
        : "+f"(c0), "+f"(c1), "+f"(c2), "+f"(c3)
        : "r"(a0), "r"(a1), "r"(a2), "r"(a3), "r"(b0), "r"(b1));
}

__device__ __forceinline__ void mma_f16(float& c0, float& c1, float& c2, float& c3,
                                        uint32_t a0, uint32_t a1, uint32_t a2, uint32_t a3,
                                        uint32_t b0, uint32_t b1) {
    asm volatile(
        "mma.sync.aligned.m16n8k16.row.col.f32.f16.f16.f32 "
        "{%0,%1,%2,%3}, {%4,%5,%6,%7}, {%8,%9}, {%0,%1,%2,%3};"
        : "+f"(c0), "+f"(c1), "+f"(c2), "+f"(c3)
        : "r"(a0), "r"(a1), "r"(a2), "r"(a3), "r"(b0), "r"(b1));
}

__device__ __forceinline__ float ex2f(float x) {
    float y;
    asm("ex2.approx.f32 %0, %1;" : "=f"(y) : "f"(x));
    return y;
}

__device__ __forceinline__ uint32_t pack_h2(float lo, float hi) {
    uint32_t d;
    asm("cvt.rn.f16x2.f32 %0, %1, %2;" : "=r"(d) : "f"(hi), "f"(lo));
    return d;
}
__device__ __forceinline__ float2 unpack_h2(uint32_t u) {
    __half2 hh = *reinterpret_cast<__half2*>(&u);
    return __half22float2(hh);
}

// fp32x4 -> bf16 hi/lo split
__device__ __forceinline__ void split4(float4 v, uint2& h8, uint2& l8) {
    __nv_bfloat16 hx = __float2bfloat16(v.x);
    __nv_bfloat16 hy = __float2bfloat16(v.y);
    __nv_bfloat16 hz = __float2bfloat16(v.z);
    __nv_bfloat16 hw = __float2bfloat16(v.w);
    __nv_bfloat16 lx = __float2bfloat16(v.x - __bfloat162float(hx));
    __nv_bfloat16 ly = __float2bfloat16(v.y - __bfloat162float(hy));
    __nv_bfloat16 lz = __float2bfloat16(v.z - __bfloat162float(hz));
    __nv_bfloat16 lw = __float2bfloat16(v.w - __bfloat162float(hw));
    __nv_bfloat162 a; a.x = hx; a.y = hy;
    __nv_bfloat162 b; b.x = hz; b.y = hw;
    __nv_bfloat162 c; c.x = lx; c.y = ly;
    __nv_bfloat162 d; d.x = lz; d.y = lw;
    h8.x = *reinterpret_cast<uint32_t*>(&a);
    h8.y = *reinterpret_cast<uint32_t*>(&b);
    l8.x = *reinterpret_cast<uint32_t*>(&c);
    l8.y = *reinterpret_cast<uint32_t*>(&d);
}

// GEMM smem tile: 128 rows x 32 bf16 cols, 64B rows, xor-swizzled 16B segs
__device__ __forceinline__ uint32_t tile_off(int r, int c) {
    return (uint32_t)(r * 64 + (((((c >> 3) & 3) ^ ((r >> 1) & 3))) << 4)
                      + ((c & 7) << 1));
}

// ===========================================================================
// Pre-processing
// ===========================================================================
__global__ __launch_bounds__(256) void transpose_split(
    const float* __restrict__ in, __nv_bfloat16* __restrict__ Wh,
    __nv_bfloat16* __restrict__ Wl, int K, int N)
{
    __shared__ float t[32][33];
    const int nb = blockIdx.x * 32;
    const int kb = blockIdx.y * 32;
    const int x = threadIdx.x & 31;
    const int y = threadIdx.x >> 5;
    #pragma unroll
    for (int i = 0; i < 32; i += 8)
        t[y + i][x] = in[(size_t)(kb + y + i) * N + nb + x];
    __syncthreads();
    #pragma unroll
    for (int i = 0; i < 32; i += 8) {
        const float v = t[x][y + i];
        const __nv_bfloat16 hi = __float2bfloat16(v);
        const __nv_bfloat16 lo = __float2bfloat16(v - __bfloat162float(hi));
        const size_t o = (size_t)(nb + y + i) * K + kb + x;
        Wh[o] = hi;
        Wl[o] = lo;
    }
}

__global__ __launch_bounds__(256) void split_rows(
    const float* __restrict__ A, __nv_bfloat16* __restrict__ Ah,
    __nv_bfloat16* __restrict__ Al, int total4)
{
    const int i = blockIdx.x * 256 + threadIdx.x;
    if (i < total4) {
        float4 v = ((const float4*)A)[i];
        uint2 h8, l8;
        split4(v, h8, l8);
        *(uint2*)(Ah + (size_t)i * 4) = h8;
        *(uint2*)(Al + (size_t)i * 4) = l8;
    }
}

// ===========================================================================
// bf16 split tensor-core GEMM.
// mode 0: C = fp32 out + bias.
// mode 1: QKV epilogue — q -> g_Q (fp16, QSCALE), k -> g_Kh/g_Kl, v -> g_Vh.
// ===========================================================================
#define GBM 128
#define GBN 128
#define GBK 32
#define SB_AH 0
#define SB_AL 8192
#define SB_BH 16384
#define SB_BL 24576
#define SB_BUF 32768
#define GEMM_SMEM (2 * SB_BUF)

__global__ __launch_bounds__(256, 2)
void gemm_bf16(const __nv_bfloat16* __restrict__ Ah, const __nv_bfloat16* __restrict__ Al,
               const __nv_bfloat16* __restrict__ Bh, const __nv_bfloat16* __restrict__ Bl,
               const float* __restrict__ bias, float* __restrict__ C,
               int M, int N, int K, int mode,
               __half* __restrict__ Qo,
               __half* __restrict__ Kho, __half* __restrict__ Klo,
               __half* __restrict__ Vho)
{
    extern __shared__ char smg[];
    const uint32_t smb = smem_u32(smg);

    const int tid  = threadIdx.x;
    const int wid  = tid >> 5;
    const int lane = tid & 31;
    const int wm   = wid & 3;
    const int wn   = wid >> 2;
    const int m0 = blockIdx.y * GBM;
    const int n0 = blockIdx.x * GBN;
    const int NCH = K / GBK;

    const int mat = lane >> 3;
    const int l7  = lane & 7;

    auto load_chunk = [&](int c, int b) {
        const int k0 = c * GBK;
        const uint32_t dst = smb + b * SB_BUF;
        #pragma unroll
        for (int t = 0; t < 2; t++) {
            const int j = tid + t * 256;
            const int r = j >> 2, c8 = (j & 3) * 8;
            const uint32_t off = tile_off(r, c8);
            const size_t ga = (size_t)(m0 + r) * K + k0 + c8;
            const size_t gb = (size_t)(n0 + r) * K + k0 + c8;
            cp_async16(dst + SB_AH + off, Ah + ga);
            cp_async16(dst + SB_AL + off, Al + ga);
            cp_async16(dst + SB_BH + off, Bh + gb);
            cp_async16(dst + SB_BL + off, Bl + gb);
        }
        cp_commit();
    };

    float acc[2][8][4];
    #pragma unroll
    for (int mt = 0; mt < 2; mt++)
        #pragma unroll
        for (int nt = 0; nt < 8; nt++)
            #pragma unroll
            for (int j = 0; j < 4; j++)
                acc[mt][nt][j] = 0.0f;

    load_chunk(0, 0);

    for (int c = 0; c < NCH; c++) {
        const int b = c & 1;
        if (c + 1 < NCH) { load_chunk(c + 1, b ^ 1); cp_wait<1>(); }
        else             { cp_wait<0>(); }
        __syncthreads();

        const uint32_t aHi = smb + b * SB_BUF + SB_AH;
        const uint32_t aLo = smb + b * SB_BUF + SB_AL;
        const uint32_t bHi = smb + b * SB_BUF + SB_BH;
        const uint32_t bLo = smb + b * SB_BUF + SB_BL;

        #pragma unroll
        for (int ks = 0; ks < 2; ks++) {
            const int kb = ks * 16;

            uint32_t ah[2][4], al[2][4];
            #pragma unroll
            for (int mt = 0; mt < 2; mt++) {
                const int r  = wm * 32 + mt * 16 + ((mat & 1) << 3) + l7;
                const int kc = kb + ((mat >> 1) << 3);
                const uint32_t off = (uint32_t)(r * 64
                    + (((((kc >> 3) & 3) ^ ((r >> 1) & 3))) << 4));
                ldsm_x4(ah[mt][0], ah[mt][1], ah[mt][2], ah[mt][3], aHi + off);
                ldsm_x4(al[mt][0], al[mt][1], al[mt][2], al[mt][3], aLo + off);
            }

            #pragma unroll
            for (int ph = 0; ph < 2; ph++) {
                uint32_t bh[4][2], bl[4][2];
                #pragma unroll
                for (int p = 0; p < 2; p++) {
                    const int r  = wn * 64 + (ph * 2 + p) * 16 + ((mat >> 1) << 3) + l7;
                    const int kc = kb + ((mat & 1) << 3);
                    const uint32_t off = (uint32_t)(r * 64
                        + (((((kc >> 3) & 3) ^ ((r >> 1) & 3))) << 4));
                    ldsm_x4(bh[2*p][0], bh[2*p][1], bh[2*p+1][0], bh[2*p+1][1], bHi + off);
                    ldsm_x4(bl[2*p][0], bl[2*p][1], bl[2*p+1][0], bl[2*p+1][1], bLo + off);
                }
                #pragma unroll
                for (int mt = 0; mt < 2; mt++)
                    #pragma unroll
                    for (int q = 0; q < 4; q++) {
                        const int nt = ph * 4 + q;
                        mma_bf16(acc[mt][nt][0], acc[mt][nt][1], acc[mt][nt][2], acc[mt][nt][3],
                                 ah[mt][0], ah[mt][1], ah[mt][2], ah[mt][3],
                                 bh[q][0], bh[q][1]);
                        mma_bf16(acc[mt][nt][0], acc[mt][nt][1], acc[mt][nt][2], acc[mt][nt][3],
                                 ah[mt][0], ah[mt][1], ah[mt][2], ah[mt][3],
                                 bl[q][0], bl[q][1]);
                        mma_bf16(acc[mt][nt][0], acc[mt][nt][1], acc[mt][nt][2], acc[mt][nt][3],
                                 al[mt][0], al[mt][1], al[mt][2], al[mt][3],
                                 bh[q][0], bh[q][1]);
                    }
            }
        }
        __syncthreads();
    }

    // Epilogue
    const int er = lane >> 2;
    const int ec = (lane & 3) * 2;
    if (mode == 0) {
        #pragma unroll
        for (int mt = 0; mt < 2; mt++) {
            #pragma unroll
            for (int nt = 0; nt < 8; nt++) {
                const int col = n0 + wn * 64 + nt * 8 + ec;
                const float b0 = bias[col], b1 = bias[col + 1];
                const int row0 = m0 + wm * 32 + mt * 16 + er;
                float2 v0 = make_float2(acc[mt][nt][0] + b0, acc[mt][nt][1] + b1);
                float2 v1 = make_float2(acc[mt][nt][2] + b0, acc[mt][nt][3] + b1);
                *(float2*)(C + (size_t)row0 * N + col)       = v0;
                *(float2*)(C + (size_t)(row0 + 8) * N + col) = v1;
            }
        }
    } else {
        const int sec = n0 >> 10;          // 0=Q, 1=K, 2=V
        #pragma unroll
        for (int mt = 0; mt < 2; mt++) {
            #pragma unroll
            for (int nt = 0; nt < 8; nt++) {
                const int col = n0 + wn * 64 + nt * 8 + ec;
                const int cloc = col & 1023;
                const float b0 = bias[col], b1 = bias[col + 1];
                const int row0 = m0 + wm * 32 + mt * 16 + er;
                const float x0 = acc[mt][nt][0] + b0, y0 = acc[mt][nt][1] + b1;
                const float x1 = acc[mt][nt][2] + b0, y1 = acc[mt][nt][3] + b1;
                if (sec == 0) {
                    *(uint32_t*)(Qo + (size_t)row0 * DMODEL + cloc)
                        = pack_h2(x0 * QSCALE, y0 * QSCALE);
                    *(uint32_t*)(Qo + (size_t)(row0 + 8) * DMODEL + cloc)
                        = pack_h2(x1 * QSCALE, y1 * QSCALE);
                } else if (sec == 1) {
                    uint32_t hh0 = pack_h2(x0, y0);
                    float2 bk0 = unpack_h2(hh0);
                    uint32_t ll0 = pack_h2(x0 - bk0.x, y0 - bk0.y);
                    *(uint32_t*)(Kho + (size_t)row0 * DMODEL + cloc) = hh0;
                    *(uint32_t*)(Klo + (size_t)row0 * DMODEL + cloc) = ll0;
                    uint32_t hh1 = pack_h2(x1, y1);
                    float2 bk1 = unpack_h2(hh1);
                    uint32_t ll1 = pack_h2(x1 - bk1.x, y1 - bk1.y);
                    *(uint32_t*)(Kho + (size_t)(row0 + 8) * DMODEL + cloc) = hh1;
                    *(uint32_t*)(Klo + (size_t)(row0 + 8) * DMODEL + cloc) = ll1;
                } else {
                    *(uint32_t*)(Vho + (size_t)row0 * DMODEL + cloc) = pack_h2(x0, y0);
                    *(uint32_t*)(Vho + (size_t)(row0 + 8) * DMODEL + cloc) = pack_h2(x1, y1);
                }
            }
        }
    }
}

// ===========================================================================
// Tensor-core flash attention.
//  - inputs pre-split fp16 (Q scaled; K hi/lo; V hi only)
//  - PV = (Ph + Pl) . Vh   (2 products)
//  - per-warp local l accumulation (no per-tile sum exchange)
//  - 2 syncthreads per tile (stage-ready, rowmax)
// smem: Q 16K | stage0 48K (KH,KL,VH) | stage1 48K | rmax 1K | lred 1K
// O-reduction reuses stage0 after the mainloop.
// ===========================================================================
#define ATT_Q    0
#define ATT_ST   16384
#define ATT_STG  49152
#define ST_KH    0
#define ST_KL    16384
#define ST_VH    32768
#define ATT_RMAX (ATT_ST + 2 * ATT_STG)     // 114688
#define ATT_LRED (ATT_RMAX + 1024)
#define ATT_SMEM (ATT_LRED + 1024)          // 116736

__global__ __launch_bounds__(256, 1) void attn_mma(
    const __half* __restrict__ Qg,
    const __half* __restrict__ Kh, const __half* __restrict__ Kl,
    const __half* __restrict__ Vh,
    __nv_bfloat16* __restrict__ Aho, __nv_bfloat16* __restrict__ Alo)
{
    extern __shared__ char sma[];
    const uint32_t smb = smem_u32(sma);
    float* redmax = (float*)(sma + ATT_RMAX);
    float* lred   = (float*)(sma + ATT_LRED);

    const int bid = blockIdx.x;
    const int qt  = 15 - (bid >> 5);          // heavy q-tiles first
    const int bh  = bid & 31;
    const int b   = bh >> 4;
    const int h   = bh & 15;

    const int tid  = threadIdx.x;
    const int wid  = tid >> 5;
    const int lane = tid & 31;
    const int wm   = wid & 3;
    const int wn   = wid >> 2;
    const int mat  = lane >> 3;
    const int l7   = lane & 7;
    const int er   = lane >> 2;
    const int ec   = (lane & 3) * 2;

    const size_t rowbase = (size_t)b * SEQ;

    // ---- prefetch one K/V tile into a stage (KH, KL, VH) ----
    auto prefetch = [&](int kd2, int st) {
        const uint32_t dst = smb + ATT_ST + st * ATT_STG;
        #pragma unroll
        for (int it = 0; it < 4; it++) {
            const int t = tid + it * 256;       // 1024 segs: 128 rows x 8
            const int r = t >> 3, g = t & 7;
            const uint32_t cb = (uint32_t)(g * 16);
            const uint32_t sw = (uint32_t)(r * 128) + (cb ^ (((uint32_t)(r & 7)) << 4));
            const size_t go = (rowbase + kd2 * 128 + r) * DMODEL + h * DHEAD + g * 8;
            cp_async16(dst + ST_KH + sw, Kh + go);
            cp_async16(dst + ST_KL + sw, Kl + go);
            cp_async16(dst + ST_VH + sw, Vh + go);
        }
        cp_commit();
    };

    // ---- Load Q tile (already fp16 + scaled) into smem ----
    #pragma unroll
    for (int it = 0; it < 4; it++) {
        const int t = tid + it * 256;
        const int r = t >> 3, g = t & 7;
        const uint32_t cb = (uint32_t)(g * 16);
        const uint32_t sw = (uint32_t)(r * 128) + (cb ^ (((uint32_t)(r & 7)) << 4));
        uint4 v = *(const uint4*)(Qg + (rowbase + qt * 128 + r) * DMODEL + h * DHEAD + g * 8);
        *(uint4*)(sma + ATT_Q + sw) = v;
    }
    prefetch(0, 0);
    __syncthreads();

    // ---- Q A-fragments (persistent) ----
    uint32_t qa[2][4][4];
    #pragma unroll
    for (int mt = 0; mt < 2; mt++) {
        #pragma unroll
        for (int k16 = 0; k16 < 4; k16++) {
            const int r  = wm * 32 + mt * 16 + ((mat & 1) << 3) + l7;
            const uint32_t cb = (uint32_t)((k16 * 16 + ((mat >> 1) << 3)) * 2);
            const uint32_t sw = (uint32_t)(r * 128) + (cb ^ (((uint32_t)(r & 7)) << 4));
            ldsm_x4(qa[mt][k16][0], qa[mt][k16][1], qa[mt][k16][2], qa[mt][k16][3],
                    smb + ATT_Q + sw);
        }
    }

    float mst[2][2], lst[2][2], oa[2][8][4];
    #pragma unroll
    for (int mt = 0; mt < 2; mt++)
        #pragma unroll
        for (int h2 = 0; h2 < 2; h2++) { mst[mt][h2] = -1e30f; lst[mt][h2] = 0.0f; }
    #pragma unroll
    for (int mt = 0; mt < 2; mt++)
        #pragma unroll
        for (int nt = 0; nt < 8; nt++)
            #pragma unroll
            for (int j = 0; j < 4; j++) oa[mt][nt][j] = 0.0f;

    for (int kd = 0; kd <= qt; kd++) {
        const int st = kd & 1;
        cp_wait<0>();
        __syncthreads();   // stage st ready; all warps done with stage st^1
        if (kd < qt) prefetch(kd + 1, st ^ 1);   // safe: everyone passed barrier

        const uint32_t stb = smb + ATT_ST + st * ATT_STG;

        // ---- S = Q @ K^T (2 products: Khi, Klo) ----
        float sc[2][8][4];
        #pragma unroll
        for (int mt = 0; mt < 2; mt++)
            #pragma unroll
            for (int nt = 0; nt < 8; nt++)
                #pragma unroll
                for (int j = 0; j < 4; j++) sc[mt][nt][j] = 0.0f;

        #pragma unroll
        for (int k16 = 0; k16 < 4; k16++) {
            uint32_t bf[8][2];
            #pragma unroll
            for (int p = 0; p < 4; p++) {
                const int r = wn * 64 + p * 16 + ((mat >> 1) << 3) + l7;
                const uint32_t cb = (uint32_t)((k16 * 16 + ((mat & 1) << 3)) * 2);
                const uint32_t sw = (uint32_t)(r * 128) + (cb ^ (((uint32_t)(r & 7)) << 4));
                ldsm_x4(bf[2*p][0], bf[2*p][1], bf[2*p+1][0], bf[2*p+1][1],
                        stb + ST_KH + sw);
            }
            #pragma unroll
            for (int mt = 0; mt < 2; mt++)
                #pragma unroll
                for (int nt = 0; nt < 8; nt++)
                    mma_f16(sc[mt][nt][0], sc[mt][nt][1], sc[mt][nt][2], sc[mt][nt][3],
                            qa[mt][k16][0], qa[mt][k16][1], qa[mt][k16][2], qa[mt][k16][3],
                            bf[nt][0], bf[nt][1]);
            #pragma unroll
            for (int p = 0; p < 4; p++) {
                const int r = wn * 64 + p * 16 + ((mat >> 1) << 3) + l7;
                const uint32_t cb = (uint32_t)((k16 * 16 + ((mat & 1) << 3)) * 2);
                const uint32_t sw = (uint32_t)(r * 128) + (cb ^ (((uint32_t)(r & 7)) << 4));
                ldsm_x4(bf[2*p][0], bf[2*p][1], bf[2*p+1][0], bf[2*p+1][1],
                        stb + ST_KL + sw);
            }
            #pragma unroll
            for (int mt = 0; mt < 2; mt++)
                #pragma unroll
                for (int nt = 0; nt < 8; nt++)
                    mma_f16(sc[mt][nt][0], sc[mt][nt][1], sc[mt][nt][2], sc[mt][nt][3],
                            qa[mt][k16][0], qa[mt][k16][1], qa[mt][k16][2], qa[mt][k16][3],
                            bf[nt][0], bf[nt][1]);
        }

        // ---- Causal mask (diagonal tile only) ----
        if (kd == qt) {
            #pragma unroll
            for (int mt = 0; mt < 2; mt++)
                #pragma unroll
                for (int nt = 0; nt < 8; nt++)
                    #pragma unroll
                    for (int j = 0; j < 4; j++) {
                        const int row = wm * 32 + mt * 16 + (j >> 1) * 8 + er;
                        const int col = wn * 64 + nt * 8 + ec + (j & 1);
                        if (col > row) sc[mt][nt][j] = -1e30f;
                    }
        }

        // ---- Row max (only cross-warp exchange per tile) ----
        #pragma unroll
        for (int mt = 0; mt < 2; mt++)
            #pragma unroll
            for (int h2 = 0; h2 < 2; h2++) {
                float mx = -1e30f;
                #pragma unroll
                for (int nt = 0; nt < 8; nt++) {
                    mx = fmaxf(mx, sc[mt][nt][2*h2]);
                    mx = fmaxf(mx, sc[mt][nt][2*h2+1]);
                }
                mx = fmaxf(mx, __shfl_xor_sync(0xffffffffu, mx, 1));
                mx = fmaxf(mx, __shfl_xor_sync(0xffffffffu, mx, 2));
                if ((lane & 3) == 0)
                    redmax[wn * 128 + wm * 32 + mt * 16 + h2 * 8 + er] = mx;
            }
        __syncthreads();

        float corr[2][2];
        #pragma unroll
        for (int mt = 0; mt < 2; mt++)
            #pragma unroll
            for (int h2 = 0; h2 < 2; h2++) {
                const int row = wm * 32 + mt * 16 + h2 * 8 + er;
                const float g = fmaxf(redmax[row], redmax[128 + row]);
                const float mnew = fmaxf(mst[mt][h2], g);
                corr[mt][h2] = ex2f(mst[mt][h2] - mnew);
                mst[mt][h2] = mnew;
            }

        // ---- exp2 + local l accumulation (no cross-warp sum) ----
        #pragma unroll
        for (int mt = 0; mt < 2; mt++) {
            float psum[2] = {0.0f, 0.0f};
            #pragma unroll
            for (int nt = 0; nt < 8; nt++)
                #pragma unroll
                for (int j = 0; j < 4; j++) {
                    const int h2 = j >> 1;
                    const float pv = ex2f(sc[mt][nt][j] - mst[mt][h2]);
                    sc[mt][nt][j] = pv;
                    psum[h2] += pv;
                }
            #pragma unroll
            for (int h2 = 0; h2 < 2; h2++) {
                float s = psum[h2];
                s += __shfl_xor_sync(0xffffffffu, s, 1);
                s += __shfl_xor_sync(0xffffffffu, s, 2);
                lst[mt][h2] = lst[mt][h2] * corr[mt][h2] + s;
            }
            #pragma unroll
            for (int nt = 0; nt < 8; nt++)
                #pragma unroll
                for (int j = 0; j < 4; j++)
                    oa[mt][nt][j] *= corr[mt][j >> 1];
        }

        // ---- PV: (Ph + Pl) @ Vh (2 products) ----
        #pragma unroll
        for (int kt2 = 0; kt2 < 4; kt2++) {
            uint32_t ah[2][4], al[2][4];
            #pragma unroll
            for (int mt = 0; mt < 2; mt++) {
                #pragma unroll
                for (int q4 = 0; q4 < 4; q4++) {
                    const int nt = 2 * kt2 + (q4 >> 1);
                    const int j0 = (q4 & 1) * 2;
                    const float p0 = sc[mt][nt][j0], p1 = sc[mt][nt][j0 + 1];
                    const uint32_t hh = pack_h2(p0, p1);
                    const float2 bk = unpack_h2(hh);
                    ah[mt][q4] = hh;
                    al[mt][q4] = pack_h2(p0 - bk.x, p1 - bk.y);
                }
            }
            uint32_t bvh[8][2];
            #pragma unroll
            for (int ntp = 0; ntp < 4; ntp++) {
                const int r = wn * 64 + kt2 * 16 + ((mat & 1) << 3) + l7;
                const uint32_t cb = (uint32_t)((ntp * 16 + ((mat >> 1) << 3)) * 2);
                const uint32_t sw = (uint32_t)(r * 128) + (cb ^ (((uint32_t)(r & 7)) << 4));
                ldsm_x4_t(bvh[2*ntp][0], bvh[2*ntp][1], bvh[2*ntp+1][0], bvh[2*ntp+1][1],
                          stb + ST_VH + sw);
            }
            #pragma unroll
            for (int mt = 0; mt < 2; mt++)
                #pragma unroll
                for (int nt = 0; nt < 8; nt++) {
                    mma_f16(oa[mt][nt][0], oa[mt][nt][1], oa[mt][nt][2], oa[mt][nt][3],
                            ah[mt][0], ah[mt][1], ah[mt][2], ah[mt][3],
                            bvh[nt][0], bvh[nt][1]);
                    mma_f16(oa[mt][nt][0], oa[mt][nt][1], oa[mt][nt][2], oa[mt][nt][3],
                            al[mt][0], al[mt][1], al[mt][2], al[mt][3],
                            bvh[nt][0], bvh[nt][1]);
                }
        }
        // no bottom sync: next iteration's stage-ready barrier orders reuse
    }

    // ---- Combine n-warp partials (reuse stage0 smem), write bf16 hi/lo ----
    __syncthreads();
    float* ored = (float*)(sma + ATT_ST);
    if (wn == 1) {
        #pragma unroll
        for (int mt = 0; mt < 2; mt++)
            #pragma unroll
            for (int nt = 0; nt < 8; nt++)
                #pragma unroll
                for (int h2 = 0; h2 < 2; h2++) {
                    const int row = wm * 32 + mt * 16 + h2 * 8 + er;
                    *(float2*)&ored[row * 64 + nt * 8 + ec] =
                        make_float2(oa[mt][nt][2*h2], oa[mt][nt][2*h2+1]);
                }
        #pragma unroll
        for (int mt = 0; mt < 2; mt++)
            #pragma unroll
            for (int h2 = 0; h2 < 2; h2++) {
                const int row = wm * 32 + mt * 16 + h2 * 8 + er;
                lred[row] = lst[mt][h2];     // same value from 4 lanes — benign
            }
    }
    __syncthreads();
    if (wn == 0) {
        #pragma unroll
        for (int mt = 0; mt < 2; mt++)
            #pragma unroll
            for (int h2 = 0; h2 < 2; h2++) {
                const int row = wm * 32 + mt * 16 + h2 * 8 + er;
                const float inv = 1.0f / (lst[mt][h2] + lred[row]);
                const size_t go = (rowbase + qt * 128 + row) * DMODEL + h * DHEAD;
                #pragma unroll
                for (int nt = 0; nt < 8; nt++) {
                    const float2 o2 = *(const float2*)&ored[row * 64 + nt * 8 + ec];
                    const float wx = (oa[mt][nt][2*h2]     + o2.x) * inv;
                    const float wy = (oa[mt][nt][2*h2 + 1] + o2.y) * inv;
                    const __nv_bfloat16 hx = __float2bfloat16(wx);
                    const __nv_bfloat16 hy = __float2bfloat16(wy);
                    const __nv_bfloat16 lx = __float2bfloat16(wx - __bfloat162float(hx));
                    const __nv_bfloat16 ly = __float2bfloat16(wy - __bfloat162float(hy));
                    __nv_bfloat162 hp; hp.x = hx; hp.y = hy;
                    __nv_bfloat162 lp; lp.x = lx; lp.y = ly;
                    *(uint32_t*)(Aho + go + nt * 8 + ec) = *reinterpret_cast<uint32_t*>(&hp);
                    *(uint32_t*)(Alo + go + nt * 8 + ec) = *reinterpret_cast<uint32_t*>(&lp);
                }
            }
    }
}

// ===========================================================================
// kernel_launch
// ===========================================================================
extern "C" void kernel_launch(void* const* d_in, const int* in_sizes, int n_in,
                              void* d_out, int out_size)
{
    const float* hidden = (const float*)d_in[0];
    const float* Wqkv   = (const float*)d_in[2];
    const float* bqkv   = (const float*)d_in[3];
    const float* Wproj  = (const float*)d_in[4];
    const float* bproj  = (const float*)d_in[5];
    float* out = (float*)d_out;

    __nv_bfloat16 *Wh, *Wl, *Ah, *Al;
    __half *Q, *Kh, *Kl, *Vh;
    cudaGetSymbolAddress((void**)&Wh, g_Wh);
    cudaGetSymbolAddress((void**)&Wl, g_Wl);
    cudaGetSymbolAddress((void**)&Ah, g_Ah);
    cudaGetSymbolAddress((void**)&Al, g_Al);
    cudaGetSymbolAddress((void**)&Q,  g_Q);
    cudaGetSymbolAddress((void**)&Kh, g_Kh);
    cudaGetSymbolAddress((void**)&Kl, g_Kl);
    cudaGetSymbolAddress((void**)&Vh, g_Vh);

    static bool attr_set = false;
    if (!attr_set) {
        cudaFuncSetAttribute(gemm_bf16, cudaFuncAttributeMaxDynamicSharedMemorySize,
                             GEMM_SMEM);
        cudaFuncSetAttribute(attn_mma, cudaFuncAttributeMaxDynamicSharedMemorySize,
                             ATT_SMEM);
        attr_set = true;
    }

    const int act4 = ROWS * DMODEL / 4;

    // ---- QKV projection (epilogue emits attention-native fp16 buffers) ----
    {
        dim3 gw(QKVDIM / 32, DMODEL / 32);
        transpose_split<<<gw, 256>>>(Wqkv, Wh, Wl, DMODEL, QKVDIM);
        split_rows<<<(act4 + 255) / 256, 256>>>(hidden, Ah, Al, act4);
        dim3 grid(QKVDIM / GBN, ROWS / GBM);   // (24, 32)
        gemm_bf16<<<grid, 256, GEMM_SMEM>>>(Ah, Al, Wh, Wl, bqkv, nullptr,
                                            ROWS, QKVDIM, DMODEL, 1,
                                            Q, Kh, Kl, Vh);
    }

    // ---- Flash causal attention (writes bf16 hi/lo for proj) ----
    attn_mma<<<512, 256, ATT_SMEM>>>(Q, Kh, Kl, Vh, Ah, Al);

    // ---- Output projection ----
    {
        dim3 gw(DMODEL / 32, DMODEL / 32);
        transpose_split<<<gw, 256>>>(Wproj, Wh, Wl, DMODEL, DMODEL);
        dim3 grid(DMODEL / GBN, ROWS / GBM);   // (8, 32)
        gemm_bf16<<<grid, 256, GEMM_SMEM>>>(Ah, Al, Wh, Wl, bproj, out,
                                            ROWS, DMODEL, DMODEL, 0,
                                            nullptr, nullptr, nullptr, nullptr);
    }
}

// round 9
// speedup vs baseline: 11.1199x; 1.2639x over previous
#include <cuda_runtime.h>
#include <cuda_bf16.h>
#include <cuda_fp16.h>
#include <cstdint>

// Problem constants (fixed by the dataset)
#define BATCH 2
#define SEQ   2048
#define DMODEL 1024
#define NHEAD 16
#define DHEAD 64
#define QKVDIM (3 * NHEAD * DHEAD)   // 3072
#define ROWS  (BATCH * SEQ)          // 4096

#define QSCALE (0.125f * 1.44269504088896340736f)   // 1/sqrt(64) * log2(e)

// Scratch (allocation-free rule: __device__ globals)
__device__ __half g_Wh[(size_t)QKVDIM * DMODEL];    // weight^T hi (fp16)
__device__ __half g_Wl[(size_t)QKVDIM * DMODEL];    // weight^T lo (fp16)
__device__ __half g_Xh[(size_t)ROWS * DMODEL];      // hidden, fp16
__device__ __half g_Oh[(size_t)ROWS * DMODEL];      // attention out, fp16
__device__ __half g_Q [(size_t)ROWS * DMODEL];      // q, fp16, pre-scaled
__device__ __half g_Kh[(size_t)ROWS * DMODEL];      // k hi fp16
__device__ __half g_Kl[(size_t)ROWS * DMODEL];      // k lo fp16
__device__ __half g_Vh[(size_t)ROWS * DMODEL];      // v hi fp16

// ===========================================================================
// Helpers
// ===========================================================================
__device__ __forceinline__ uint32_t smem_u32(const void* p) {
    uint32_t a;
    asm("{ .reg .u64 t; cvta.to.shared.u64 t, %1; cvt.u32.u64 %0, t; }"
        : "=r"(a) : "l"(p));
    return a;
}

__device__ __forceinline__ void cp_async16(uint32_t dst, const void* src) {
    asm volatile("cp.async.cg.shared.global [%0], [%1], 16;"
                 :: "r"(dst), "l"(src) : "memory");
}
__device__ __forceinline__ void cp_commit() {
    asm volatile("cp.async.commit_group;" ::: "memory");
}
template <int N>
__device__ __forceinline__ void cp_wait() {
    asm volatile("cp.async.wait_group %0;" :: "n"(N) : "memory");
}

__device__ __forceinline__ void ldsm_x4(uint32_t& r0, uint32_t& r1,
                                        uint32_t& r2, uint32_t& r3,
                                        uint32_t addr) {
    asm volatile("ldmatrix.sync.aligned.m8n8.x4.shared.b16 {%0,%1,%2,%3}, [%4];"
                 : "=r"(r0), "=r"(r1), "=r"(r2), "=r"(r3) : "r"(addr));
}

__device__ __forceinline__ void ldsm_x4_t(uint32_t& r0, uint32_t& r1,
                                          uint32_t& r2, uint32_t& r3,
                                          uint32_t addr) {
    asm volatile("ldmatrix.sync.aligned.m8n8.x4.trans.shared.b16 {%0,%1,%2,%3}, [%4];"
                 : "=r"(r0), "=r"(r1), "=r"(r2), "=r"(r3) : "r"(addr));
}

__device__ __forceinline__ void mma_f16(float& c0, float& c1, float& c2, float& c3,
                                        uint32_t a0, uint32_t a1, uint32_t a2, uint32_t a3,
                                        uint32_t b0, uint32_t b1) {
    asm volatile(
        "mma.sync.aligned.m16n8k16.row.col.f32.f16.f16.f32 "
        "{%0,%1,%2,%3}, {%4,%5,%6,%7}, {%8,%9}, {%0,%1,%2,%3};"
        : "+f"(c0), "+f"(c1), "+f"(c2), "+f"(c3)
        : "r"(a0), "r"(a1), "r"(a2), "r"(a3), "r"(b0), "r"(b1));
}

__device__ __forceinline__ float ex2f(float x) {
    float y;
    asm("ex2.approx.f32 %0, %1;" : "=f"(y) : "f"(x));
    return y;
}

__device__ __forceinline__ uint32_t pack_h2(float lo, float hi) {
    uint32_t d;
    asm("cvt.rn.f16x2.f32 %0, %1, %2;" : "=r"(d) : "f"(hi), "f"(lo));
    return d;
}
__device__ __forceinline__ float2 unpack_h2(uint32_t u) {
    __half2 hh = *reinterpret_cast<__half2*>(&u);
    return __half22float2(hh);
}

// GEMM smem tile: 128 rows x 32 fp16 cols, 64B rows, xor-swizzled 16B segs
__device__ __forceinline__ uint32_t tile_off(int r, int c) {
    return (uint32_t)(r * 64 + (((((c >> 3) & 3) ^ ((r >> 1) & 3))) << 4)
                      + ((c & 7) << 1));
}

// ===========================================================================
// Pre-processing
// ===========================================================================
__global__ __launch_bounds__(256) void transpose_split(
    const float* __restrict__ in, __half* __restrict__ Wh,
    __half* __restrict__ Wl, int K, int N)
{
    __shared__ float t[32][33];
    const int nb = blockIdx.x * 32;
    const int kb = blockIdx.y * 32;
    const int x = threadIdx.x & 31;
    const int y = threadIdx.x >> 5;
    #pragma unroll
    for (int i = 0; i < 32; i += 8)
        t[y + i][x] = in[(size_t)(kb + y + i) * N + nb + x];
    __syncthreads();
    #pragma unroll
    for (int i = 0; i < 32; i += 8) {
        const float v = t[x][y + i];
        const __half hi = __float2half(v);
        const __half lo = __float2half(v - __half2float(hi));
        const size_t o = (size_t)(nb + y + i) * K + kb + x;
        Wh[o] = hi;
        Wl[o] = lo;
    }
}

__global__ __launch_bounds__(256) void conv_rows(
    const float* __restrict__ A, __half* __restrict__ Ah, int total4)
{
    const int i = blockIdx.x * 256 + threadIdx.x;
    if (i < total4) {
        float4 v = ((const float4*)A)[i];
        uint2 h;
        h.x = pack_h2(v.x, v.y);
        h.y = pack_h2(v.z, v.w);
        *(uint2*)(Ah + (size_t)i * 4) = h;
    }
}

// ===========================================================================
// fp16 tensor-core GEMM: C = A[M,K] @ (Bh+Bl)[N,K]^T + bias[N]
// A single fp16 (2^-12 rounding), B split hi/lo -> 2 MMA products.
// CTA tile 128x128, BK=32, 8 warps (4m x 2n), cp.async double buffer.
// mode 0: fp32 C out. mode 1: QKV epilogue (Q fp16*QSCALE, K hi/lo, V hi).
// ===========================================================================
#define GBM 128
#define GBN 128
#define GBK 32
#define SB_A  0
#define SB_BH 8192
#define SB_BL 16384
#define SB_BUF 24576
#define GEMM_SMEM (2 * SB_BUF)

__global__ __launch_bounds__(256, 2)
void gemm_f16k(const __half* __restrict__ A,
               const __half* __restrict__ Bh, const __half* __restrict__ Bl,
               const float* __restrict__ bias, float* __restrict__ C,
               int M, int N, int K, int mode,
               __half* __restrict__ Qo,
               __half* __restrict__ Kho, __half* __restrict__ Klo,
               __half* __restrict__ Vho)
{
    extern __shared__ char smg[];
    const uint32_t smb = smem_u32(smg);

    const int tid  = threadIdx.x;
    const int wid  = tid >> 5;
    const int lane = tid & 31;
    const int wm   = wid & 3;
    const int wn   = wid >> 2;
    const int m0 = blockIdx.y * GBM;
    const int n0 = blockIdx.x * GBN;
    const int NCH = K / GBK;

    const int mat = lane >> 3;
    const int l7  = lane & 7;

    auto load_chunk = [&](int c, int b) {
        const int k0 = c * GBK;
        const uint32_t dst = smb + b * SB_BUF;
        #pragma unroll
        for (int t = 0; t < 2; t++) {
            const int j = tid + t * 256;
            const int r = j >> 2, c8 = (j & 3) * 8;
            const uint32_t off = tile_off(r, c8);
            cp_async16(dst + SB_A  + off, A  + (size_t)(m0 + r) * K + k0 + c8);
            cp_async16(dst + SB_BH + off, Bh + (size_t)(n0 + r) * K + k0 + c8);
            cp_async16(dst + SB_BL + off, Bl + (size_t)(n0 + r) * K + k0 + c8);
        }
        cp_commit();
    };

    float acc[2][8][4];
    #pragma unroll
    for (int mt = 0; mt < 2; mt++)
        #pragma unroll
        for (int nt = 0; nt < 8; nt++)
            #pragma unroll
            for (int j = 0; j < 4; j++)
                acc[mt][nt][j] = 0.0f;

    load_chunk(0, 0);

    for (int c = 0; c < NCH; c++) {
        const int b = c & 1;
        if (c + 1 < NCH) { load_chunk(c + 1, b ^ 1); cp_wait<1>(); }
        else             { cp_wait<0>(); }
        __syncthreads();

        const uint32_t aB  = smb + b * SB_BUF + SB_A;
        const uint32_t bHi = smb + b * SB_BUF + SB_BH;
        const uint32_t bLo = smb + b * SB_BUF + SB_BL;

        #pragma unroll
        for (int ks = 0; ks < 2; ks++) {
            const int kb = ks * 16;

            uint32_t ah[2][4];
            #pragma unroll
            for (int mt = 0; mt < 2; mt++) {
                const int r  = wm * 32 + mt * 16 + ((mat & 1) << 3) + l7;
                const int kc = kb + ((mat >> 1) << 3);
                const uint32_t off = (uint32_t)(r * 64
                    + (((((kc >> 3) & 3) ^ ((r >> 1) & 3))) << 4));
                ldsm_x4(ah[mt][0], ah[mt][1], ah[mt][2], ah[mt][3], aB + off);
            }

            #pragma unroll
            for (int ph = 0; ph < 2; ph++) {
                uint32_t bh[4][2], bl[4][2];
                #pragma unroll
                for (int p = 0; p < 2; p++) {
                    const int r  = wn * 64 + (ph * 2 + p) * 16 + ((mat >> 1) << 3) + l7;
                    const int kc = kb + ((mat & 1) << 3);
                    const uint32_t off = (uint32_t)(r * 64
                        + (((((kc >> 3) & 3) ^ ((r >> 1) & 3))) << 4));
                    ldsm_x4(bh[2*p][0], bh[2*p][1], bh[2*p+1][0], bh[2*p+1][1], bHi + off);
                    ldsm_x4(bl[2*p][0], bl[2*p][1], bl[2*p+1][0], bl[2*p+1][1], bLo + off);
                }
                #pragma unroll
                for (int mt = 0; mt < 2; mt++)
                    #pragma unroll
                    for (int q = 0; q < 4; q++) {
                        const int nt = ph * 4 + q;
                        mma_f16(acc[mt][nt][0], acc[mt][nt][1], acc[mt][nt][2], acc[mt][nt][3],
                                ah[mt][0], ah[mt][1], ah[mt][2], ah[mt][3],
                                bh[q][0], bh[q][1]);
                        mma_f16(acc[mt][nt][0], acc[mt][nt][1], acc[mt][nt][2], acc[mt][nt][3],
                                ah[mt][0], ah[mt][1], ah[mt][2], ah[mt][3],
                                bl[q][0], bl[q][1]);
                    }
            }
        }
        __syncthreads();
    }

    // Epilogue
    const int er = lane >> 2;
    const int ec = (lane & 3) * 2;
    if (mode == 0) {
        #pragma unroll
        for (int mt = 0; mt < 2; mt++) {
            #pragma unroll
            for (int nt = 0; nt < 8; nt++) {
                const int col = n0 + wn * 64 + nt * 8 + ec;
                const float b0 = bias[col], b1 = bias[col + 1];
                const int row0 = m0 + wm * 32 + mt * 16 + er;
                float2 v0 = make_float2(acc[mt][nt][0] + b0, acc[mt][nt][1] + b1);
                float2 v1 = make_float2(acc[mt][nt][2] + b0, acc[mt][nt][3] + b1);
                *(float2*)(C + (size_t)row0 * N + col)       = v0;
                *(float2*)(C + (size_t)(row0 + 8) * N + col) = v1;
            }
        }
    } else {
        const int sec = n0 >> 10;          // 0=Q, 1=K, 2=V
        #pragma unroll
        for (int mt = 0; mt < 2; mt++) {
            #pragma unroll
            for (int nt = 0; nt < 8; nt++) {
                const int col = n0 + wn * 64 + nt * 8 + ec;
                const int cloc = col & 1023;
                const float b0 = bias[col], b1 = bias[col + 1];
                const int row0 = m0 + wm * 32 + mt * 16 + er;
                const float x0 = acc[mt][nt][0] + b0, y0 = acc[mt][nt][1] + b1;
                const float x1 = acc[mt][nt][2] + b0, y1 = acc[mt][nt][3] + b1;
                if (sec == 0) {
                    *(uint32_t*)(Qo + (size_t)row0 * DMODEL + cloc)
                        = pack_h2(x0 * QSCALE, y0 * QSCALE);
                    *(uint32_t*)(Qo + (size_t)(row0 + 8) * DMODEL + cloc)
                        = pack_h2(x1 * QSCALE, y1 * QSCALE);
                } else if (sec == 1) {
                    uint32_t hh0 = pack_h2(x0, y0);
                    float2 bk0 = unpack_h2(hh0);
                    uint32_t ll0 = pack_h2(x0 - bk0.x, y0 - bk0.y);
                    *(uint32_t*)(Kho + (size_t)row0 * DMODEL + cloc) = hh0;
                    *(uint32_t*)(Klo + (size_t)row0 * DMODEL + cloc) = ll0;
                    uint32_t hh1 = pack_h2(x1, y1);
                    float2 bk1 = unpack_h2(hh1);
                    uint32_t ll1 = pack_h2(x1 - bk1.x, y1 - bk1.y);
                    *(uint32_t*)(Kho + (size_t)(row0 + 8) * DMODEL + cloc) = hh1;
                    *(uint32_t*)(Klo + (size_t)(row0 + 8) * DMODEL + cloc) = ll1;
                } else {
                    *(uint32_t*)(Vho + (size_t)row0 * DMODEL + cloc) = pack_h2(x0, y0);
                    *(uint32_t*)(Vho + (size_t)(row0 + 8) * DMODEL + cloc) = pack_h2(x1, y1);
                }
            }
        }
    }
}

// ===========================================================================
// Tensor-core flash attention (unchanged from R8 except fp16 output).
// smem: Q 16K | stage0 48K (KH,KL,VH) | stage1 48K | rmax 1K | lred 1K
// ===========================================================================
#define ATT_Q    0
#define ATT_ST   16384
#define ATT_STG  49152
#define ST_KH    0
#define ST_KL    16384
#define ST_VH    32768
#define ATT_RMAX (ATT_ST + 2 * ATT_STG)     // 114688
#define ATT_LRED (ATT_RMAX + 1024)
#define ATT_SMEM (ATT_LRED + 1024)          // 116736

__global__ __launch_bounds__(256, 1) void attn_mma(
    const __half* __restrict__ Qg,
    const __half* __restrict__ Kh, const __half* __restrict__ Kl,
    const __half* __restrict__ Vh,
    __half* __restrict__ Oh)
{
    extern __shared__ char sma[];
    const uint32_t smb = smem_u32(sma);
    float* redmax = (float*)(sma + ATT_RMAX);
    float* lred   = (float*)(sma + ATT_LRED);

    const int bid = blockIdx.x;
    const int qt  = 15 - (bid >> 5);          // heavy q-tiles first
    const int bh  = bid & 31;
    const int b   = bh >> 4;
    const int h   = bh & 15;

    const int tid  = threadIdx.x;
    const int wid  = tid >> 5;
    const int lane = tid & 31;
    const int wm   = wid & 3;
    const int wn   = wid >> 2;
    const int mat  = lane >> 3;
    const int l7   = lane & 7;
    const int er   = lane >> 2;
    const int ec   = (lane & 3) * 2;

    const size_t rowbase = (size_t)b * SEQ;

    auto prefetch = [&](int kd2, int st) {
        const uint32_t dst = smb + ATT_ST + st * ATT_STG;
        #pragma unroll
        for (int it = 0; it < 4; it++) {
            const int t = tid + it * 256;
            const int r = t >> 3, g = t & 7;
            const uint32_t cb = (uint32_t)(g * 16);
            const uint32_t sw = (uint32_t)(r * 128) + (cb ^ (((uint32_t)(r & 7)) << 4));
            const size_t go = (rowbase + kd2 * 128 + r) * DMODEL + h * DHEAD + g * 8;
            cp_async16(dst + ST_KH + sw, Kh + go);
            cp_async16(dst + ST_KL + sw, Kl + go);
            cp_async16(dst + ST_VH + sw, Vh + go);
        }
        cp_commit();
    };

    #pragma unroll
    for (int it = 0; it < 4; it++) {
        const int t = tid + it * 256;
        const int r = t >> 3, g = t & 7;
        const uint32_t cb = (uint32_t)(g * 16);
        const uint32_t sw = (uint32_t)(r * 128) + (cb ^ (((uint32_t)(r & 7)) << 4));
        uint4 v = *(const uint4*)(Qg + (rowbase + qt * 128 + r) * DMODEL + h * DHEAD + g * 8);
        *(uint4*)(sma + ATT_Q + sw) = v;
    }
    prefetch(0, 0);
    __syncthreads();

    uint32_t qa[2][4][4];
    #pragma unroll
    for (int mt = 0; mt < 2; mt++) {
        #pragma unroll
        for (int k16 = 0; k16 < 4; k16++) {
            const int r  = wm * 32 + mt * 16 + ((mat & 1) << 3) + l7;
            const uint32_t cb = (uint32_t)((k16 * 16 + ((mat >> 1) << 3)) * 2);
            const uint32_t sw = (uint32_t)(r * 128) + (cb ^ (((uint32_t)(r & 7)) << 4));
            ldsm_x4(qa[mt][k16][0], qa[mt][k16][1], qa[mt][k16][2], qa[mt][k16][3],
                    smb + ATT_Q + sw);
        }
    }

    float mst[2][2], lst[2][2], oa[2][8][4];
    #pragma unroll
    for (int mt = 0; mt < 2; mt++)
        #pragma unroll
        for (int h2 = 0; h2 < 2; h2++) { mst[mt][h2] = -1e30f; lst[mt][h2] = 0.0f; }
    #pragma unroll
    for (int mt = 0; mt < 2; mt++)
        #pragma unroll
        for (int nt = 0; nt < 8; nt++)
            #pragma unroll
            for (int j = 0; j < 4; j++) oa[mt][nt][j] = 0.0f;

    for (int kd = 0; kd <= qt; kd++) {
        const int st = kd & 1;
        cp_wait<0>();
        __syncthreads();
        if (kd < qt) prefetch(kd + 1, st ^ 1);

        const uint32_t stb = smb + ATT_ST + st * ATT_STG;

        float sc[2][8][4];
        #pragma unroll
        for (int mt = 0; mt < 2; mt++)
            #pragma unroll
            for (int nt = 0; nt < 8; nt++)
                #pragma unroll
                for (int j = 0; j < 4; j++) sc[mt][nt][j] = 0.0f;

        #pragma unroll
        for (int k16 = 0; k16 < 4; k16++) {
            uint32_t bf[8][2];
            #pragma unroll
            for (int p = 0; p < 4; p++) {
                const int r = wn * 64 + p * 16 + ((mat >> 1) << 3) + l7;
                const uint32_t cb = (uint32_t)((k16 * 16 + ((mat & 1) << 3)) * 2);
                const uint32_t sw = (uint32_t)(r * 128) + (cb ^ (((uint32_t)(r & 7)) << 4));
                ldsm_x4(bf[2*p][0], bf[2*p][1], bf[2*p+1][0], bf[2*p+1][1],
                        stb + ST_KH + sw);
            }
            #pragma unroll
            for (int mt = 0; mt < 2; mt++)
                #pragma unroll
                for (int nt = 0; nt < 8; nt++)
                    mma_f16(sc[mt][nt][0], sc[mt][nt][1], sc[mt][nt][2], sc[mt][nt][3],
                            qa[mt][k16][0], qa[mt][k16][1], qa[mt][k16][2], qa[mt][k16][3],
                            bf[nt][0], bf[nt][1]);
            #pragma unroll
            for (int p = 0; p < 4; p++) {
                const int r = wn * 64 + p * 16 + ((mat >> 1) << 3) + l7;
                const uint32_t cb = (uint32_t)((k16 * 16 + ((mat & 1) << 3)) * 2);
                const uint32_t sw = (uint32_t)(r * 128) + (cb ^ (((uint32_t)(r & 7)) << 4));
                ldsm_x4(bf[2*p][0], bf[2*p][1], bf[2*p+1][0], bf[2*p+1][1],
                        stb + ST_KL + sw);
            }
            #pragma unroll
            for (int mt = 0; mt < 2; mt++)
                #pragma unroll
                for (int nt = 0; nt < 8; nt++)
                    mma_f16(sc[mt][nt][0], sc[mt][nt][1], sc[mt][nt][2], sc[mt][nt][3],
                            qa[mt][k16][0], qa[mt][k16][1], qa[mt][k16][2], qa[mt][k16][3],
                            bf[nt][0], bf[nt][1]);
        }

        if (kd == qt) {
            #pragma unroll
            for (int mt = 0; mt < 2; mt++)
                #pragma unroll
                for (int nt = 0; nt < 8; nt++)
                    #pragma unroll
                    for (int j = 0; j < 4; j++) {
                        const int row = wm * 32 + mt * 16 + (j >> 1) * 8 + er;
                        const int col = wn * 64 + nt * 8 + ec + (j & 1);
                        if (col > row) sc[mt][nt][j] = -1e30f;
                    }
        }

        #pragma unroll
        for (int mt = 0; mt < 2; mt++)
            #pragma unroll
            for (int h2 = 0; h2 < 2; h2++) {
                float mx = -1e30f;
                #pragma unroll
                for (int nt = 0; nt < 8; nt++) {
                    mx = fmaxf(mx, sc[mt][nt][2*h2]);
                    mx = fmaxf(mx, sc[mt][nt][2*h2+1]);
                }
                mx = fmaxf(mx, __shfl_xor_sync(0xffffffffu, mx, 1));
                mx = fmaxf(mx, __shfl_xor_sync(0xffffffffu, mx, 2));
                if ((lane & 3) == 0)
                    redmax[wn * 128 + wm * 32 + mt * 16 + h2 * 8 + er] = mx;
            }
        __syncthreads();

        float corr[2][2];
        #pragma unroll
        for (int mt = 0; mt < 2; mt++)
            #pragma unroll
            for (int h2 = 0; h2 < 2; h2++) {
                const int row = wm * 32 + mt * 16 + h2 * 8 + er;
                const float g = fmaxf(redmax[row], redmax[128 + row]);
                const float mnew = fmaxf(mst[mt][h2], g);
                corr[mt][h2] = ex2f(mst[mt][h2] - mnew);
                mst[mt][h2] = mnew;
            }

        #pragma unroll
        for (int mt = 0; mt < 2; mt++) {
            float psum[2] = {0.0f, 0.0f};
            #pragma unroll
            for (int nt = 0; nt < 8; nt++)
                #pragma unroll
                for (int j = 0; j < 4; j++) {
                    const int h2 = j >> 1;
                    const float pv = ex2f(sc[mt][nt][j] - mst[mt][h2]);
                    sc[mt][nt][j] = pv;
                    psum[h2] += pv;
                }
            #pragma unroll
            for (int h2 = 0; h2 < 2; h2++) {
                float s = psum[h2];
                s += __shfl_xor_sync(0xffffffffu, s, 1);
                s += __shfl_xor_sync(0xffffffffu, s, 2);
                lst[mt][h2] = lst[mt][h2] * corr[mt][h2] + s;
            }
            #pragma unroll
            for (int nt = 0; nt < 8; nt++)
                #pragma unroll
                for (int j = 0; j < 4; j++)
                    oa[mt][nt][j] *= corr[mt][j >> 1];
        }

        #pragma unroll
        for (int kt2 = 0; kt2 < 4; kt2++) {
            uint32_t ah[2][4], al[2][4];
            #pragma unroll
            for (int mt = 0; mt < 2; mt++) {
                #pragma unroll
                for (int q4 = 0; q4 < 4; q4++) {
                    const int nt = 2 * kt2 + (q4 >> 1);
                    const int j0 = (q4 & 1) * 2;
                    const float p0 = sc[mt][nt][j0], p1 = sc[mt][nt][j0 + 1];
                    const uint32_t hh = pack_h2(p0, p1);
                    const float2 bk = unpack_h2(hh);
                    ah[mt][q4] = hh;
                    al[mt][q4] = pack_h2(p0 - bk.x, p1 - bk.y);
                }
            }
            uint32_t bvh[8][2];
            #pragma unroll
            for (int ntp = 0; ntp < 4; ntp++) {
                const int r = wn * 64 + kt2 * 16 + ((mat & 1) << 3) + l7;
                const uint32_t cb = (uint32_t)((ntp * 16 + ((mat >> 1) << 3)) * 2);
                const uint32_t sw = (uint32_t)(r * 128) + (cb ^ (((uint32_t)(r & 7)) << 4));
                ldsm_x4_t(bvh[2*ntp][0], bvh[2*ntp][1], bvh[2*ntp+1][0], bvh[2*ntp+1][1],
                          stb + ST_VH + sw);
            }
            #pragma unroll
            for (int mt = 0; mt < 2; mt++)
                #pragma unroll
                for (int nt = 0; nt < 8; nt++) {
                    mma_f16(oa[mt][nt][0], oa[mt][nt][1], oa[mt][nt][2], oa[mt][nt][3],
                            ah[mt][0], ah[mt][1], ah[mt][2], ah[mt][3],
                            bvh[nt][0], bvh[nt][1]);
                    mma_f16(oa[mt][nt][0], oa[mt][nt][1], oa[mt][nt][2], oa[mt][nt][3],
                            al[mt][0], al[mt][1], al[mt][2], al[mt][3],
                            bvh[nt][0], bvh[nt][1]);
                }
        }
    }

    // ---- Combine n-warp partials, write fp16 O for the proj GEMM ----
    __syncthreads();
    float* ored = (float*)(sma + ATT_ST);
    if (wn == 1) {
        #pragma unroll
        for (int mt = 0; mt < 2; mt++)
            #pragma unroll
            for (int nt = 0; nt < 8; nt++)
                #pragma unroll
                for (int h2 = 0; h2 < 2; h2++) {
                    const int row = wm * 32 + mt * 16 + h2 * 8 + er;
                    *(float2*)&ored[row * 64 + nt * 8 + ec] =
                        make_float2(oa[mt][nt][2*h2], oa[mt][nt][2*h2+1]);
                }
        #pragma unroll
        for (int mt = 0; mt < 2; mt++)
            #pragma unroll
            for (int h2 = 0; h2 < 2; h2++) {
                const int row = wm * 32 + mt * 16 + h2 * 8 + er;
                lred[row] = lst[mt][h2];
            }
    }
    __syncthreads();
    if (wn == 0) {
        #pragma unroll
        for (int mt = 0; mt < 2; mt++)
            #pragma unroll
            for (int h2 = 0; h2 < 2; h2++) {
                const int row = wm * 32 + mt * 16 + h2 * 8 + er;
                const float inv = 1.0f / (lst[mt][h2] + lred[row]);
                const size_t go = (rowbase + qt * 128 + row) * DMODEL + h * DHEAD;
                #pragma unroll
                for (int nt = 0; nt < 8; nt++) {
                    const float2 o2 = *(const float2*)&ored[row * 64 + nt * 8 + ec];
                    const float wx = (oa[mt][nt][2*h2]     + o2.x) * inv;
                    const float wy = (oa[mt][nt][2*h2 + 1] + o2.y) * inv;
                    *(uint32_t*)(Oh + go + nt * 8 + ec) = pack_h2(wx, wy);
                }
            }
    }
}

// ===========================================================================
// kernel_launch
// ===========================================================================
extern "C" void kernel_launch(void* const* d_in, const int* in_sizes, int n_in,
                              void* d_out, int out_size)
{
    const float* hidden = (const float*)d_in[0];
    const float* Wqkv   = (const float*)d_in[2];
    const float* bqkv   = (const float*)d_in[3];
    const float* Wproj  = (const float*)d_in[4];
    const float* bproj  = (const float*)d_in[5];
    float* out = (float*)d_out;

    __half *Wh, *Wl, *Xh, *Oh, *Q, *Kh, *Kl, *Vh;
    cudaGetSymbolAddress((void**)&Wh, g_Wh);
    cudaGetSymbolAddress((void**)&Wl, g_Wl);
    cudaGetSymbolAddress((void**)&Xh, g_Xh);
    cudaGetSymbolAddress((void**)&Oh, g_Oh);
    cudaGetSymbolAddress((void**)&Q,  g_Q);
    cudaGetSymbolAddress((void**)&Kh, g_Kh);
    cudaGetSymbolAddress((void**)&Kl, g_Kl);
    cudaGetSymbolAddress((void**)&Vh, g_Vh);

    static bool attr_set = false;
    if (!attr_set) {
        cudaFuncSetAttribute(gemm_f16k, cudaFuncAttributeMaxDynamicSharedMemorySize,
                             GEMM_SMEM);
        cudaFuncSetAttribute(attn_mma, cudaFuncAttributeMaxDynamicSharedMemorySize,
                             ATT_SMEM);
        attr_set = true;
    }

    const int act4 = ROWS * DMODEL / 4;

    // ---- QKV projection (epilogue emits attention-native fp16 buffers) ----
    {
        dim3 gw(QKVDIM / 32, DMODEL / 32);
        transpose_split<<<gw, 256>>>(Wqkv, Wh, Wl, DMODEL, QKVDIM);
        conv_rows<<<(act4 + 255) / 256, 256>>>(hidden, Xh, act4);
        dim3 grid(QKVDIM / GBN, ROWS / GBM);   // (24, 32)
        gemm_f16k<<<grid, 256, GEMM_SMEM>>>(Xh, Wh, Wl, bqkv, nullptr,
                                            ROWS, QKVDIM, DMODEL, 1,
                                            Q, Kh, Kl, Vh);
    }

    // ---- Flash causal attention (writes fp16 O for proj) ----
    attn_mma<<<512, 256, ATT_SMEM>>>(Q, Kh, Kl, Vh, Oh);

    // ---- Output projection ----
    {
        dim3 gw(DMODEL / 32, DMODEL / 32);
        transpose_split<<<gw, 256>>>(Wproj, Wh, Wl, DMODEL, DMODEL);
        dim3 grid(DMODEL / GBN, ROWS / GBM);   // (8, 32)
        gemm_f16k<<<grid, 256, GEMM_SMEM>>>(Oh, Wh, Wl, bproj, out,
                                            ROWS, DMODEL, DMODEL, 0,
                                            nullptr, nullptr, nullptr, nullptr);
    }
}

// round 10
// speedup vs baseline: 11.9865x; 1.0779x over previous
#include <cuda_runtime.h>
#include <cuda_bf16.h>
#include <cuda_fp16.h>
#include <cstdint>

// Problem constants (fixed by the dataset)
#define BATCH 2
#define SEQ   2048
#define DMODEL 1024
#define NHEAD 16
#define DHEAD 64
#define QKVDIM (3 * NHEAD * DHEAD)   // 3072
#define ROWS  (BATCH * SEQ)          // 4096

#define QSCALE (0.125f * 1.44269504088896340736f)   // 1/sqrt(64) * log2(e)

// Scratch (allocation-free rule: __device__ globals)
__device__ __half g_Wh[(size_t)QKVDIM * DMODEL];    // weight^T hi (fp16)
__device__ __half g_Wl[(size_t)QKVDIM * DMODEL];    // weight^T lo (fp16)
__device__ __half g_Xh[(size_t)ROWS * DMODEL];      // hidden, fp16
__device__ __half g_Oh[(size_t)ROWS * DMODEL];      // attention out, fp16
__device__ __half g_Q [(size_t)ROWS * DMODEL];      // q, fp16, pre-scaled
__device__ __half g_Kh[(size_t)ROWS * DMODEL];      // k fp16
__device__ __half g_Vh[(size_t)ROWS * DMODEL];      // v fp16

// ===========================================================================
// Helpers
// ===========================================================================
__device__ __forceinline__ uint32_t smem_u32(const void* p) {
    uint32_t a;
    asm("{ .reg .u64 t; cvta.to.shared.u64 t, %1; cvt.u32.u64 %0, t; }"
        : "=r"(a) : "l"(p));
    return a;
}

__device__ __forceinline__ void cp_async16(uint32_t dst, const void* src) {
    asm volatile("cp.async.cg.shared.global [%0], [%1], 16;"
                 :: "r"(dst), "l"(src) : "memory");
}
__device__ __forceinline__ void cp_commit() {
    asm volatile("cp.async.commit_group;" ::: "memory");
}
template <int N>
__device__ __forceinline__ void cp_wait() {
    asm volatile("cp.async.wait_group %0;" :: "n"(N) : "memory");
}

__device__ __forceinline__ void ldsm_x4(uint32_t& r0, uint32_t& r1,
                                        uint32_t& r2, uint32_t& r3,
                                        uint32_t addr) {
    asm volatile("ldmatrix.sync.aligned.m8n8.x4.shared.b16 {%0,%1,%2,%3}, [%4];"
                 : "=r"(r0), "=r"(r1), "=r"(r2), "=r"(r3) : "r"(addr));
}

__device__ __forceinline__ void ldsm_x4_t(uint32_t& r0, uint32_t& r1,
                                          uint32_t& r2, uint32_t& r3,
                                          uint32_t addr) {
    asm volatile("ldmatrix.sync.aligned.m8n8.x4.trans.shared.b16 {%0,%1,%2,%3}, [%4];"
                 : "=r"(r0), "=r"(r1), "=r"(r2), "=r"(r3) : "r"(addr));
}

__device__ __forceinline__ void mma_f16(float& c0, float& c1, float& c2, float& c3,
                                        uint32_t a0, uint32_t a1, uint32_t a2, uint32_t a3,
                                        uint32_t b0, uint32_t b1) {
    asm volatile(
        "mma.sync.aligned.m16n8k16.row.col.f32.f16.f16.f32 "
        "{%0,%1,%2,%3}, {%4,%5,%6,%7}, {%8,%9}, {%0,%1,%2,%3};"
        : "+f"(c0), "+f"(c1), "+f"(c2), "+f"(c3)
        : "r"(a0), "r"(a1), "r"(a2), "r"(a3), "r"(b0), "r"(b1));
}

__device__ __forceinline__ float ex2f(float x) {
    float y;
    asm("ex2.approx.f32 %0, %1;" : "=f"(y) : "f"(x));
    return y;
}

__device__ __forceinline__ uint32_t pack_h2(float lo, float hi) {
    uint32_t d;
    asm("cvt.rn.f16x2.f32 %0, %1, %2;" : "=r"(d) : "f"(hi), "f"(lo));
    return d;
}
__device__ __forceinline__ float2 unpack_h2(uint32_t u) {
    __half2 hh = *reinterpret_cast<__half2*>(&u);
    return __half22float2(hh);
}

// GEMM smem tile: 128 rows x 32 fp16 cols, 64B rows, xor-swizzled 16B segs
__device__ __forceinline__ uint32_t tile_off(int r, int c) {
    return (uint32_t)(r * 64 + (((((c >> 3) & 3) ^ ((r >> 1) & 3))) << 4)
                      + ((c & 7) << 1));
}

// ===========================================================================
// Pre-processing
// ===========================================================================
__global__ __launch_bounds__(256) void transpose_split(
    const float* __restrict__ in, __half* __restrict__ Wh,
    __half* __restrict__ Wl, int K, int N)
{
    __shared__ float t[32][33];
    const int nb = blockIdx.x * 32;
    const int kb = blockIdx.y * 32;
    const int x = threadIdx.x & 31;
    const int y = threadIdx.x >> 5;
    #pragma unroll
    for (int i = 0; i < 32; i += 8)
        t[y + i][x] = in[(size_t)(kb + y + i) * N + nb + x];
    __syncthreads();
    #pragma unroll
    for (int i = 0; i < 32; i += 8) {
        const float v = t[x][y + i];
        const __half hi = __float2half(v);
        const __half lo = __float2half(v - __half2float(hi));
        const size_t o = (size_t)(nb + y + i) * K + kb + x;
        Wh[o] = hi;
        Wl[o] = lo;
    }
}

__global__ __launch_bounds__(256) void conv_rows(
    const float* __restrict__ A, __half* __restrict__ Ah, int total4)
{
    const int i = blockIdx.x * 256 + threadIdx.x;
    if (i < total4) {
        float4 v = ((const float4*)A)[i];
        uint2 h;
        h.x = pack_h2(v.x, v.y);
        h.y = pack_h2(v.z, v.w);
        *(uint2*)(Ah + (size_t)i * 4) = h;
    }
}

// ===========================================================================
// fp16 tensor-core GEMM: C = A[M,K] @ (Bh+Bl)[N,K]^T + bias[N]
// A single fp16, B split hi/lo -> 2 MMA products.
// One barrier per K-chunk (barrier proves prior buffer no longer read).
// mode 0: fp32 C out. mode 1: QKV epilogue (Q fp16*QSCALE, K fp16, V fp16).
// ===========================================================================
#define GBM 128
#define GBN 128
#define GBK 32
#define SB_A  0
#define SB_BH 8192
#define SB_BL 16384
#define SB_BUF 24576
#define GEMM_SMEM (2 * SB_BUF)

__global__ __launch_bounds__(256, 2)
void gemm_f16k(const __half* __restrict__ A,
               const __half* __restrict__ Bh, const __half* __restrict__ Bl,
               const float* __restrict__ bias, float* __restrict__ C,
               int M, int N, int K, int mode,
               __half* __restrict__ Qo,
               __half* __restrict__ Kho, __half* __restrict__ Vho)
{
    extern __shared__ char smg[];
    const uint32_t smb = smem_u32(smg);

    const int tid  = threadIdx.x;
    const int wid  = tid >> 5;
    const int lane = tid & 31;
    const int wm   = wid & 3;
    const int wn   = wid >> 2;
    const int m0 = blockIdx.y * GBM;
    const int n0 = blockIdx.x * GBN;
    const int NCH = K / GBK;

    const int mat = lane >> 3;
    const int l7  = lane & 7;

    auto load_chunk = [&](int c, int b) {
        const int k0 = c * GBK;
        const uint32_t dst = smb + b * SB_BUF;
        #pragma unroll
        for (int t = 0; t < 2; t++) {
            const int j = tid + t * 256;
            const int r = j >> 2, c8 = (j & 3) * 8;
            const uint32_t off = tile_off(r, c8);
            cp_async16(dst + SB_A  + off, A  + (size_t)(m0 + r) * K + k0 + c8);
            cp_async16(dst + SB_BH + off, Bh + (size_t)(n0 + r) * K + k0 + c8);
            cp_async16(dst + SB_BL + off, Bl + (size_t)(n0 + r) * K + k0 + c8);
        }
        cp_commit();
    };

    float acc[2][8][4];
    #pragma unroll
    for (int mt = 0; mt < 2; mt++)
        #pragma unroll
        for (int nt = 0; nt < 8; nt++)
            #pragma unroll
            for (int j = 0; j < 4; j++)
                acc[mt][nt][j] = 0.0f;

    load_chunk(0, 0);

    for (int c = 0; c < NCH; c++) {
        const int b = c & 1;
        cp_wait<0>();
        __syncthreads();                       // buf b ready; buf b^1 free
        if (c + 1 < NCH) load_chunk(c + 1, b ^ 1);

        const uint32_t aB  = smb + b * SB_BUF + SB_A;
        const uint32_t bHi = smb + b * SB_BUF + SB_BH;
        const uint32_t bLo = smb + b * SB_BUF + SB_BL;

        #pragma unroll
        for (int ks = 0; ks < 2; ks++) {
            const int kb = ks * 16;

            uint32_t ah[2][4];
            #pragma unroll
            for (int mt = 0; mt < 2; mt++) {
                const int r  = wm * 32 + mt * 16 + ((mat & 1) << 3) + l7;
                const int kc = kb + ((mat >> 1) << 3);
                const uint32_t off = (uint32_t)(r * 64
                    + (((((kc >> 3) & 3) ^ ((r >> 1) & 3))) << 4));
                ldsm_x4(ah[mt][0], ah[mt][1], ah[mt][2], ah[mt][3], aB + off);
            }

            #pragma unroll
            for (int ph = 0; ph < 2; ph++) {
                uint32_t bh[4][2], bl[4][2];
                #pragma unroll
                for (int p = 0; p < 2; p++) {
                    const int r  = wn * 64 + (ph * 2 + p) * 16 + ((mat >> 1) << 3) + l7;
                    const int kc = kb + ((mat & 1) << 3);
                    const uint32_t off = (uint32_t)(r * 64
                        + (((((kc >> 3) & 3) ^ ((r >> 1) & 3))) << 4));
                    ldsm_x4(bh[2*p][0], bh[2*p][1], bh[2*p+1][0], bh[2*p+1][1], bHi + off);
                    ldsm_x4(bl[2*p][0], bl[2*p][1], bl[2*p+1][0], bl[2*p+1][1], bLo + off);
                }
                #pragma unroll
                for (int mt = 0; mt < 2; mt++)
                    #pragma unroll
                    for (int q = 0; q < 4; q++) {
                        const int nt = ph * 4 + q;
                        mma_f16(acc[mt][nt][0], acc[mt][nt][1], acc[mt][nt][2], acc[mt][nt][3],
                                ah[mt][0], ah[mt][1], ah[mt][2], ah[mt][3],
                                bh[q][0], bh[q][1]);
                        mma_f16(acc[mt][nt][0], acc[mt][nt][1], acc[mt][nt][2], acc[mt][nt][3],
                                ah[mt][0], ah[mt][1], ah[mt][2], ah[mt][3],
                                bl[q][0], bl[q][1]);
                    }
            }
        }
        // no bottom sync: next iteration's top barrier orders buffer reuse
    }

    // Epilogue
    const int er = lane >> 2;
    const int ec = (lane & 3) * 2;
    if (mode == 0) {
        #pragma unroll
        for (int mt = 0; mt < 2; mt++) {
            #pragma unroll
            for (int nt = 0; nt < 8; nt++) {
                const int col = n0 + wn * 64 + nt * 8 + ec;
                const float b0 = bias[col], b1 = bias[col + 1];
                const int row0 = m0 + wm * 32 + mt * 16 + er;
                float2 v0 = make_float2(acc[mt][nt][0] + b0, acc[mt][nt][1] + b1);
                float2 v1 = make_float2(acc[mt][nt][2] + b0, acc[mt][nt][3] + b1);
                *(float2*)(C + (size_t)row0 * N + col)       = v0;
                *(float2*)(C + (size_t)(row0 + 8) * N + col) = v1;
            }
        }
    } else {
        const int sec = n0 >> 10;          // 0=Q, 1=K, 2=V
        __half* Ho = (sec == 1) ? Kho : Vho;
        #pragma unroll
        for (int mt = 0; mt < 2; mt++) {
            #pragma unroll
            for (int nt = 0; nt < 8; nt++) {
                const int col = n0 + wn * 64 + nt * 8 + ec;
                const int cloc = col & 1023;
                const float b0 = bias[col], b1 = bias[col + 1];
                const int row0 = m0 + wm * 32 + mt * 16 + er;
                const float x0 = acc[mt][nt][0] + b0, y0 = acc[mt][nt][1] + b1;
                const float x1 = acc[mt][nt][2] + b0, y1 = acc[mt][nt][3] + b1;
                if (sec == 0) {
                    *(uint32_t*)(Qo + (size_t)row0 * DMODEL + cloc)
                        = pack_h2(x0 * QSCALE, y0 * QSCALE);
                    *(uint32_t*)(Qo + (size_t)(row0 + 8) * DMODEL + cloc)
                        = pack_h2(x1 * QSCALE, y1 * QSCALE);
                } else {
                    *(uint32_t*)(Ho + (size_t)row0 * DMODEL + cloc) = pack_h2(x0, y0);
                    *(uint32_t*)(Ho + (size_t)(row0 + 8) * DMODEL + cloc) = pack_h2(x1, y1);
                }
            }
        }
    }
}

// ===========================================================================
// Tensor-core flash attention.
//  - Q fp16 pre-scaled; K fp16 single; V fp16 single
//  - S = Q . K (1 product); PV = (Ph + Pl) . V (2 products)
// smem: Q 16K | stage0 32K (KH,VH) | stage1 32K | rmax 1K | lred 1K
// ===========================================================================
#define ATT_Q    0
#define ATT_ST   16384
#define ATT_STG  32768
#define ST_KH    0
#define ST_VH    16384
#define ATT_RMAX (ATT_ST + 2 * ATT_STG)     // 81920
#define ATT_LRED (ATT_RMAX + 1024)
#define ATT_SMEM (ATT_LRED + 1024)          // 83968

__global__ __launch_bounds__(256, 1) void attn_mma(
    const __half* __restrict__ Qg,
    const __half* __restrict__ Kh,
    const __half* __restrict__ Vh,
    __half* __restrict__ Oh)
{
    extern __shared__ char sma[];
    const uint32_t smb = smem_u32(sma);
    float* redmax = (float*)(sma + ATT_RMAX);
    float* lred   = (float*)(sma + ATT_LRED);

    const int bid = blockIdx.x;
    const int qt  = 15 - (bid >> 5);          // heavy q-tiles first
    const int bh  = bid & 31;
    const int b   = bh >> 4;
    const int h   = bh & 15;

    const int tid  = threadIdx.x;
    const int wid  = tid >> 5;
    const int lane = tid & 31;
    const int wm   = wid & 3;
    const int wn   = wid >> 2;
    const int mat  = lane >> 3;
    const int l7   = lane & 7;
    const int er   = lane >> 2;
    const int ec   = (lane & 3) * 2;

    const size_t rowbase = (size_t)b * SEQ;

    auto prefetch = [&](int kd2, int st) {
        const uint32_t dst = smb + ATT_ST + st * ATT_STG;
        #pragma unroll
        for (int it = 0; it < 4; it++) {
            const int t = tid + it * 256;
            const int r = t >> 3, g = t & 7;
            const uint32_t cb = (uint32_t)(g * 16);
            const uint32_t sw = (uint32_t)(r * 128) + (cb ^ (((uint32_t)(r & 7)) << 4));
            const size_t go = (rowbase + kd2 * 128 + r) * DMODEL + h * DHEAD + g * 8;
            cp_async16(dst + ST_KH + sw, Kh + go);
            cp_async16(dst + ST_VH + sw, Vh + go);
        }
        cp_commit();
    };

    #pragma unroll
    for (int it = 0; it < 4; it++) {
        const int t = tid + it * 256;
        const int r = t >> 3, g = t & 7;
        const uint32_t cb = (uint32_t)(g * 16);
        const uint32_t sw = (uint32_t)(r * 128) + (cb ^ (((uint32_t)(r & 7)) << 4));
        uint4 v = *(const uint4*)(Qg + (rowbase + qt * 128 + r) * DMODEL + h * DHEAD + g * 8);
        *(uint4*)(sma + ATT_Q + sw) = v;
    }
    prefetch(0, 0);
    __syncthreads();

    uint32_t qa[2][4][4];
    #pragma unroll
    for (int mt = 0; mt < 2; mt++) {
        #pragma unroll
        for (int k16 = 0; k16 < 4; k16++) {
            const int r  = wm * 32 + mt * 16 + ((mat & 1) << 3) + l7;
            const uint32_t cb = (uint32_t)((k16 * 16 + ((mat >> 1) << 3)) * 2);
            const uint32_t sw = (uint32_t)(r * 128) + (cb ^ (((uint32_t)(r & 7)) << 4));
            ldsm_x4(qa[mt][k16][0], qa[mt][k16][1], qa[mt][k16][2], qa[mt][k16][3],
                    smb + ATT_Q + sw);
        }
    }

    float mst[2][2], lst[2][2], oa[2][8][4];
    #pragma unroll
    for (int mt = 0; mt < 2; mt++)
        #pragma unroll
        for (int h2 = 0; h2 < 2; h2++) { mst[mt][h2] = -1e30f; lst[mt][h2] = 0.0f; }
    #pragma unroll
    for (int mt = 0; mt < 2; mt++)
        #pragma unroll
        for (int nt = 0; nt < 8; nt++)
            #pragma unroll
            for (int j = 0; j < 4; j++) oa[mt][nt][j] = 0.0f;

    for (int kd = 0; kd <= qt; kd++) {
        const int st = kd & 1;
        cp_wait<0>();
        __syncthreads();
        if (kd < qt) prefetch(kd + 1, st ^ 1);

        const uint32_t stb = smb + ATT_ST + st * ATT_STG;

        // ---- S = Q @ K^T (single product) ----
        float sc[2][8][4];
        #pragma unroll
        for (int mt = 0; mt < 2; mt++)
            #pragma unroll
            for (int nt = 0; nt < 8; nt++)
                #pragma unroll
                for (int j = 0; j < 4; j++) sc[mt][nt][j] = 0.0f;

        #pragma unroll
        for (int k16 = 0; k16 < 4; k16++) {
            uint32_t bf[8][2];
            #pragma unroll
            for (int p = 0; p < 4; p++) {
                const int r = wn * 64 + p * 16 + ((mat >> 1) << 3) + l7;
                const uint32_t cb = (uint32_t)((k16 * 16 + ((mat & 1) << 3)) * 2);
                const uint32_t sw = (uint32_t)(r * 128) + (cb ^ (((uint32_t)(r & 7)) << 4));
                ldsm_x4(bf[2*p][0], bf[2*p][1], bf[2*p+1][0], bf[2*p+1][1],
                        stb + ST_KH + sw);
            }
            #pragma unroll
            for (int mt = 0; mt < 2; mt++)
                #pragma unroll
                for (int nt = 0; nt < 8; nt++)
                    mma_f16(sc[mt][nt][0], sc[mt][nt][1], sc[mt][nt][2], sc[mt][nt][3],
                            qa[mt][k16][0], qa[mt][k16][1], qa[mt][k16][2], qa[mt][k16][3],
                            bf[nt][0], bf[nt][1]);
        }

        // ---- Causal mask (diagonal tile only) ----
        if (kd == qt) {
            #pragma unroll
            for (int mt = 0; mt < 2; mt++)
                #pragma unroll
                for (int nt = 0; nt < 8; nt++)
                    #pragma unroll
                    for (int j = 0; j < 4; j++) {
                        const int row = wm * 32 + mt * 16 + (j >> 1) * 8 + er;
                        const int col = wn * 64 + nt * 8 + ec + (j & 1);
                        if (col > row) sc[mt][nt][j] = -1e30f;
                    }
        }

        // ---- Row max ----
        #pragma unroll
        for (int mt = 0; mt < 2; mt++)
            #pragma unroll
            for (int h2 = 0; h2 < 2; h2++) {
                float mx = -1e30f;
                #pragma unroll
                for (int nt = 0; nt < 8; nt++) {
                    mx = fmaxf(mx, sc[mt][nt][2*h2]);
                    mx = fmaxf(mx, sc[mt][nt][2*h2+1]);
                }
                mx = fmaxf(mx, __shfl_xor_sync(0xffffffffu, mx, 1));
                mx = fmaxf(mx, __shfl_xor_sync(0xffffffffu, mx, 2));
                if ((lane & 3) == 0)
                    redmax[wn * 128 + wm * 32 + mt * 16 + h2 * 8 + er] = mx;
            }
        __syncthreads();

        float corr[2][2];
        #pragma unroll
        for (int mt = 0; mt < 2; mt++)
            #pragma unroll
            for (int h2 = 0; h2 < 2; h2++) {
                const int row = wm * 32 + mt * 16 + h2 * 8 + er;
                const float g = fmaxf(redmax[row], redmax[128 + row]);
                const float mnew = fmaxf(mst[mt][h2], g);
                corr[mt][h2] = ex2f(mst[mt][h2] - mnew);
                mst[mt][h2] = mnew;
            }

        // ---- exp2 + local l accumulation ----
        #pragma unroll
        for (int mt = 0; mt < 2; mt++) {
            float psum[2] = {0.0f, 0.0f};
            #pragma unroll
            for (int nt = 0; nt < 8; nt++)
                #pragma unroll
                for (int j = 0; j < 4; j++) {
                    const int h2 = j >> 1;
                    const float pv = ex2f(sc[mt][nt][j] - mst[mt][h2]);
                    sc[mt][nt][j] = pv;
                    psum[h2] += pv;
                }
            #pragma unroll
            for (int h2 = 0; h2 < 2; h2++) {
                float s = psum[h2];
                s += __shfl_xor_sync(0xffffffffu, s, 1);
                s += __shfl_xor_sync(0xffffffffu, s, 2);
                lst[mt][h2] = lst[mt][h2] * corr[mt][h2] + s;
            }
            #pragma unroll
            for (int nt = 0; nt < 8; nt++)
                #pragma unroll
                for (int j = 0; j < 4; j++)
                    oa[mt][nt][j] *= corr[mt][j >> 1];
        }

        // ---- PV: (Ph + Pl) @ V (2 products) ----
        #pragma unroll
        for (int kt2 = 0; kt2 < 4; kt2++) {
            uint32_t ah[2][4], al[2][4];
            #pragma unroll
            for (int mt = 0; mt < 2; mt++) {
                #pragma unroll
                for (int q4 = 0; q4 < 4; q4++) {
                    const int nt = 2 * kt2 + (q4 >> 1);
                    const int j0 = (q4 & 1) * 2;
                    const float p0 = sc[mt][nt][j0], p1 = sc[mt][nt][j0 + 1];
                    const uint32_t hh = pack_h2(p0, p1);
                    const float2 bk = unpack_h2(hh);
                    ah[mt][q4] = hh;
                    al[mt][q4] = pack_h2(p0 - bk.x, p1 - bk.y);
                }
            }
            uint32_t bvh[8][2];
            #pragma unroll
            for (int ntp = 0; ntp < 4; ntp++) {
                const int r = wn * 64 + kt2 * 16 + ((mat & 1) << 3) + l7;
                const uint32_t cb = (uint32_t)((ntp * 16 + ((mat >> 1) << 3)) * 2);
                const uint32_t sw = (uint32_t)(r * 128) + (cb ^ (((uint32_t)(r & 7)) << 4));
                ldsm_x4_t(bvh[2*ntp][0], bvh[2*ntp][1], bvh[2*ntp+1][0], bvh[2*ntp+1][1],
                          stb + ST_VH + sw);
            }
            #pragma unroll
            for (int mt = 0; mt < 2; mt++)
                #pragma unroll
                for (int nt = 0; nt < 8; nt++) {
                    mma_f16(oa[mt][nt][0], oa[mt][nt][1], oa[mt][nt][2], oa[mt][nt][3],
                            ah[mt][0], ah[mt][1], ah[mt][2], ah[mt][3],
                            bvh[nt][0], bvh[nt][1]);
                    mma_f16(oa[mt][nt][0], oa[mt][nt][1], oa[mt][nt][2], oa[mt][nt][3],
                            al[mt][0], al[mt][1], al[mt][2], al[mt][3],
                            bvh[nt][0], bvh[nt][1]);
                }
        }
    }

    // ---- Combine n-warp partials, write fp16 O for the proj GEMM ----
    __syncthreads();
    float* ored = (float*)(sma + ATT_ST);
    if (wn == 1) {
        #pragma unroll
        for (int mt = 0; mt < 2; mt++)
            #pragma unroll
            for (int nt = 0; nt < 8; nt++)
                #pragma unroll
                for (int h2 = 0; h2 < 2; h2++) {
                    const int row = wm * 32 + mt * 16 + h2 * 8 + er;
                    *(float2*)&ored[row * 64 + nt * 8 + ec] =
                        make_float2(oa[mt][nt][2*h2], oa[mt][nt][2*h2+1]);
                }
        #pragma unroll
        for (int mt = 0; mt < 2; mt++)
            #pragma unroll
            for (int h2 = 0; h2 < 2; h2++) {
                const int row = wm * 32 + mt * 16 + h2 * 8 + er;
                lred[row] = lst[mt][h2];
            }
    }
    __syncthreads();
    if (wn == 0) {
        #pragma unroll
        for (int mt = 0; mt < 2; mt++)
            #pragma unroll
            for (int h2 = 0; h2 < 2; h2++) {
                const int row = wm * 32 + mt * 16 + h2 * 8 + er;
                const float inv = 1.0f / (lst[mt][h2] + lred[row]);
                const size_t go = (rowbase + qt * 128 + row) * DMODEL + h * DHEAD;
                #pragma unroll
                for (int nt = 0; nt < 8; nt++) {
                    const float2 o2 = *(const float2*)&ored[row * 64 + nt * 8 + ec];
                    const float wx = (oa[mt][nt][2*h2]     + o2.x) * inv;
                    const float wy = (oa[mt][nt][2*h2 + 1] + o2.y) * inv;
                    *(uint32_t*)(Oh + go + nt * 8 + ec) = pack_h2(wx, wy);
                }
            }
    }
}

// ===========================================================================
// kernel_launch
// ===========================================================================
extern "C" void kernel_launch(void* const* d_in, const int* in_sizes, int n_in,
                              void* d_out, int out_size)
{
    const float* hidden = (const float*)d_in[0];
    const float* Wqkv   = (const float*)d_in[2];
    const float* bqkv   = (const float*)d_in[3];
    const float* Wproj  = (const float*)d_in[4];
    const float* bproj  = (const float*)d_in[5];
    float* out = (float*)d_out;

    __half *Wh, *Wl, *Xh, *Oh, *Q, *Kh, *Vh;
    cudaGetSymbolAddress((void**)&Wh, g_Wh);
    cudaGetSymbolAddress((void**)&Wl, g_Wl);
    cudaGetSymbolAddress((void**)&Xh, g_Xh);
    cudaGetSymbolAddress((void**)&Oh, g_Oh);
    cudaGetSymbolAddress((void**)&Q,  g_Q);
    cudaGetSymbolAddress((void**)&Kh, g_Kh);
    cudaGetSymbolAddress((void**)&Vh, g_Vh);

    static bool attr_set = false;
    if (!attr_set) {
        cudaFuncSetAttribute(gemm_f16k, cudaFuncAttributeMaxDynamicSharedMemorySize,
                             GEMM_SMEM);
        cudaFuncSetAttribute(attn_mma, cudaFuncAttributeMaxDynamicSharedMemorySize,
                             ATT_SMEM);
        attr_set = true;
    }

    const int act4 = ROWS * DMODEL / 4;

    // ---- QKV projection (epilogue emits attention-native fp16 buffers) ----
    {
        dim3 gw(QKVDIM / 32, DMODEL / 32);
        transpose_split<<<gw, 256>>>(Wqkv, Wh, Wl, DMODEL, QKVDIM);
        conv_rows<<<(act4 + 255) / 256, 256>>>(hidden, Xh, act4);
        dim3 grid(QKVDIM / GBN, ROWS / GBM);   // (24, 32)
        gemm_f16k<<<grid, 256, GEMM_SMEM>>>(Xh, Wh, Wl, bqkv, nullptr,
                                            ROWS, QKVDIM, DMODEL, 1,
                                            Q, Kh, Vh);
    }

    // ---- Flash causal attention (writes fp16 O for proj) ----
    attn_mma<<<512, 256, ATT_SMEM>>>(Q, Kh, Vh, Oh);

    // ---- Output projection ----
    {
        dim3 gw(DMODEL / 32, DMODEL / 32);
        transpose_split<<<gw, 256>>>(Wproj, Wh, Wl, DMODEL, DMODEL);
        dim3 grid(DMODEL / GBN, ROWS / GBM);   // (8, 32)
        gemm_f16k<<<grid, 256, GEMM_SMEM>>>(Oh, Wh, Wl, bproj, out,
                                            ROWS, DMODEL, DMODEL, 0,
                                            nullptr, nullptr, nullptr);
    }
}

// round 11
// speedup vs baseline: 16.2320x; 1.3542x over previous
#include <cuda_runtime.h>
#include <cuda_bf16.h>
#include <cuda_fp16.h>
#include <cstdint>

// Problem constants (fixed by the dataset)
#define BATCH 2
#define SEQ   2048
#define DMODEL 1024
#define NHEAD 16
#define DHEAD 64
#define QKVDIM (3 * NHEAD * DHEAD)   // 3072
#define ROWS  (BATCH * SEQ)          // 4096

#define QSCALE (0.125f * 1.44269504088896340736f)   // 1/sqrt(64) * log2(e)

// Scratch (allocation-free rule: __device__ globals)
__device__ __half g_Wh[(size_t)QKVDIM * DMODEL];    // weight^T fp16
__device__ __half g_Xh[(size_t)ROWS * DMODEL];      // hidden, fp16
__device__ __half g_Oh[(size_t)ROWS * DMODEL];      // attention out, fp16
__device__ __half g_Q [(size_t)ROWS * DMODEL];      // q, fp16, pre-scaled
__device__ __half g_Kh[(size_t)ROWS * DMODEL];      // k fp16
__device__ __half g_Vh[(size_t)ROWS * DMODEL];      // v fp16

// ===========================================================================
// Helpers
// ===========================================================================
__device__ __forceinline__ uint32_t smem_u32(const void* p) {
    uint32_t a;
    asm("{ .reg .u64 t; cvta.to.shared.u64 t, %1; cvt.u32.u64 %0, t; }"
        : "=r"(a) : "l"(p));
    return a;
}

__device__ __forceinline__ void cp_async16(uint32_t dst, const void* src) {
    asm volatile("cp.async.cg.shared.global [%0], [%1], 16;"
                 :: "r"(dst), "l"(src) : "memory");
}
__device__ __forceinline__ void cp_commit() {
    asm volatile("cp.async.commit_group;" ::: "memory");
}
template <int N>
__device__ __forceinline__ void cp_wait() {
    asm volatile("cp.async.wait_group %0;" :: "n"(N) : "memory");
}

__device__ __forceinline__ void ldsm_x4(uint32_t& r0, uint32_t& r1,
                                        uint32_t& r2, uint32_t& r3,
                                        uint32_t addr) {
    asm volatile("ldmatrix.sync.aligned.m8n8.x4.shared.b16 {%0,%1,%2,%3}, [%4];"
                 : "=r"(r0), "=r"(r1), "=r"(r2), "=r"(r3) : "r"(addr));
}

__device__ __forceinline__ void ldsm_x4_t(uint32_t& r0, uint32_t& r1,
                                          uint32_t& r2, uint32_t& r3,
                                          uint32_t addr) {
    asm volatile("ldmatrix.sync.aligned.m8n8.x4.trans.shared.b16 {%0,%1,%2,%3}, [%4];"
                 : "=r"(r0), "=r"(r1), "=r"(r2), "=r"(r3) : "r"(addr));
}

__device__ __forceinline__ void mma_f16(float& c0, float& c1, float& c2, float& c3,
                                        uint32_t a0, uint32_t a1, uint32_t a2, uint32_t a3,
                                        uint32_t b0, uint32_t b1) {
    asm volatile(
        "mma.sync.aligned.m16n8k16.row.col.f32.f16.f16.f32 "
        "{%0,%1,%2,%3}, {%4,%5,%6,%7}, {%8,%9}, {%0,%1,%2,%3};"
        : "+f"(c0), "+f"(c1), "+f"(c2), "+f"(c3)
        : "r"(a0), "r"(a1), "r"(a2), "r"(a3), "r"(b0), "r"(b1));
}

__device__ __forceinline__ float ex2f(float x) {
    float y;
    asm("ex2.approx.f32 %0, %1;" : "=f"(y) : "f"(x));
    return y;
}

__device__ __forceinline__ uint32_t pack_h2(float lo, float hi) {
    uint32_t d;
    asm("cvt.rn.f16x2.f32 %0, %1, %2;" : "=r"(d) : "f"(hi), "f"(lo));
    return d;
}
__device__ __forceinline__ float2 unpack_h2(uint32_t u) {
    __half2 hh = *reinterpret_cast<__half2*>(&u);
    return __half22float2(hh);
}

// GEMM smem tile: 128 rows x 32 fp16 cols, 64B rows, xor-swizzled 16B segs
__device__ __forceinline__ uint32_t tile_off(int r, int c) {
    return (uint32_t)(r * 64 + (((((c >> 3) & 3) ^ ((r >> 1) & 3))) << 4)
                      + ((c & 7) << 1));
}

// ===========================================================================
// Pre-processing
// ===========================================================================
__global__ __launch_bounds__(256) void transpose_h(
    const float* __restrict__ in, __half* __restrict__ Wh, int K, int N)
{
    __shared__ float t[32][33];
    const int nb = blockIdx.x * 32;
    const int kb = blockIdx.y * 32;
    const int x = threadIdx.x & 31;
    const int y = threadIdx.x >> 5;
    #pragma unroll
    for (int i = 0; i < 32; i += 8)
        t[y + i][x] = in[(size_t)(kb + y + i) * N + nb + x];
    __syncthreads();
    #pragma unroll
    for (int i = 0; i < 32; i += 8)
        Wh[(size_t)(nb + y + i) * K + kb + x] = __float2half(t[x][y + i]);
}

__global__ __launch_bounds__(256) void conv_rows(
    const float* __restrict__ A, __half* __restrict__ Ah, int total4)
{
    const int i = blockIdx.x * 256 + threadIdx.x;
    if (i < total4) {
        float4 v = ((const float4*)A)[i];
        uint2 h;
        h.x = pack_h2(v.x, v.y);
        h.y = pack_h2(v.z, v.w);
        *(uint2*)(Ah + (size_t)i * 4) = h;
    }
}

// ===========================================================================
// fp16 tensor-core GEMM: C = A[M,K] @ B[N,K]^T + bias[N]  (single product)
// CTA tile 128x128, BK=32, 8 warps (4m x 2n), cp.async double buffer,
// one barrier per K-chunk.
// mode 0: fp32 C out. mode 1: QKV epilogue (Q fp16*QSCALE, K fp16, V fp16).
// ===========================================================================
#define GBM 128
#define GBN 128
#define GBK 32
#define SB_A  0
#define SB_B  8192
#define SB_BUF 16384
#define GEMM_SMEM (2 * SB_BUF)

__global__ __launch_bounds__(256, 2)
void gemm_f16k(const __half* __restrict__ A, const __half* __restrict__ B,
               const float* __restrict__ bias, float* __restrict__ C,
               int M, int N, int K, int mode,
               __half* __restrict__ Qo,
               __half* __restrict__ Kho, __half* __restrict__ Vho)
{
    extern __shared__ char smg[];
    const uint32_t smb = smem_u32(smg);

    const int tid  = threadIdx.x;
    const int wid  = tid >> 5;
    const int lane = tid & 31;
    const int wm   = wid & 3;
    const int wn   = wid >> 2;
    const int m0 = blockIdx.y * GBM;
    const int n0 = blockIdx.x * GBN;
    const int NCH = K / GBK;

    const int mat = lane >> 3;
    const int l7  = lane & 7;

    auto load_chunk = [&](int c, int b) {
        const int k0 = c * GBK;
        const uint32_t dst = smb + b * SB_BUF;
        #pragma unroll
        for (int t = 0; t < 2; t++) {
            const int j = tid + t * 256;
            const int r = j >> 2, c8 = (j & 3) * 8;
            const uint32_t off = tile_off(r, c8);
            cp_async16(dst + SB_A + off, A + (size_t)(m0 + r) * K + k0 + c8);
            cp_async16(dst + SB_B + off, B + (size_t)(n0 + r) * K + k0 + c8);
        }
        cp_commit();
    };

    float acc[2][8][4];
    #pragma unroll
    for (int mt = 0; mt < 2; mt++)
        #pragma unroll
        for (int nt = 0; nt < 8; nt++)
            #pragma unroll
            for (int j = 0; j < 4; j++)
                acc[mt][nt][j] = 0.0f;

    load_chunk(0, 0);

    for (int c = 0; c < NCH; c++) {
        const int b = c & 1;
        cp_wait<0>();
        __syncthreads();                       // buf b ready; buf b^1 free
        if (c + 1 < NCH) load_chunk(c + 1, b ^ 1);

        const uint32_t aB = smb + b * SB_BUF + SB_A;
        const uint32_t bB = smb + b * SB_BUF + SB_B;

        #pragma unroll
        for (int ks = 0; ks < 2; ks++) {
            const int kb = ks * 16;

            uint32_t ah[2][4];
            #pragma unroll
            for (int mt = 0; mt < 2; mt++) {
                const int r  = wm * 32 + mt * 16 + ((mat & 1) << 3) + l7;
                const int kc = kb + ((mat >> 1) << 3);
                const uint32_t off = (uint32_t)(r * 64
                    + (((((kc >> 3) & 3) ^ ((r >> 1) & 3))) << 4));
                ldsm_x4(ah[mt][0], ah[mt][1], ah[mt][2], ah[mt][3], aB + off);
            }

            uint32_t bh[8][2];
            #pragma unroll
            for (int p = 0; p < 4; p++) {
                const int r  = wn * 64 + p * 16 + ((mat >> 1) << 3) + l7;
                const int kc = kb + ((mat & 1) << 3);
                const uint32_t off = (uint32_t)(r * 64
                    + (((((kc >> 3) & 3) ^ ((r >> 1) & 3))) << 4));
                ldsm_x4(bh[2*p][0], bh[2*p][1], bh[2*p+1][0], bh[2*p+1][1], bB + off);
            }

            #pragma unroll
            for (int mt = 0; mt < 2; mt++)
                #pragma unroll
                for (int nt = 0; nt < 8; nt++)
                    mma_f16(acc[mt][nt][0], acc[mt][nt][1], acc[mt][nt][2], acc[mt][nt][3],
                            ah[mt][0], ah[mt][1], ah[mt][2], ah[mt][3],
                            bh[nt][0], bh[nt][1]);
        }
        // no bottom sync: next iteration's top barrier orders buffer reuse
    }

    // Epilogue
    const int er = lane >> 2;
    const int ec = (lane & 3) * 2;
    if (mode == 0) {
        #pragma unroll
        for (int mt = 0; mt < 2; mt++) {
            #pragma unroll
            for (int nt = 0; nt < 8; nt++) {
                const int col = n0 + wn * 64 + nt * 8 + ec;
                const float b0 = bias[col], b1 = bias[col + 1];
                const int row0 = m0 + wm * 32 + mt * 16 + er;
                float2 v0 = make_float2(acc[mt][nt][0] + b0, acc[mt][nt][1] + b1);
                float2 v1 = make_float2(acc[mt][nt][2] + b0, acc[mt][nt][3] + b1);
                *(float2*)(C + (size_t)row0 * N + col)       = v0;
                *(float2*)(C + (size_t)(row0 + 8) * N + col) = v1;
            }
        }
    } else {
        const int sec = n0 >> 10;          // 0=Q, 1=K, 2=V
        __half* Ho = (sec == 1) ? Kho : Vho;
        #pragma unroll
        for (int mt = 0; mt < 2; mt++) {
            #pragma unroll
            for (int nt = 0; nt < 8; nt++) {
                const int col = n0 + wn * 64 + nt * 8 + ec;
                const int cloc = col & 1023;
                const float b0 = bias[col], b1 = bias[col + 1];
                const int row0 = m0 + wm * 32 + mt * 16 + er;
                const float x0 = acc[mt][nt][0] + b0, y0 = acc[mt][nt][1] + b1;
                const float x1 = acc[mt][nt][2] + b0, y1 = acc[mt][nt][3] + b1;
                if (sec == 0) {
                    *(uint32_t*)(Qo + (size_t)row0 * DMODEL + cloc)
                        = pack_h2(x0 * QSCALE, y0 * QSCALE);
                    *(uint32_t*)(Qo + (size_t)(row0 + 8) * DMODEL + cloc)
                        = pack_h2(x1 * QSCALE, y1 * QSCALE);
                } else {
                    *(uint32_t*)(Ho + (size_t)row0 * DMODEL + cloc) = pack_h2(x0, y0);
                    *(uint32_t*)(Ho + (size_t)(row0 + 8) * DMODEL + cloc) = pack_h2(x1, y1);
                }
            }
        }
    }
}

// ===========================================================================
// Tensor-core flash attention (unchanged from R10 — 89.6us).
//  - Q fp16 pre-scaled; K fp16 single; V fp16 single
//  - S = Q . K (1 product); PV = (Ph + Pl) . V (2 products)
// smem: Q 16K | stage0 32K (KH,VH) | stage1 32K | rmax 1K | lred 1K
// ===========================================================================
#define ATT_Q    0
#define ATT_ST   16384
#define ATT_STG  32768
#define ST_KH    0
#define ST_VH    16384
#define ATT_RMAX (ATT_ST + 2 * ATT_STG)     // 81920
#define ATT_LRED (ATT_RMAX + 1024)
#define ATT_SMEM (ATT_LRED + 1024)          // 83968

__global__ __launch_bounds__(256, 1) void attn_mma(
    const __half* __restrict__ Qg,
    const __half* __restrict__ Kh,
    const __half* __restrict__ Vh,
    __half* __restrict__ Oh)
{
    extern __shared__ char sma[];
    const uint32_t smb = smem_u32(sma);
    float* redmax = (float*)(sma + ATT_RMAX);
    float* lred   = (float*)(sma + ATT_LRED);

    const int bid = blockIdx.x;
    const int qt  = 15 - (bid >> 5);          // heavy q-tiles first
    const int bh  = bid & 31;
    const int b   = bh >> 4;
    const int h   = bh & 15;

    const int tid  = threadIdx.x;
    const int wid  = tid >> 5;
    const int lane = tid & 31;
    const int wm   = wid & 3;
    const int wn   = wid >> 2;
    const int mat  = lane >> 3;
    const int l7   = lane & 7;
    const int er   = lane >> 2;
    const int ec   = (lane & 3) * 2;

    const size_t rowbase = (size_t)b * SEQ;

    auto prefetch = [&](int kd2, int st) {
        const uint32_t dst = smb + ATT_ST + st * ATT_STG;
        #pragma unroll
        for (int it = 0; it < 4; it++) {
            const int t = tid + it * 256;
            const int r = t >> 3, g = t & 7;
            const uint32_t cb = (uint32_t)(g * 16);
            const uint32_t sw = (uint32_t)(r * 128) + (cb ^ (((uint32_t)(r & 7)) << 4));
            const size_t go = (rowbase + kd2 * 128 + r) * DMODEL + h * DHEAD + g * 8;
            cp_async16(dst + ST_KH + sw, Kh + go);
            cp_async16(dst + ST_VH + sw, Vh + go);
        }
        cp_commit();
    };

    #pragma unroll
    for (int it = 0; it < 4; it++) {
        const int t = tid + it * 256;
        const int r = t >> 3, g = t & 7;
        const uint32_t cb = (uint32_t)(g * 16);
        const uint32_t sw = (uint32_t)(r * 128) + (cb ^ (((uint32_t)(r & 7)) << 4));
        uint4 v = *(const uint4*)(Qg + (rowbase + qt * 128 + r) * DMODEL + h * DHEAD + g * 8);
        *(uint4*)(sma + ATT_Q + sw) = v;
    }
    prefetch(0, 0);
    __syncthreads();

    uint32_t qa[2][4][4];
    #pragma unroll
    for (int mt = 0; mt < 2; mt++) {
        #pragma unroll
        for (int k16 = 0; k16 < 4; k16++) {
            const int r  = wm * 32 + mt * 16 + ((mat & 1) << 3) + l7;
            const uint32_t cb = (uint32_t)((k16 * 16 + ((mat >> 1) << 3)) * 2);
            const uint32_t sw = (uint32_t)(r * 128) + (cb ^ (((uint32_t)(r & 7)) << 4));
            ldsm_x4(qa[mt][k16][0], qa[mt][k16][1], qa[mt][k16][2], qa[mt][k16][3],
                    smb + ATT_Q + sw);
        }
    }

    float mst[2][2], lst[2][2], oa[2][8][4];
    #pragma unroll
    for (int mt = 0; mt < 2; mt++)
        #pragma unroll
        for (int h2 = 0; h2 < 2; h2++) { mst[mt][h2] = -1e30f; lst[mt][h2] = 0.0f; }
    #pragma unroll
    for (int mt = 0; mt < 2; mt++)
        #pragma unroll
        for (int nt = 0; nt < 8; nt++)
            #pragma unroll
            for (int j = 0; j < 4; j++) oa[mt][nt][j] = 0.0f;

    for (int kd = 0; kd <= qt; kd++) {
        const int st = kd & 1;
        cp_wait<0>();
        __syncthreads();
        if (kd < qt) prefetch(kd + 1, st ^ 1);

        const uint32_t stb = smb + ATT_ST + st * ATT_STG;

        // ---- S = Q @ K^T (single product) ----
        float sc[2][8][4];
        #pragma unroll
        for (int mt = 0; mt < 2; mt++)
            #pragma unroll
            for (int nt = 0; nt < 8; nt++)
                #pragma unroll
                for (int j = 0; j < 4; j++) sc[mt][nt][j] = 0.0f;

        #pragma unroll
        for (int k16 = 0; k16 < 4; k16++) {
            uint32_t bf[8][2];
            #pragma unroll
            for (int p = 0; p < 4; p++) {
                const int r = wn * 64 + p * 16 + ((mat >> 1) << 3) + l7;
                const uint32_t cb = (uint32_t)((k16 * 16 + ((mat & 1) << 3)) * 2);
                const uint32_t sw = (uint32_t)(r * 128) + (cb ^ (((uint32_t)(r & 7)) << 4));
                ldsm_x4(bf[2*p][0], bf[2*p][1], bf[2*p+1][0], bf[2*p+1][1],
                        stb + ST_KH + sw);
            }
            #pragma unroll
            for (int mt = 0; mt < 2; mt++)
                #pragma unroll
                for (int nt = 0; nt < 8; nt++)
                    mma_f16(sc[mt][nt][0], sc[mt][nt][1], sc[mt][nt][2], sc[mt][nt][3],
                            qa[mt][k16][0], qa[mt][k16][1], qa[mt][k16][2], qa[mt][k16][3],
                            bf[nt][0], bf[nt][1]);
        }

        // ---- Causal mask (diagonal tile only) ----
        if (kd == qt) {
            #pragma unroll
            for (int mt = 0; mt < 2; mt++)
                #pragma unroll
                for (int nt = 0; nt < 8; nt++)
                    #pragma unroll
                    for (int j = 0; j < 4; j++) {
                        const int row = wm * 32 + mt * 16 + (j >> 1) * 8 + er;
                        const int col = wn * 64 + nt * 8 + ec + (j & 1);
                        if (col > row) sc[mt][nt][j] = -1e30f;
                    }
        }

        // ---- Row max ----
        #pragma unroll
        for (int mt = 0; mt < 2; mt++)
            #pragma unroll
            for (int h2 = 0; h2 < 2; h2++) {
                float mx = -1e30f;
                #pragma unroll
                for (int nt = 0; nt < 8; nt++) {
                    mx = fmaxf(mx, sc[mt][nt][2*h2]);
                    mx = fmaxf(mx, sc[mt][nt][2*h2+1]);
                }
                mx = fmaxf(mx, __shfl_xor_sync(0xffffffffu, mx, 1));
                mx = fmaxf(mx, __shfl_xor_sync(0xffffffffu, mx, 2));
                if ((lane & 3) == 0)
                    redmax[wn * 128 + wm * 32 + mt * 16 + h2 * 8 + er] = mx;
            }
        __syncthreads();

        float corr[2][2];
        #pragma unroll
        for (int mt = 0; mt < 2; mt++)
            #pragma unroll
            for (int h2 = 0; h2 < 2; h2++) {
                const int row = wm * 32 + mt * 16 + h2 * 8 + er;
                const float g = fmaxf(redmax[row], redmax[128 + row]);
                const float mnew = fmaxf(mst[mt][h2], g);
                corr[mt][h2] = ex2f(mst[mt][h2] - mnew);
                mst[mt][h2] = mnew;
            }

        // ---- exp2 + local l accumulation ----
        #pragma unroll
        for (int mt = 0; mt < 2; mt++) {
            float psum[2] = {0.0f, 0.0f};
            #pragma unroll
            for (int nt = 0; nt < 8; nt++)
                #pragma unroll
                for (int j = 0; j < 4; j++) {
                    const int h2 = j >> 1;
                    const float pv = ex2f(sc[mt][nt][j] - mst[mt][h2]);
                    sc[mt][nt][j] = pv;
                    psum[h2] += pv;
                }
            #pragma unroll
            for (int h2 = 0; h2 < 2; h2++) {
                float s = psum[h2];
                s += __shfl_xor_sync(0xffffffffu, s, 1);
                s += __shfl_xor_sync(0xffffffffu, s, 2);
                lst[mt][h2] = lst[mt][h2] * corr[mt][h2] + s;
            }
            #pragma unroll
            for (int nt = 0; nt < 8; nt++)
                #pragma unroll
                for (int j = 0; j < 4; j++)
                    oa[mt][nt][j] *= corr[mt][j >> 1];
        }

        // ---- PV: (Ph + Pl) @ V (2 products) ----
        #pragma unroll
        for (int kt2 = 0; kt2 < 4; kt2++) {
            uint32_t ah[2][4], al[2][4];
            #pragma unroll
            for (int mt = 0; mt < 2; mt++) {
                #pragma unroll
                for (int q4 = 0; q4 < 4; q4++) {
                    const int nt = 2 * kt2 + (q4 >> 1);
                    const int j0 = (q4 & 1) * 2;
                    const float p0 = sc[mt][nt][j0], p1 = sc[mt][nt][j0 + 1];
                    const uint32_t hh = pack_h2(p0, p1);
                    const float2 bk = unpack_h2(hh);
                    ah[mt][q4] = hh;
                    al[mt][q4] = pack_h2(p0 - bk.x, p1 - bk.y);
                }
            }
            uint32_t bvh[8][2];
            #pragma unroll
            for (int ntp = 0; ntp < 4; ntp++) {
                const int r = wn * 64 + kt2 * 16 + ((mat & 1) << 3) + l7;
                const uint32_t cb = (uint32_t)((ntp * 16 + ((mat >> 1) << 3)) * 2);
                const uint32_t sw = (uint32_t)(r * 128) + (cb ^ (((uint32_t)(r & 7)) << 4));
                ldsm_x4_t(bvh[2*ntp][0], bvh[2*ntp][1], bvh[2*ntp+1][0], bvh[2*ntp+1][1],
                          stb + ST_VH + sw);
            }
            #pragma unroll
            for (int mt = 0; mt < 2; mt++)
                #pragma unroll
                for (int nt = 0; nt < 8; nt++) {
                    mma_f16(oa[mt][nt][0], oa[mt][nt][1], oa[mt][nt][2], oa[mt][nt][3],
                            ah[mt][0], ah[mt][1], ah[mt][2], ah[mt][3],
                            bvh[nt][0], bvh[nt][1]);
                    mma_f16(oa[mt][nt][0], oa[mt][nt][1], oa[mt][nt][2], oa[mt][nt][3],
                            al[mt][0], al[mt][1], al[mt][2], al[mt][3],
                            bvh[nt][0], bvh[nt][1]);
                }
        }
    }

    // ---- Combine n-warp partials, write fp16 O for the proj GEMM ----
    __syncthreads();
    float* ored = (float*)(sma + ATT_ST);
    if (wn == 1) {
        #pragma unroll
        for (int mt = 0; mt < 2; mt++)
            #pragma unroll
            for (int nt = 0; nt < 8; nt++)
                #pragma unroll
                for (int h2 = 0; h2 < 2; h2++) {
                    const int row = wm * 32 + mt * 16 + h2 * 8 + er;
                    *(float2*)&ored[row * 64 + nt * 8 + ec] =
                        make_float2(oa[mt][nt][2*h2], oa[mt][nt][2*h2+1]);
                }
        #pragma unroll
        for (int mt = 0; mt < 2; mt++)
            #pragma unroll
            for (int h2 = 0; h2 < 2; h2++) {
                const int row = wm * 32 + mt * 16 + h2 * 8 + er;
                lred[row] = lst[mt][h2];
            }
    }
    __syncthreads();
    if (wn == 0) {
        #pragma unroll
        for (int mt = 0; mt < 2; mt++)
            #pragma unroll
            for (int h2 = 0; h2 < 2; h2++) {
                const int row = wm * 32 + mt * 16 + h2 * 8 + er;
                const float inv = 1.0f / (lst[mt][h2] + lred[row]);
                const size_t go = (rowbase + qt * 128 + row) * DMODEL + h * DHEAD;
                #pragma unroll
                for (int nt = 0; nt < 8; nt++) {
                    const float2 o2 = *(const float2*)&ored[row * 64 + nt * 8 + ec];
                    const float wx = (oa[mt][nt][2*h2]     + o2.x) * inv;
                    const float wy = (oa[mt][nt][2*h2 + 1] + o2.y) * inv;
                    *(uint32_t*)(Oh + go + nt * 8 + ec) = pack_h2(wx, wy);
                }
            }
    }
}

// ===========================================================================
// kernel_launch
// ===========================================================================
extern "C" void kernel_launch(void* const* d_in, const int* in_sizes, int n_in,
                              void* d_out, int out_size)
{
    const float* hidden = (const float*)d_in[0];
    const float* Wqkv   = (const float*)d_in[2];
    const float* bqkv   = (const float*)d_in[3];
    const float* Wproj  = (const float*)d_in[4];
    const float* bproj  = (const float*)d_in[5];
    float* out = (float*)d_out;

    __half *Wh, *Xh, *Oh, *Q, *Kh, *Vh;
    cudaGetSymbolAddress((void**)&Wh, g_Wh);
    cudaGetSymbolAddress((void**)&Xh, g_Xh);
    cudaGetSymbolAddress((void**)&Oh, g_Oh);
    cudaGetSymbolAddress((void**)&Q,  g_Q);
    cudaGetSymbolAddress((void**)&Kh, g_Kh);
    cudaGetSymbolAddress((void**)&Vh, g_Vh);

    static bool attr_set = false;
    if (!attr_set) {
        cudaFuncSetAttribute(gemm_f16k, cudaFuncAttributeMaxDynamicSharedMemorySize,
                             GEMM_SMEM);
        cudaFuncSetAttribute(attn_mma, cudaFuncAttributeMaxDynamicSharedMemorySize,
                             ATT_SMEM);
        attr_set = true;
    }

    const int act4 = ROWS * DMODEL / 4;

    // ---- QKV projection (epilogue emits attention-native fp16 buffers) ----
    {
        dim3 gw(QKVDIM / 32, DMODEL / 32);
        transpose_h<<<gw, 256>>>(Wqkv, Wh, DMODEL, QKVDIM);
        conv_rows<<<(act4 + 255) / 256, 256>>>(hidden, Xh, act4);
        dim3 grid(QKVDIM / GBN, ROWS / GBM);   // (24, 32)
        gemm_f16k<<<grid, 256, GEMM_SMEM>>>(Xh, Wh, bqkv, nullptr,
                                            ROWS, QKVDIM, DMODEL, 1,
                                            Q, Kh, Vh);
    }

    // ---- Flash causal attention (writes fp16 O for proj) ----
    attn_mma<<<512, 256, ATT_SMEM>>>(Q, Kh, Vh, Oh);

    // ---- Output projection ----
    {
        dim3 gw(DMODEL / 32, DMODEL / 32);
        transpose_h<<<gw, 256>>>(Wproj, Wh, DMODEL, DMODEL);
        dim3 grid(DMODEL / GBN, ROWS / GBM);   // (8, 32)
        gemm_f16k<<<grid, 256, GEMM_SMEM>>>(Oh, Wh, bproj, out,
                                            ROWS, DMODEL, DMODEL, 0,
                                            nullptr, nullptr, nullptr);
    }
}

// round 12
// speedup vs baseline: 17.1350x; 1.0556x over previous
#include <cuda_runtime.h>
#include <cuda_bf16.h>
#include <cuda_fp16.h>
#include <cstdint>

// Problem constants (fixed by the dataset)
#define BATCH 2
#define SEQ   2048
#define DMODEL 1024
#define NHEAD 16
#define DHEAD 64
#define QKVDIM (3 * NHEAD * DHEAD)   // 3072
#define ROWS  (BATCH * SEQ)          // 4096

#define QSCALE (0.125f * 1.44269504088896340736f)   // 1/sqrt(64) * log2(e)

// Scratch (allocation-free rule: __device__ globals)
__device__ __half g_Wh[(size_t)QKVDIM * DMODEL];    // weight^T fp16
__device__ __half g_Xh[(size_t)ROWS * DMODEL];      // hidden, fp16
__device__ __half g_Oh[(size_t)ROWS * DMODEL];      // attention out, fp16
__device__ __half g_Q [(size_t)ROWS * DMODEL];      // q, fp16, pre-scaled
__device__ __half g_Kh[(size_t)ROWS * DMODEL];      // k fp16
__device__ __half g_Vh[(size_t)ROWS * DMODEL];      // v fp16

// ===========================================================================
// Helpers
// ===========================================================================
__device__ __forceinline__ uint32_t smem_u32(const void* p) {
    uint32_t a;
    asm("{ .reg .u64 t; cvta.to.shared.u64 t, %1; cvt.u32.u64 %0, t; }"
        : "=r"(a) : "l"(p));
    return a;
}

__device__ __forceinline__ void cp_async16(uint32_t dst, const void* src) {
    asm volatile("cp.async.cg.shared.global [%0], [%1], 16;"
                 :: "r"(dst), "l"(src) : "memory");
}
__device__ __forceinline__ void cp_commit() {
    asm volatile("cp.async.commit_group;" ::: "memory");
}
template <int N>
__device__ __forceinline__ void cp_wait() {
    asm volatile("cp.async.wait_group %0;" :: "n"(N) : "memory");
}

__device__ __forceinline__ void ldsm_x4(uint32_t& r0, uint32_t& r1,
                                        uint32_t& r2, uint32_t& r3,
                                        uint32_t addr) {
    asm volatile("ldmatrix.sync.aligned.m8n8.x4.shared.b16 {%0,%1,%2,%3}, [%4];"
                 : "=r"(r0), "=r"(r1), "=r"(r2), "=r"(r3) : "r"(addr));
}

__device__ __forceinline__ void ldsm_x4_t(uint32_t& r0, uint32_t& r1,
                                          uint32_t& r2, uint32_t& r3,
                                          uint32_t addr) {
    asm volatile("ldmatrix.sync.aligned.m8n8.x4.trans.shared.b16 {%0,%1,%2,%3}, [%4];"
                 : "=r"(r0), "=r"(r1), "=r"(r2), "=r"(r3) : "r"(addr));
}

__device__ __forceinline__ void mma_f16(float& c0, float& c1, float& c2, float& c3,
                                        uint32_t a0, uint32_t a1, uint32_t a2, uint32_t a3,
                                        uint32_t b0, uint32_t b1) {
    asm volatile(
        "mma.sync.aligned.m16n8k16.row.col.f32.f16.f16.f32 "
        "{%0,%1,%2,%3}, {%4,%5,%6,%7}, {%8,%9}, {%0,%1,%2,%3};"
        : "+f"(c0), "+f"(c1), "+f"(c2), "+f"(c3)
        : "r"(a0), "r"(a1), "r"(a2), "r"(a3), "r"(b0), "r"(b1));
}

__device__ __forceinline__ float ex2f(float x) {
    float y;
    asm("ex2.approx.f32 %0, %1;" : "=f"(y) : "f"(x));
    return y;
}

__device__ __forceinline__ uint32_t pack_h2(float lo, float hi) {
    uint32_t d;
    asm("cvt.rn.f16x2.f32 %0, %1, %2;" : "=r"(d) : "f"(hi), "f"(lo));
    return d;
}
__device__ __forceinline__ float2 unpack_h2(uint32_t u) {
    __half2 hh = *reinterpret_cast<__half2*>(&u);
    return __half22float2(hh);
}

// 128B-row swizzled tile offset (row-stride 128B, 16B segs, xor phase r&7)
__device__ __forceinline__ uint32_t t128_off(int r, int c) {
    return (uint32_t)(r * 128 + ((((c >> 3) ^ (r & 7)) & 7) * 16) + ((c & 7) * 2));
}

// ===========================================================================
// Pre-processing
// ===========================================================================
__global__ __launch_bounds__(256) void transpose_h(
    const float* __restrict__ in, __half* __restrict__ Wh, int K, int N)
{
    __shared__ float t[32][33];
    const int nb = blockIdx.x * 32;
    const int kb = blockIdx.y * 32;
    const int x = threadIdx.x & 31;
    const int y = threadIdx.x >> 5;
    #pragma unroll
    for (int i = 0; i < 32; i += 8)
        t[y + i][x] = in[(size_t)(kb + y + i) * N + nb + x];
    __syncthreads();
    #pragma unroll
    for (int i = 0; i < 32; i += 8)
        Wh[(size_t)(nb + y + i) * K + kb + x] = __float2half(t[x][y + i]);
}

__global__ __launch_bounds__(256) void conv_rows(
    const float* __restrict__ A, __half* __restrict__ Ah, int total4)
{
    const int i = blockIdx.x * 256 + threadIdx.x;
    if (i < total4) {
        float4 v = ((const float4*)A)[i];
        uint2 h;
        h.x = pack_h2(v.x, v.y);
        h.y = pack_h2(v.z, v.w);
        *(uint2*)(Ah + (size_t)i * 4) = h;
    }
}

// ===========================================================================
// fp16 tensor-core GEMM: C = A[M,K] @ B[N,K]^T + bias[N]  (single product)
// CTA tile 128x128, BK=64, 8 warps (4m x 2n), cp.async double buffer,
// one barrier per K-chunk.
// mode 0: fp32 C out. mode 1: QKV epilogue (Q fp16*QSCALE, K fp16, V fp16).
// ===========================================================================
#define GBM 128
#define GBN 128
#define GBK 64
#define SB_A  0
#define SB_B  16384
#define SB_BUF 32768
#define GEMM_SMEM (2 * SB_BUF)

__global__ __launch_bounds__(256, 2)
void gemm_f16k(const __half* __restrict__ A, const __half* __restrict__ B,
               const float* __restrict__ bias, float* __restrict__ C,
               int M, int N, int K, int mode,
               __half* __restrict__ Qo,
               __half* __restrict__ Kho, __half* __restrict__ Vho)
{
    extern __shared__ char smg[];
    const uint32_t smb = smem_u32(smg);

    const int tid  = threadIdx.x;
    const int wid  = tid >> 5;
    const int lane = tid & 31;
    const int wm   = wid & 3;
    const int wn   = wid >> 2;
    const int m0 = blockIdx.y * GBM;
    const int n0 = blockIdx.x * GBN;
    const int NCH = K / GBK;

    const int mat = lane >> 3;
    const int l7  = lane & 7;

    auto load_chunk = [&](int c, int b) {
        const int k0 = c * GBK;
        const uint32_t dst = smb + b * SB_BUF;
        #pragma unroll
        for (int t = 0; t < 4; t++) {
            const int j = tid + t * 256;          // 0..1023
            const int r = j >> 3, c8 = (j & 7) * 8;
            const uint32_t off = t128_off(r, c8);
            cp_async16(dst + SB_A + off, A + (size_t)(m0 + r) * K + k0 + c8);
            cp_async16(dst + SB_B + off, B + (size_t)(n0 + r) * K + k0 + c8);
        }
        cp_commit();
    };

    float acc[2][8][4];
    #pragma unroll
    for (int mt = 0; mt < 2; mt++)
        #pragma unroll
        for (int nt = 0; nt < 8; nt++)
            #pragma unroll
            for (int j = 0; j < 4; j++)
                acc[mt][nt][j] = 0.0f;

    load_chunk(0, 0);

    for (int c = 0; c < NCH; c++) {
        const int b = c & 1;
        cp_wait<0>();
        __syncthreads();                       // buf b ready; buf b^1 free
        if (c + 1 < NCH) load_chunk(c + 1, b ^ 1);

        const uint32_t aB = smb + b * SB_BUF + SB_A;
        const uint32_t bB = smb + b * SB_BUF + SB_B;

        #pragma unroll
        for (int ks = 0; ks < 4; ks++) {
            const int kb = ks * 16;

            uint32_t ah[2][4];
            #pragma unroll
            for (int mt = 0; mt < 2; mt++) {
                const int r  = wm * 32 + mt * 16 + ((mat & 1) << 3) + l7;
                const int kc = kb + ((mat >> 1) << 3);
                ldsm_x4(ah[mt][0], ah[mt][1], ah[mt][2], ah[mt][3],
                        aB + t128_off(r, kc));
            }

            uint32_t bh[8][2];
            #pragma unroll
            for (int p = 0; p < 4; p++) {
                const int r  = wn * 64 + p * 16 + ((mat >> 1) << 3) + l7;
                const int kc = kb + ((mat & 1) << 3);
                ldsm_x4(bh[2*p][0], bh[2*p][1], bh[2*p+1][0], bh[2*p+1][1],
                        bB + t128_off(r, kc));
            }

            #pragma unroll
            for (int mt = 0; mt < 2; mt++)
                #pragma unroll
                for (int nt = 0; nt < 8; nt++)
                    mma_f16(acc[mt][nt][0], acc[mt][nt][1], acc[mt][nt][2], acc[mt][nt][3],
                            ah[mt][0], ah[mt][1], ah[mt][2], ah[mt][3],
                            bh[nt][0], bh[nt][1]);
        }
        // no bottom sync: next iteration's top barrier orders buffer reuse
    }

    // Epilogue
    const int er = lane >> 2;
    const int ec = (lane & 3) * 2;
    if (mode == 0) {
        #pragma unroll
        for (int mt = 0; mt < 2; mt++) {
            #pragma unroll
            for (int nt = 0; nt < 8; nt++) {
                const int col = n0 + wn * 64 + nt * 8 + ec;
                const float b0 = bias[col], b1 = bias[col + 1];
                const int row0 = m0 + wm * 32 + mt * 16 + er;
                float2 v0 = make_float2(acc[mt][nt][0] + b0, acc[mt][nt][1] + b1);
                float2 v1 = make_float2(acc[mt][nt][2] + b0, acc[mt][nt][3] + b1);
                *(float2*)(C + (size_t)row0 * N + col)       = v0;
                *(float2*)(C + (size_t)(row0 + 8) * N + col) = v1;
            }
        }
    } else {
        const int sec = n0 >> 10;          // 0=Q, 1=K, 2=V
        __half* Ho = (sec == 1) ? Kho : Vho;
        #pragma unroll
        for (int mt = 0; mt < 2; mt++) {
            #pragma unroll
            for (int nt = 0; nt < 8; nt++) {
                const int col = n0 + wn * 64 + nt * 8 + ec;
                const int cloc = col & 1023;
                const float b0 = bias[col], b1 = bias[col + 1];
                const int row0 = m0 + wm * 32 + mt * 16 + er;
                const float x0 = acc[mt][nt][0] + b0, y0 = acc[mt][nt][1] + b1;
                const float x1 = acc[mt][nt][2] + b0, y1 = acc[mt][nt][3] + b1;
                if (sec == 0) {
                    *(uint32_t*)(Qo + (size_t)row0 * DMODEL + cloc)
                        = pack_h2(x0 * QSCALE, y0 * QSCALE);
                    *(uint32_t*)(Qo + (size_t)(row0 + 8) * DMODEL + cloc)
                        = pack_h2(x1 * QSCALE, y1 * QSCALE);
                } else {
                    *(uint32_t*)(Ho + (size_t)row0 * DMODEL + cloc) = pack_h2(x0, y0);
                    *(uint32_t*)(Ho + (size_t)(row0 + 8) * DMODEL + cloc) = pack_h2(x1, y1);
                }
            }
        }
    }
}

// ===========================================================================
// Tensor-core flash attention, 64-q-row CTAs, 2 CTAs/SM.
//  - 8 warps = 4m (16 q-rows each) x 2n (64-key slices)
//  - S = Q . K (1 product); PV = (Ph + Pl) . V (2 products)
// smem: Q 8K | stage0 32K (K,V) | stage1 32K | rmax 512B | lred 512B
// O-reduction reuses stage0 after the mainloop.
// ===========================================================================
#define ATT_Q    0
#define ATT_ST   8192
#define ATT_STG  32768
#define ST_KH    0
#define ST_VH    16384
#define ATT_RMAX (ATT_ST + 2 * ATT_STG)     // 73728
#define ATT_LRED (ATT_RMAX + 512)
#define ATT_SMEM (ATT_LRED + 512)           // 74752

__global__ __launch_bounds__(256, 2) void attn_mma(
    const __half* __restrict__ Qg,
    const __half* __restrict__ Kh,
    const __half* __restrict__ Vh,
    __half* __restrict__ Oh)
{
    extern __shared__ char sma[];
    const uint32_t smb = smem_u32(sma);
    float* redmax = (float*)(sma + ATT_RMAX);
    float* lred   = (float*)(sma + ATT_LRED);

    const int bid = blockIdx.x;
    const int qt  = 31 - (bid >> 5);          // 64-row q tile, heavy first
    const int bh  = bid & 31;
    const int b   = bh >> 4;
    const int h   = bh & 15;
    const int kdmax = qt >> 1;                // last 128-key tile index

    const int tid  = threadIdx.x;
    const int wid  = tid >> 5;
    const int lane = tid & 31;
    const int wm   = wid & 3;                 // q rows wm*16
    const int wn   = wid >> 2;                // keys wn*64
    const int mat  = lane >> 3;
    const int l7   = lane & 7;
    const int er   = lane >> 2;
    const int ec   = (lane & 3) * 2;

    const size_t rowbase = (size_t)b * SEQ;

    auto prefetch = [&](int kd2, int st) {
        const uint32_t dst = smb + ATT_ST + st * ATT_STG;
        #pragma unroll
        for (int it = 0; it < 4; it++) {
            const int t = tid + it * 256;       // 1024: 128 rows x 8 segs
            const int r = t >> 3, g = t & 7;
            const uint32_t sw = (uint32_t)(r * 128) + (((g ^ (r & 7)) & 7) * 16);
            const size_t go = (rowbase + kd2 * 128 + r) * DMODEL + h * DHEAD + g * 8;
            cp_async16(dst + ST_KH + sw, Kh + go);
            cp_async16(dst + ST_VH + sw, Vh + go);
        }
        cp_commit();
    };

    // ---- Load Q tile (64 rows) ----
    #pragma unroll
    for (int it = 0; it < 2; it++) {
        const int t = tid + it * 256;           // 512: 64 rows x 8 segs
        const int r = t >> 3, g = t & 7;
        const uint32_t sw = (uint32_t)(r * 128) + (((g ^ (r & 7)) & 7) * 16);
        uint4 v = *(const uint4*)(Qg + (rowbase + qt * 64 + r) * DMODEL + h * DHEAD + g * 8);
        *(uint4*)(sma + ATT_Q + sw) = v;
    }
    prefetch(0, 0);
    __syncthreads();

    // ---- Q A-fragments (persistent): 16 q-rows per warp ----
    uint32_t qa[4][4];
    #pragma unroll
    for (int k16 = 0; k16 < 4; k16++) {
        const int r  = wm * 16 + ((mat & 1) << 3) + l7;
        const int kc = k16 * 16 + ((mat >> 1) << 3);
        ldsm_x4(qa[k16][0], qa[k16][1], qa[k16][2], qa[k16][3],
                smb + ATT_Q + t128_off(r, kc));
    }

    float mst[2], lst[2], oa[8][4];
    #pragma unroll
    for (int h2 = 0; h2 < 2; h2++) { mst[h2] = -1e30f; lst[h2] = 0.0f; }
    #pragma unroll
    for (int nt = 0; nt < 8; nt++)
        #pragma unroll
        for (int j = 0; j < 4; j++) oa[nt][j] = 0.0f;

    for (int kd = 0; kd <= kdmax; kd++) {
        const int st = kd & 1;
        cp_wait<0>();
        __syncthreads();
        if (kd < kdmax) prefetch(kd + 1, st ^ 1);

        const uint32_t stb = smb + ATT_ST + st * ATT_STG;

        // ---- S = Q @ K^T (warp: 16q x 64k) ----
        float sc[8][4];
        #pragma unroll
        for (int nt = 0; nt < 8; nt++)
            #pragma unroll
            for (int j = 0; j < 4; j++) sc[nt][j] = 0.0f;

        #pragma unroll
        for (int k16 = 0; k16 < 4; k16++) {
            uint32_t bf[8][2];
            #pragma unroll
            for (int p = 0; p < 4; p++) {
                const int r = wn * 64 + p * 16 + ((mat >> 1) << 3) + l7;
                const int kc = k16 * 16 + ((mat & 1) << 3);
                ldsm_x4(bf[2*p][0], bf[2*p][1], bf[2*p+1][0], bf[2*p+1][1],
                        stb + ST_KH + t128_off(r, kc));
            }
            #pragma unroll
            for (int nt = 0; nt < 8; nt++)
                mma_f16(sc[nt][0], sc[nt][1], sc[nt][2], sc[nt][3],
                        qa[k16][0], qa[k16][1], qa[k16][2], qa[k16][3],
                        bf[nt][0], bf[nt][1]);
        }

        // ---- Causal mask (diagonal tile only) ----
        if (kd == kdmax) {
            #pragma unroll
            for (int nt = 0; nt < 8; nt++)
                #pragma unroll
                for (int j = 0; j < 4; j++) {
                    const int grow = qt * 64 + wm * 16 + (j >> 1) * 8 + er;
                    const int gcol = kd * 128 + wn * 64 + nt * 8 + ec + (j & 1);
                    if (gcol > grow) sc[nt][j] = -1e30f;
                }
        }

        // ---- Row max (cross n-warp via 512B smem) ----
        #pragma unroll
        for (int h2 = 0; h2 < 2; h2++) {
            float mx = -1e30f;
            #pragma unroll
            for (int nt = 0; nt < 8; nt++) {
                mx = fmaxf(mx, sc[nt][2*h2]);
                mx = fmaxf(mx, sc[nt][2*h2+1]);
            }
            mx = fmaxf(mx, __shfl_xor_sync(0xffffffffu, mx, 1));
            mx = fmaxf(mx, __shfl_xor_sync(0xffffffffu, mx, 2));
            if ((lane & 3) == 0)
                redmax[wn * 64 + wm * 16 + h2 * 8 + er] = mx;
        }
        __syncthreads();

        float corr[2];
        #pragma unroll
        for (int h2 = 0; h2 < 2; h2++) {
            const int row = wm * 16 + h2 * 8 + er;
            const float g = fmaxf(redmax[row], redmax[64 + row]);
            const float mnew = fmaxf(mst[h2], g);
            corr[h2] = ex2f(mst[h2] - mnew);
            mst[h2] = mnew;
        }

        // ---- exp2 + local l ----
        {
            float psum[2] = {0.0f, 0.0f};
            #pragma unroll
            for (int nt = 0; nt < 8; nt++)
                #pragma unroll
                for (int j = 0; j < 4; j++) {
                    const int h2 = j >> 1;
                    const float pv = ex2f(sc[nt][j] - mst[h2]);
                    sc[nt][j] = pv;
                    psum[h2] += pv;
                }
            #pragma unroll
            for (int h2 = 0; h2 < 2; h2++) {
                float s = psum[h2];
                s += __shfl_xor_sync(0xffffffffu, s, 1);
                s += __shfl_xor_sync(0xffffffffu, s, 2);
                lst[h2] = lst[h2] * corr[h2] + s;
            }
            #pragma unroll
            for (int nt = 0; nt < 8; nt++)
                #pragma unroll
                for (int j = 0; j < 4; j++)
                    oa[nt][j] *= corr[j >> 1];
        }

        // ---- PV: (Ph + Pl) @ V (warp: 16q x 64k slice, d=64) ----
        #pragma unroll
        for (int kt2 = 0; kt2 < 4; kt2++) {
            uint32_t ah[4], al[4];
            #pragma unroll
            for (int q4 = 0; q4 < 4; q4++) {
                const int nt = 2 * kt2 + (q4 >> 1);
                const int j0 = (q4 & 1) * 2;
                const float p0 = sc[nt][j0], p1 = sc[nt][j0 + 1];
                const uint32_t hh = pack_h2(p0, p1);
                const float2 bk = unpack_h2(hh);
                ah[q4] = hh;
                al[q4] = pack_h2(p0 - bk.x, p1 - bk.y);
            }
            uint32_t bvh[8][2];
            #pragma unroll
            for (int ntp = 0; ntp < 4; ntp++) {
                const int r = wn * 64 + kt2 * 16 + ((mat & 1) << 3) + l7;
                const int kc = ntp * 16 + ((mat >> 1) << 3);
                ldsm_x4_t(bvh[2*ntp][0], bvh[2*ntp][1], bvh[2*ntp+1][0], bvh[2*ntp+1][1],
                          stb + ST_VH + t128_off(r, kc));
            }
            #pragma unroll
            for (int nt = 0; nt < 8; nt++) {
                mma_f16(oa[nt][0], oa[nt][1], oa[nt][2], oa[nt][3],
                        ah[0], ah[1], ah[2], ah[3], bvh[nt][0], bvh[nt][1]);
                mma_f16(oa[nt][0], oa[nt][1], oa[nt][2], oa[nt][3],
                        al[0], al[1], al[2], al[3], bvh[nt][0], bvh[nt][1]);
            }
        }
    }

    // ---- Combine n-warp partials (reuse stage0), write fp16 O ----
    __syncthreads();
    float* ored = (float*)(sma + ATT_ST);     // 64 x 64 floats = 16KB
    if (wn == 1) {
        #pragma unroll
        for (int nt = 0; nt < 8; nt++)
            #pragma unroll
            for (int h2 = 0; h2 < 2; h2++) {
                const int row = wm * 16 + h2 * 8 + er;
                *(float2*)&ored[row * 64 + nt * 8 + ec] =
                    make_float2(oa[nt][2*h2], oa[nt][2*h2+1]);
            }
        #pragma unroll
        for (int h2 = 0; h2 < 2; h2++) {
            const int row = wm * 16 + h2 * 8 + er;
            lred[row] = lst[h2];
        }
    }
    __syncthreads();
    if (wn == 0) {
        #pragma unroll
        for (int h2 = 0; h2 < 2; h2++) {
            const int row = wm * 16 + h2 * 8 + er;
            const float inv = 1.0f / (lst[h2] + lred[row]);
            const size_t go = (rowbase + qt * 64 + row) * DMODEL + h * DHEAD;
            #pragma unroll
            for (int nt = 0; nt < 8; nt++) {
                const float2 o2 = *(const float2*)&ored[row * 64 + nt * 8 + ec];
                const float wx = (oa[nt][2*h2]     + o2.x) * inv;
                const float wy = (oa[nt][2*h2 + 1] + o2.y) * inv;
                *(uint32_t*)(Oh + go + nt * 8 + ec) = pack_h2(wx, wy);
            }
        }
    }
}

// ===========================================================================
// kernel_launch
// ===========================================================================
extern "C" void kernel_launch(void* const* d_in, const int* in_sizes, int n_in,
                              void* d_out, int out_size)
{
    const float* hidden = (const float*)d_in[0];
    const float* Wqkv   = (const float*)d_in[2];
    const float* bqkv   = (const float*)d_in[3];
    const float* Wproj  = (const float*)d_in[4];
    const float* bproj  = (const float*)d_in[5];
    float* out = (float*)d_out;

    __half *Wh, *Xh, *Oh, *Q, *Kh, *Vh;
    cudaGetSymbolAddress((void**)&Wh, g_Wh);
    cudaGetSymbolAddress((void**)&Xh, g_Xh);
    cudaGetSymbolAddress((void**)&Oh, g_Oh);
    cudaGetSymbolAddress((void**)&Q,  g_Q);
    cudaGetSymbolAddress((void**)&Kh, g_Kh);
    cudaGetSymbolAddress((void**)&Vh, g_Vh);

    static bool attr_set = false;
    if (!attr_set) {
        cudaFuncSetAttribute(gemm_f16k, cudaFuncAttributeMaxDynamicSharedMemorySize,
                             GEMM_SMEM);
        cudaFuncSetAttribute(attn_mma, cudaFuncAttributeMaxDynamicSharedMemorySize,
                             ATT_SMEM);
        attr_set = true;
    }

    const int act4 = ROWS * DMODEL / 4;

    // ---- QKV projection (epilogue emits attention-native fp16 buffers) ----
    {
        dim3 gw(QKVDIM / 32, DMODEL / 32);
        transpose_h<<<gw, 256>>>(Wqkv, Wh, DMODEL, QKVDIM);
        conv_rows<<<(act4 + 255) / 256, 256>>>(hidden, Xh, act4);
        dim3 grid(QKVDIM / GBN, ROWS / GBM);   // (24, 32)
        gemm_f16k<<<grid, 256, GEMM_SMEM>>>(Xh, Wh, bqkv, nullptr,
                                            ROWS, QKVDIM, DMODEL, 1,
                                            Q, Kh, Vh);
    }

    // ---- Flash causal attention (64-q-row CTAs, writes fp16 O) ----
    attn_mma<<<1024, 256, ATT_SMEM>>>(Q, Kh, Vh, Oh);

    // ---- Output projection ----
    {
        dim3 gw(DMODEL / 32, DMODEL / 32);
        transpose_h<<<gw, 256>>>(Wproj, Wh, DMODEL, DMODEL);
        dim3 grid(DMODEL / GBN, ROWS / GBM);   // (8, 32)
        gemm_f16k<<<grid, 256, GEMM_SMEM>>>(Oh, Wh, bproj, out,
                                            ROWS, DMODEL, DMODEL, 0,
                                            nullptr, nullptr, nullptr);
    }
}

// round 13
// speedup vs baseline: 18.6082x; 1.0860x over previous
#include <cuda_runtime.h>
#include <cuda_bf16.h>
#include <cuda_fp16.h>
#include <cstdint>

// Problem constants (fixed by the dataset)
#define BATCH 2
#define SEQ   2048
#define DMODEL 1024
#define NHEAD 16
#define DHEAD 64
#define QKVDIM (3 * NHEAD * DHEAD)   // 3072
#define ROWS  (BATCH * SEQ)          // 4096

#define QSCALE (0.125f * 1.44269504088896340736f)   // 1/sqrt(64) * log2(e)

// Scratch (allocation-free rule: __device__ globals)
__device__ __half g_Wh[(size_t)QKVDIM * DMODEL];    // weight^T fp16
__device__ __half g_Xh[(size_t)ROWS * DMODEL];      // hidden, fp16
__device__ __half g_Oh[(size_t)ROWS * DMODEL];      // attention out, fp16
__device__ __half g_Q [(size_t)ROWS * DMODEL];      // q, fp16, pre-scaled
__device__ __half g_Kh[(size_t)ROWS * DMODEL];      // k fp16
__device__ __half g_Vh[(size_t)ROWS * DMODEL];      // v fp16

// ===========================================================================
// Helpers
// ===========================================================================
__device__ __forceinline__ uint32_t smem_u32(const void* p) {
    uint32_t a;
    asm("{ .reg .u64 t; cvta.to.shared.u64 t, %1; cvt.u32.u64 %0, t; }"
        : "=r"(a) : "l"(p));
    return a;
}

__device__ __forceinline__ void cp_async16(uint32_t dst, const void* src) {
    asm volatile("cp.async.cg.shared.global [%0], [%1], 16;"
                 :: "r"(dst), "l"(src) : "memory");
}
__device__ __forceinline__ void cp_commit() {
    asm volatile("cp.async.commit_group;" ::: "memory");
}
template <int N>
__device__ __forceinline__ void cp_wait() {
    asm volatile("cp.async.wait_group %0;" :: "n"(N) : "memory");
}

__device__ __forceinline__ void ldsm_x4(uint32_t& r0, uint32_t& r1,
                                        uint32_t& r2, uint32_t& r3,
                                        uint32_t addr) {
    asm volatile("ldmatrix.sync.aligned.m8n8.x4.shared.b16 {%0,%1,%2,%3}, [%4];"
                 : "=r"(r0), "=r"(r1), "=r"(r2), "=r"(r3) : "r"(addr));
}

__device__ __forceinline__ void ldsm_x4_t(uint32_t& r0, uint32_t& r1,
                                          uint32_t& r2, uint32_t& r3,
                                          uint32_t addr) {
    asm volatile("ldmatrix.sync.aligned.m8n8.x4.trans.shared.b16 {%0,%1,%2,%3}, [%4];"
                 : "=r"(r0), "=r"(r1), "=r"(r2), "=r"(r3) : "r"(addr));
}

__device__ __forceinline__ void mma_f16(float& c0, float& c1, float& c2, float& c3,
                                        uint32_t a0, uint32_t a1, uint32_t a2, uint32_t a3,
                                        uint32_t b0, uint32_t b1) {
    asm volatile(
        "mma.sync.aligned.m16n8k16.row.col.f32.f16.f16.f32 "
        "{%0,%1,%2,%3}, {%4,%5,%6,%7}, {%8,%9}, {%0,%1,%2,%3};"
        : "+f"(c0), "+f"(c1), "+f"(c2), "+f"(c3)
        : "r"(a0), "r"(a1), "r"(a2), "r"(a3), "r"(b0), "r"(b1));
}

__device__ __forceinline__ float ex2f(float x) {
    float y;
    asm("ex2.approx.f32 %0, %1;" : "=f"(y) : "f"(x));
    return y;
}

__device__ __forceinline__ uint32_t pack_h2(float lo, float hi) {
    uint32_t d;
    asm("cvt.rn.f16x2.f32 %0, %1, %2;" : "=r"(d) : "f"(hi), "f"(lo));
    return d;
}
__device__ __forceinline__ float2 unpack_h2(uint32_t u) {
    __half2 hh = *reinterpret_cast<__half2*>(&u);
    return __half22float2(hh);
}

// 128B-row swizzled tile offset (row-stride 128B, 16B segs, xor phase r&7)
__device__ __forceinline__ uint32_t t128_off(int r, int c) {
    return (uint32_t)(r * 128 + ((((c >> 3) ^ (r & 7)) & 7) * 16) + ((c & 7) * 2));
}

// ===========================================================================
// Pre-processing
// ===========================================================================
__global__ __launch_bounds__(256) void transpose_h(
    const float* __restrict__ in, __half* __restrict__ Wh, int K, int N)
{
    __shared__ float t[32][33];
    const int nb = blockIdx.x * 32;
    const int kb = blockIdx.y * 32;
    const int x = threadIdx.x & 31;
    const int y = threadIdx.x >> 5;
    #pragma unroll
    for (int i = 0; i < 32; i += 8)
        t[y + i][x] = in[(size_t)(kb + y + i) * N + nb + x];
    __syncthreads();
    #pragma unroll
    for (int i = 0; i < 32; i += 8)
        Wh[(size_t)(nb + y + i) * K + kb + x] = __float2half(t[x][y + i]);
}

__global__ __launch_bounds__(256) void conv_rows(
    const float* __restrict__ A, __half* __restrict__ Ah, int total4)
{
    const int i = blockIdx.x * 256 + threadIdx.x;
    if (i < total4) {
        float4 v = ((const float4*)A)[i];
        uint2 h;
        h.x = pack_h2(v.x, v.y);
        h.y = pack_h2(v.z, v.w);
        *(uint2*)(Ah + (size_t)i * 4) = h;
    }
}

// ===========================================================================
// fp16 tensor-core GEMM (unchanged from R12): C = A @ B^T + bias
// CTA tile 128x128, BK=64, 8 warps (4m x 2n), cp.async double buffer.
// ===========================================================================
#define GBM 128
#define GBN 128
#define GBK 64
#define SB_A  0
#define SB_B  16384
#define SB_BUF 32768
#define GEMM_SMEM (2 * SB_BUF)

__global__ __launch_bounds__(256, 2)
void gemm_f16k(const __half* __restrict__ A, const __half* __restrict__ B,
               const float* __restrict__ bias, float* __restrict__ C,
               int M, int N, int K, int mode,
               __half* __restrict__ Qo,
               __half* __restrict__ Kho, __half* __restrict__ Vho)
{
    extern __shared__ char smg[];
    const uint32_t smb = smem_u32(smg);

    const int tid  = threadIdx.x;
    const int wid  = tid >> 5;
    const int lane = tid & 31;
    const int wm   = wid & 3;
    const int wn   = wid >> 2;
    const int m0 = blockIdx.y * GBM;
    const int n0 = blockIdx.x * GBN;
    const int NCH = K / GBK;

    const int mat = lane >> 3;
    const int l7  = lane & 7;

    auto load_chunk = [&](int c, int b) {
        const int k0 = c * GBK;
        const uint32_t dst = smb + b * SB_BUF;
        #pragma unroll
        for (int t = 0; t < 4; t++) {
            const int j = tid + t * 256;
            const int r = j >> 3, c8 = (j & 7) * 8;
            const uint32_t off = t128_off(r, c8);
            cp_async16(dst + SB_A + off, A + (size_t)(m0 + r) * K + k0 + c8);
            cp_async16(dst + SB_B + off, B + (size_t)(n0 + r) * K + k0 + c8);
        }
        cp_commit();
    };

    float acc[2][8][4];
    #pragma unroll
    for (int mt = 0; mt < 2; mt++)
        #pragma unroll
        for (int nt = 0; nt < 8; nt++)
            #pragma unroll
            for (int j = 0; j < 4; j++)
                acc[mt][nt][j] = 0.0f;

    load_chunk(0, 0);

    for (int c = 0; c < NCH; c++) {
        const int b = c & 1;
        cp_wait<0>();
        __syncthreads();
        if (c + 1 < NCH) load_chunk(c + 1, b ^ 1);

        const uint32_t aB = smb + b * SB_BUF + SB_A;
        const uint32_t bB = smb + b * SB_BUF + SB_B;

        #pragma unroll
        for (int ks = 0; ks < 4; ks++) {
            const int kb = ks * 16;

            uint32_t ah[2][4];
            #pragma unroll
            for (int mt = 0; mt < 2; mt++) {
                const int r  = wm * 32 + mt * 16 + ((mat & 1) << 3) + l7;
                const int kc = kb + ((mat >> 1) << 3);
                ldsm_x4(ah[mt][0], ah[mt][1], ah[mt][2], ah[mt][3],
                        aB + t128_off(r, kc));
            }

            uint32_t bh[8][2];
            #pragma unroll
            for (int p = 0; p < 4; p++) {
                const int r  = wn * 64 + p * 16 + ((mat >> 1) << 3) + l7;
                const int kc = kb + ((mat & 1) << 3);
                ldsm_x4(bh[2*p][0], bh[2*p][1], bh[2*p+1][0], bh[2*p+1][1],
                        bB + t128_off(r, kc));
            }

            #pragma unroll
            for (int mt = 0; mt < 2; mt++)
                #pragma unroll
                for (int nt = 0; nt < 8; nt++)
                    mma_f16(acc[mt][nt][0], acc[mt][nt][1], acc[mt][nt][2], acc[mt][nt][3],
                            ah[mt][0], ah[mt][1], ah[mt][2], ah[mt][3],
                            bh[nt][0], bh[nt][1]);
        }
    }

    // Epilogue
    const int er = lane >> 2;
    const int ec = (lane & 3) * 2;
    if (mode == 0) {
        #pragma unroll
        for (int mt = 0; mt < 2; mt++) {
            #pragma unroll
            for (int nt = 0; nt < 8; nt++) {
                const int col = n0 + wn * 64 + nt * 8 + ec;
                const float b0 = bias[col], b1 = bias[col + 1];
                const int row0 = m0 + wm * 32 + mt * 16 + er;
                float2 v0 = make_float2(acc[mt][nt][0] + b0, acc[mt][nt][1] + b1);
                float2 v1 = make_float2(acc[mt][nt][2] + b0, acc[mt][nt][3] + b1);
                *(float2*)(C + (size_t)row0 * N + col)       = v0;
                *(float2*)(C + (size_t)(row0 + 8) * N + col) = v1;
            }
        }
    } else {
        const int sec = n0 >> 10;          // 0=Q, 1=K, 2=V
        __half* Ho = (sec == 1) ? Kho : Vho;
        #pragma unroll
        for (int mt = 0; mt < 2; mt++) {
            #pragma unroll
            for (int nt = 0; nt < 8; nt++) {
                const int col = n0 + wn * 64 + nt * 8 + ec;
                const int cloc = col & 1023;
                const float b0 = bias[col], b1 = bias[col + 1];
                const int row0 = m0 + wm * 32 + mt * 16 + er;
                const float x0 = acc[mt][nt][0] + b0, y0 = acc[mt][nt][1] + b1;
                const float x1 = acc[mt][nt][2] + b0, y1 = acc[mt][nt][3] + b1;
                if (sec == 0) {
                    *(uint32_t*)(Qo + (size_t)row0 * DMODEL + cloc)
                        = pack_h2(x0 * QSCALE, y0 * QSCALE);
                    *(uint32_t*)(Qo + (size_t)(row0 + 8) * DMODEL + cloc)
                        = pack_h2(x1 * QSCALE, y1 * QSCALE);
                } else {
                    *(uint32_t*)(Ho + (size_t)row0 * DMODEL + cloc) = pack_h2(x0, y0);
                    *(uint32_t*)(Ho + (size_t)(row0 + 8) * DMODEL + cloc) = pack_h2(x1, y1);
                }
            }
        }
    }
}

// ===========================================================================
// Tensor-core flash attention, 64-q-row CTAs, 2 CTAs/SM.
//  - S = Q . K (1 product); PV = P . V (1 product, fp16 P)
//  - XOR-hoisted ldsm addressing (addr(k16) = base ^ (k16<<5))
// smem: Q 8K | stage0 32K (K,V) | stage1 32K | rmax 512B | lred 512B
// ===========================================================================
#define ATT_Q    0
#define ATT_ST   8192
#define ATT_STG  32768
#define ST_KH    0
#define ST_VH    16384
#define ATT_RMAX (ATT_ST + 2 * ATT_STG)     // 73728
#define ATT_LRED (ATT_RMAX + 512)
#define ATT_SMEM (ATT_LRED + 512)           // 74752

__global__ __launch_bounds__(256, 2) void attn_mma(
    const __half* __restrict__ Qg,
    const __half* __restrict__ Kh,
    const __half* __restrict__ Vh,
    __half* __restrict__ Oh)
{
    extern __shared__ char sma[];
    const uint32_t smb = smem_u32(sma);
    float* redmax = (float*)(sma + ATT_RMAX);
    float* lred   = (float*)(sma + ATT_LRED);

    const int bid = blockIdx.x;
    const int qt  = 31 - (bid >> 5);          // 64-row q tile, heavy first
    const int bh  = bid & 31;
    const int b   = bh >> 4;
    const int h   = bh & 15;
    const int kdmax = qt >> 1;                // last 128-key tile index

    const int tid  = threadIdx.x;
    const int wid  = tid >> 5;
    const int lane = tid & 31;
    const int wm   = wid & 3;                 // q rows wm*16
    const int wn   = wid >> 2;                // keys wn*64
    const int mat  = lane >> 3;
    const int l7   = lane & 7;
    const int er   = lane >> 2;
    const int ec   = (lane & 3) * 2;

    const size_t rowbase = (size_t)b * SEQ;

    auto prefetch = [&](int kd2, int st) {
        const uint32_t dst = smb + ATT_ST + st * ATT_STG;
        #pragma unroll
        for (int it = 0; it < 4; it++) {
            const int t = tid + it * 256;       // 1024: 128 rows x 8 segs
            const int r = t >> 3, g = t & 7;
            const uint32_t sw = (uint32_t)(r * 128) + (((g ^ (r & 7)) & 7) * 16);
            const size_t go = (rowbase + kd2 * 128 + r) * DMODEL + h * DHEAD + g * 8;
            cp_async16(dst + ST_KH + sw, Kh + go);
            cp_async16(dst + ST_VH + sw, Vh + go);
        }
        cp_commit();
    };

    // ---- Load Q tile (64 rows) ----
    #pragma unroll
    for (int it = 0; it < 2; it++) {
        const int t = tid + it * 256;
        const int r = t >> 3, g = t & 7;
        const uint32_t sw = (uint32_t)(r * 128) + (((g ^ (r & 7)) & 7) * 16);
        uint4 v = *(const uint4*)(Qg + (rowbase + qt * 64 + r) * DMODEL + h * DHEAD + g * 8);
        *(uint4*)(sma + ATT_Q + sw) = v;
    }
    prefetch(0, 0);
    __syncthreads();

    // ---- Q A-fragments (persistent): 16 q-rows per warp ----
    uint32_t qa[4][4];
    #pragma unroll
    for (int k16 = 0; k16 < 4; k16++) {
        const int r  = wm * 16 + ((mat & 1) << 3) + l7;
        const int kc = k16 * 16 + ((mat >> 1) << 3);
        ldsm_x4(qa[k16][0], qa[k16][1], qa[k16][2], qa[k16][3],
                smb + ATT_Q + t128_off(r, kc));
    }

    // ---- Hoisted ldsm base addresses (stage-relative) ----
    // K b-frag base for p=0..3 (row r_p, kc0 = (mat&1)*8); addr(k16) = base ^ (k16<<5)
    uint32_t koff[4];
    #pragma unroll
    for (int p = 0; p < 4; p++) {
        const int r = wn * 64 + p * 16 + ((mat >> 1) << 3) + l7;
        koff[p] = ST_KH + t128_off(r, (mat & 1) << 3);
    }
    // V b-frag base (row r0 in first 16-key group, kc0 = (mat>>1)*8);
    // addr(kt2, ntp) = (base + kt2*2048) ^ (ntp<<5)
    const uint32_t voff0 = ST_VH +
        t128_off(wn * 64 + ((mat & 1) << 3) + l7, (mat >> 1) << 3);

    float mst[2], lst[2], oa[8][4];
    #pragma unroll
    for (int h2 = 0; h2 < 2; h2++) { mst[h2] = -1e30f; lst[h2] = 0.0f; }
    #pragma unroll
    for (int nt = 0; nt < 8; nt++)
        #pragma unroll
        for (int j = 0; j < 4; j++) oa[nt][j] = 0.0f;

    for (int kd = 0; kd <= kdmax; kd++) {
        const int st = kd & 1;
        cp_wait<0>();
        __syncthreads();
        if (kd < kdmax) prefetch(kd + 1, st ^ 1);

        const uint32_t stb = smb + ATT_ST + st * ATT_STG;

        // ---- S = Q @ K^T (warp: 16q x 64k, single product) ----
        float sc[8][4];
        #pragma unroll
        for (int nt = 0; nt < 8; nt++)
            #pragma unroll
            for (int j = 0; j < 4; j++) sc[nt][j] = 0.0f;

        #pragma unroll
        for (int k16 = 0; k16 < 4; k16++) {
            const uint32_t kx = (uint32_t)(k16 << 5);
            uint32_t bf[8][2];
            #pragma unroll
            for (int p = 0; p < 4; p++)
                ldsm_x4(bf[2*p][0], bf[2*p][1], bf[2*p+1][0], bf[2*p+1][1],
                        stb + (koff[p] ^ kx));
            #pragma unroll
            for (int nt = 0; nt < 8; nt++)
                mma_f16(sc[nt][0], sc[nt][1], sc[nt][2], sc[nt][3],
                        qa[k16][0], qa[k16][1], qa[k16][2], qa[k16][3],
                        bf[nt][0], bf[nt][1]);
        }

        // ---- Causal mask (diagonal tile only) ----
        if (kd == kdmax) {
            #pragma unroll
            for (int nt = 0; nt < 8; nt++)
                #pragma unroll
                for (int j = 0; j < 4; j++) {
                    const int grow = qt * 64 + wm * 16 + (j >> 1) * 8 + er;
                    const int gcol = kd * 128 + wn * 64 + nt * 8 + ec + (j & 1);
                    if (gcol > grow) sc[nt][j] = -1e30f;
                }
        }

        // ---- Row max (cross n-warp via 512B smem) ----
        #pragma unroll
        for (int h2 = 0; h2 < 2; h2++) {
            float mx = -1e30f;
            #pragma unroll
            for (int nt = 0; nt < 8; nt++) {
                mx = fmaxf(mx, sc[nt][2*h2]);
                mx = fmaxf(mx, sc[nt][2*h2+1]);
            }
            mx = fmaxf(mx, __shfl_xor_sync(0xffffffffu, mx, 1));
            mx = fmaxf(mx, __shfl_xor_sync(0xffffffffu, mx, 2));
            if ((lane & 3) == 0)
                redmax[wn * 64 + wm * 16 + h2 * 8 + er] = mx;
        }
        __syncthreads();

        float corr[2];
        #pragma unroll
        for (int h2 = 0; h2 < 2; h2++) {
            const int row = wm * 16 + h2 * 8 + er;
            const float g = fmaxf(redmax[row], redmax[64 + row]);
            const float mnew = fmaxf(mst[h2], g);
            corr[h2] = ex2f(mst[h2] - mnew);
            mst[h2] = mnew;
        }

        // ---- exp2 + local l ----
        {
            float psum[2] = {0.0f, 0.0f};
            #pragma unroll
            for (int nt = 0; nt < 8; nt++)
                #pragma unroll
                for (int j = 0; j < 4; j++) {
                    const int h2 = j >> 1;
                    const float pv = ex2f(sc[nt][j] - mst[h2]);
                    sc[nt][j] = pv;
                    psum[h2] += pv;
                }
            #pragma unroll
            for (int h2 = 0; h2 < 2; h2++) {
                float s = psum[h2];
                s += __shfl_xor_sync(0xffffffffu, s, 1);
                s += __shfl_xor_sync(0xffffffffu, s, 2);
                lst[h2] = lst[h2] * corr[h2] + s;
            }
            #pragma unroll
            for (int nt = 0; nt < 8; nt++)
                #pragma unroll
                for (int j = 0; j < 4; j++)
                    oa[nt][j] *= corr[j >> 1];
        }

        // ---- PV: P @ V (single product, fp16 P) ----
        #pragma unroll
        for (int kt2 = 0; kt2 < 4; kt2++) {
            uint32_t ah[4];
            #pragma unroll
            for (int q4 = 0; q4 < 4; q4++) {
                const int nt = 2 * kt2 + (q4 >> 1);
                const int j0 = (q4 & 1) * 2;
                ah[q4] = pack_h2(sc[nt][j0], sc[nt][j0 + 1]);
            }
            const uint32_t vb = stb + voff0 + (uint32_t)(kt2 * 2048);
            uint32_t bvh[8][2];
            #pragma unroll
            for (int ntp = 0; ntp < 4; ntp++)
                ldsm_x4_t(bvh[2*ntp][0], bvh[2*ntp][1], bvh[2*ntp+1][0], bvh[2*ntp+1][1],
                          vb ^ (uint32_t)(ntp << 5));
            #pragma unroll
            for (int nt = 0; nt < 8; nt++)
                mma_f16(oa[nt][0], oa[nt][1], oa[nt][2], oa[nt][3],
                        ah[0], ah[1], ah[2], ah[3], bvh[nt][0], bvh[nt][1]);
        }
    }

    // ---- Combine n-warp partials (reuse stage0), write fp16 O ----
    __syncthreads();
    float* ored = (float*)(sma + ATT_ST);
    if (wn == 1) {
        #pragma unroll
        for (int nt = 0; nt < 8; nt++)
            #pragma unroll
            for (int h2 = 0; h2 < 2; h2++) {
                const int row = wm * 16 + h2 * 8 + er;
                *(float2*)&ored[row * 64 + nt * 8 + ec] =
                    make_float2(oa[nt][2*h2], oa[nt][2*h2+1]);
            }
        #pragma unroll
        for (int h2 = 0; h2 < 2; h2++) {
            const int row = wm * 16 + h2 * 8 + er;
            lred[row] = lst[h2];
        }
    }
    __syncthreads();
    if (wn == 0) {
        #pragma unroll
        for (int h2 = 0; h2 < 2; h2++) {
            const int row = wm * 16 + h2 * 8 + er;
            const float inv = 1.0f / (lst[h2] + lred[row]);
            const size_t go = (rowbase + qt * 64 + row) * DMODEL + h * DHEAD;
            #pragma unroll
            for (int nt = 0; nt < 8; nt++) {
                const float2 o2 = *(const float2*)&ored[row * 64 + nt * 8 + ec];
                const float wx = (oa[nt][2*h2]     + o2.x) * inv;
                const float wy = (oa[nt][2*h2 + 1] + o2.y) * inv;
                *(uint32_t*)(Oh + go + nt * 8 + ec) = pack_h2(wx, wy);
            }
        }
    }
}

// ===========================================================================
// kernel_launch
// ===========================================================================
extern "C" void kernel_launch(void* const* d_in, const int* in_sizes, int n_in,
                              void* d_out, int out_size)
{
    const float* hidden = (const float*)d_in[0];
    const float* Wqkv   = (const float*)d_in[2];
    const float* bqkv   = (const float*)d_in[3];
    const float* Wproj  = (const float*)d_in[4];
    const float* bproj  = (const float*)d_in[5];
    float* out = (float*)d_out;

    __half *Wh, *Xh, *Oh, *Q, *Kh, *Vh;
    cudaGetSymbolAddress((void**)&Wh, g_Wh);
    cudaGetSymbolAddress((void**)&Xh, g_Xh);
    cudaGetSymbolAddress((void**)&Oh, g_Oh);
    cudaGetSymbolAddress((void**)&Q,  g_Q);
    cudaGetSymbolAddress((void**)&Kh, g_Kh);
    cudaGetSymbolAddress((void**)&Vh, g_Vh);

    static bool attr_set = false;
    if (!attr_set) {
        cudaFuncSetAttribute(gemm_f16k, cudaFuncAttributeMaxDynamicSharedMemorySize,
                             GEMM_SMEM);
        cudaFuncSetAttribute(attn_mma, cudaFuncAttributeMaxDynamicSharedMemorySize,
                             ATT_SMEM);
        attr_set = true;
    }

    const int act4 = ROWS * DMODEL / 4;

    // ---- QKV projection (epilogue emits attention-native fp16 buffers) ----
    {
        dim3 gw(QKVDIM / 32, DMODEL / 32);
        transpose_h<<<gw, 256>>>(Wqkv, Wh, DMODEL, QKVDIM);
        conv_rows<<<(act4 + 255) / 256, 256>>>(hidden, Xh, act4);
        dim3 grid(QKVDIM / GBN, ROWS / GBM);   // (24, 32)
        gemm_f16k<<<grid, 256, GEMM_SMEM>>>(Xh, Wh, bqkv, nullptr,
                                            ROWS, QKVDIM, DMODEL, 1,
                                            Q, Kh, Vh);
    }

    // ---- Flash causal attention (64-q-row CTAs, writes fp16 O) ----
    attn_mma<<<1024, 256, ATT_SMEM>>>(Q, Kh, Vh, Oh);

    // ---- Output projection ----
    {
        dim3 gw(DMODEL / 32, DMODEL / 32);
        transpose_h<<<gw, 256>>>(Wproj, Wh, DMODEL, DMODEL);
        dim3 grid(DMODEL / GBN, ROWS / GBM);   // (8, 32)
        gemm_f16k<<<grid, 256, GEMM_SMEM>>>(Oh, Wh, bproj, out,
                                            ROWS, DMODEL, DMODEL, 0,
                                            nullptr, nullptr, nullptr);
    }
}

// round 14
// speedup vs baseline: 19.2457x; 1.0343x over previous
#include <cuda_runtime.h>
#include <cuda_bf16.h>
#include <cuda_fp16.h>
#include <cstdint>

// Problem constants (fixed by the dataset)
#define BATCH 2
#define SEQ   2048
#define DMODEL 1024
#define NHEAD 16
#define DHEAD 64
#define QKVDIM (3 * NHEAD * DHEAD)   // 3072
#define ROWS  (BATCH * SEQ)          // 4096

#define QSCALE (0.125f * 1.44269504088896340736f)   // 1/sqrt(64) * log2(e)

// Scratch (allocation-free rule: __device__ globals)
__device__ __half g_Wh[(size_t)QKVDIM * DMODEL];    // weight^T fp16
__device__ __half g_Xh[(size_t)ROWS * DMODEL];      // hidden, fp16
__device__ __half g_Oh[(size_t)ROWS * DMODEL];      // attention out, fp16
__device__ __half g_Q [(size_t)ROWS * DMODEL];      // q, fp16, pre-scaled
__device__ __half g_Kh[(size_t)ROWS * DMODEL];      // k fp16
__device__ __half g_Vh[(size_t)ROWS * DMODEL];      // v fp16

// ===========================================================================
// Helpers
// ===========================================================================
__device__ __forceinline__ uint32_t smem_u32(const void* p) {
    uint32_t a;
    asm("{ .reg .u64 t; cvta.to.shared.u64 t, %1; cvt.u32.u64 %0, t; }"
        : "=r"(a) : "l"(p));
    return a;
}

__device__ __forceinline__ void cp_async16(uint32_t dst, const void* src) {
    asm volatile("cp.async.cg.shared.global [%0], [%1], 16;"
                 :: "r"(dst), "l"(src) : "memory");
}
__device__ __forceinline__ void cp_commit() {
    asm volatile("cp.async.commit_group;" ::: "memory");
}
template <int N>
__device__ __forceinline__ void cp_wait() {
    asm volatile("cp.async.wait_group %0;" :: "n"(N) : "memory");
}

__device__ __forceinline__ void ldsm_x4(uint32_t& r0, uint32_t& r1,
                                        uint32_t& r2, uint32_t& r3,
                                        uint32_t addr) {
    asm volatile("ldmatrix.sync.aligned.m8n8.x4.shared.b16 {%0,%1,%2,%3}, [%4];"
                 : "=r"(r0), "=r"(r1), "=r"(r2), "=r"(r3) : "r"(addr));
}

__device__ __forceinline__ void ldsm_x4_t(uint32_t& r0, uint32_t& r1,
                                          uint32_t& r2, uint32_t& r3,
                                          uint32_t addr) {
    asm volatile("ldmatrix.sync.aligned.m8n8.x4.trans.shared.b16 {%0,%1,%2,%3}, [%4];"
                 : "=r"(r0), "=r"(r1), "=r"(r2), "=r"(r3) : "r"(addr));
}

__device__ __forceinline__ void mma_f16(float& c0, float& c1, float& c2, float& c3,
                                        uint32_t a0, uint32_t a1, uint32_t a2, uint32_t a3,
                                        uint32_t b0, uint32_t b1) {
    asm volatile(
        "mma.sync.aligned.m16n8k16.row.col.f32.f16.f16.f32 "
        "{%0,%1,%2,%3}, {%4,%5,%6,%7}, {%8,%9}, {%0,%1,%2,%3};"
        : "+f"(c0), "+f"(c1), "+f"(c2), "+f"(c3)
        : "r"(a0), "r"(a1), "r"(a2), "r"(a3), "r"(b0), "r"(b1));
}

__device__ __forceinline__ float ex2f(float x) {
    float y;
    asm("ex2.approx.f32 %0, %1;" : "=f"(y) : "f"(x));
    return y;
}

__device__ __forceinline__ uint32_t pack_h2(float lo, float hi) {
    uint32_t d;
    asm("cvt.rn.f16x2.f32 %0, %1, %2;" : "=r"(d) : "f"(hi), "f"(lo));
    return d;
}
__device__ __forceinline__ float2 unpack_h2(uint32_t u) {
    __half2 hh = *reinterpret_cast<__half2*>(&u);
    return __half22float2(hh);
}

// 128B-row swizzled tile offset (row-stride 128B, 16B segs, xor phase r&7)
__device__ __forceinline__ uint32_t t128_off(int r, int c) {
    return (uint32_t)(r * 128 + ((((c >> 3) ^ (r & 7)) & 7) * 16) + ((c & 7) * 2));
}

// ===========================================================================
// Pre-processing
// ===========================================================================
__global__ __launch_bounds__(256) void transpose_h(
    const float* __restrict__ in, __half* __restrict__ Wh, int K, int N)
{
    __shared__ float t[32][33];
    const int nb = blockIdx.x * 32;
    const int kb = blockIdx.y * 32;
    const int x = threadIdx.x & 31;
    const int y = threadIdx.x >> 5;
    #pragma unroll
    for (int i = 0; i < 32; i += 8)
        t[y + i][x] = in[(size_t)(kb + y + i) * N + nb + x];
    __syncthreads();
    #pragma unroll
    for (int i = 0; i < 32; i += 8)
        Wh[(size_t)(nb + y + i) * K + kb + x] = __float2half(t[x][y + i]);
}

__global__ __launch_bounds__(256) void conv_rows(
    const float* __restrict__ A, __half* __restrict__ Ah, int total4)
{
    const int i = blockIdx.x * 256 + threadIdx.x;
    if (i < total4) {
        float4 v = ((const float4*)A)[i];
        uint2 h;
        h.x = pack_h2(v.x, v.y);
        h.y = pack_h2(v.z, v.w);
        *(uint2*)(Ah + (size_t)i * 4) = h;
    }
}

// ===========================================================================
// fp16 tensor-core GEMM (unchanged from R13): C = A @ B^T + bias
// CTA tile 128x128, BK=64, 8 warps (4m x 2n), cp.async double buffer.
// ===========================================================================
#define GBM 128
#define GBN 128
#define GBK 64
#define SB_A  0
#define SB_B  16384
#define SB_BUF 32768
#define GEMM_SMEM (2 * SB_BUF)

__global__ __launch_bounds__(256, 2)
void gemm_f16k(const __half* __restrict__ A, const __half* __restrict__ B,
               const float* __restrict__ bias, float* __restrict__ C,
               int M, int N, int K, int mode,
               __half* __restrict__ Qo,
               __half* __restrict__ Kho, __half* __restrict__ Vho)
{
    extern __shared__ char smg[];
    const uint32_t smb = smem_u32(smg);

    const int tid  = threadIdx.x;
    const int wid  = tid >> 5;
    const int lane = tid & 31;
    const int wm   = wid & 3;
    const int wn   = wid >> 2;
    const int m0 = blockIdx.y * GBM;
    const int n0 = blockIdx.x * GBN;
    const int NCH = K / GBK;

    const int mat = lane >> 3;
    const int l7  = lane & 7;

    auto load_chunk = [&](int c, int b) {
        const int k0 = c * GBK;
        const uint32_t dst = smb + b * SB_BUF;
        #pragma unroll
        for (int t = 0; t < 4; t++) {
            const int j = tid + t * 256;
            const int r = j >> 3, c8 = (j & 7) * 8;
            const uint32_t off = t128_off(r, c8);
            cp_async16(dst + SB_A + off, A + (size_t)(m0 + r) * K + k0 + c8);
            cp_async16(dst + SB_B + off, B + (size_t)(n0 + r) * K + k0 + c8);
        }
        cp_commit();
    };

    float acc[2][8][4];
    #pragma unroll
    for (int mt = 0; mt < 2; mt++)
        #pragma unroll
        for (int nt = 0; nt < 8; nt++)
            #pragma unroll
            for (int j = 0; j < 4; j++)
                acc[mt][nt][j] = 0.0f;

    load_chunk(0, 0);

    for (int c = 0; c < NCH; c++) {
        const int b = c & 1;
        cp_wait<0>();
        __syncthreads();
        if (c + 1 < NCH) load_chunk(c + 1, b ^ 1);

        const uint32_t aB = smb + b * SB_BUF + SB_A;
        const uint32_t bB = smb + b * SB_BUF + SB_B;

        #pragma unroll
        for (int ks = 0; ks < 4; ks++) {
            const int kb = ks * 16;

            uint32_t ah[2][4];
            #pragma unroll
            for (int mt = 0; mt < 2; mt++) {
                const int r  = wm * 32 + mt * 16 + ((mat & 1) << 3) + l7;
                const int kc = kb + ((mat >> 1) << 3);
                ldsm_x4(ah[mt][0], ah[mt][1], ah[mt][2], ah[mt][3],
                        aB + t128_off(r, kc));
            }

            uint32_t bh[8][2];
            #pragma unroll
            for (int p = 0; p < 4; p++) {
                const int r  = wn * 64 + p * 16 + ((mat >> 1) << 3) + l7;
                const int kc = kb + ((mat & 1) << 3);
                ldsm_x4(bh[2*p][0], bh[2*p][1], bh[2*p+1][0], bh[2*p+1][1],
                        bB + t128_off(r, kc));
            }

            #pragma unroll
            for (int mt = 0; mt < 2; mt++)
                #pragma unroll
                for (int nt = 0; nt < 8; nt++)
                    mma_f16(acc[mt][nt][0], acc[mt][nt][1], acc[mt][nt][2], acc[mt][nt][3],
                            ah[mt][0], ah[mt][1], ah[mt][2], ah[mt][3],
                            bh[nt][0], bh[nt][1]);
        }
    }

    // Epilogue
    const int er = lane >> 2;
    const int ec = (lane & 3) * 2;
    if (mode == 0) {
        #pragma unroll
        for (int mt = 0; mt < 2; mt++) {
            #pragma unroll
            for (int nt = 0; nt < 8; nt++) {
                const int col = n0 + wn * 64 + nt * 8 + ec;
                const float b0 = bias[col], b1 = bias[col + 1];
                const int row0 = m0 + wm * 32 + mt * 16 + er;
                float2 v0 = make_float2(acc[mt][nt][0] + b0, acc[mt][nt][1] + b1);
                float2 v1 = make_float2(acc[mt][nt][2] + b0, acc[mt][nt][3] + b1);
                *(float2*)(C + (size_t)row0 * N + col)       = v0;
                *(float2*)(C + (size_t)(row0 + 8) * N + col) = v1;
            }
        }
    } else {
        const int sec = n0 >> 10;          // 0=Q, 1=K, 2=V
        __half* Ho = (sec == 1) ? Kho : Vho;
        #pragma unroll
        for (int mt = 0; mt < 2; mt++) {
            #pragma unroll
            for (int nt = 0; nt < 8; nt++) {
                const int col = n0 + wn * 64 + nt * 8 + ec;
                const int cloc = col & 1023;
                const float b0 = bias[col], b1 = bias[col + 1];
                const int row0 = m0 + wm * 32 + mt * 16 + er;
                const float x0 = acc[mt][nt][0] + b0, y0 = acc[mt][nt][1] + b1;
                const float x1 = acc[mt][nt][2] + b0, y1 = acc[mt][nt][3] + b1;
                if (sec == 0) {
                    *(uint32_t*)(Qo + (size_t)row0 * DMODEL + cloc)
                        = pack_h2(x0 * QSCALE, y0 * QSCALE);
                    *(uint32_t*)(Qo + (size_t)(row0 + 8) * DMODEL + cloc)
                        = pack_h2(x1 * QSCALE, y1 * QSCALE);
                } else {
                    *(uint32_t*)(Ho + (size_t)row0 * DMODEL + cloc) = pack_h2(x0, y0);
                    *(uint32_t*)(Ho + (size_t)(row0 + 8) * DMODEL + cloc) = pack_h2(x1, y1);
                }
            }
        }
    }
}

// ===========================================================================
// Tensor-core flash attention, 64-q-row CTAs, 2 CTAs/SM, SPLIT SOFTMAX:
// each n-warp keeps a LOCAL running max/sum over its 64-key half; the two
// halves merge once in the epilogue with 2^(m_i - m) scales. One barrier
// per tile (stage-ready). Fully-masked halves self-cancel (scale -> 0).
// smem: Q 8K | stage0 32K (K,V) | stage1 32K | lred 256B | mred 256B
// ===========================================================================
#define ATT_Q    0
#define ATT_ST   8192
#define ATT_STG  32768
#define ST_KH    0
#define ST_VH    16384
#define ATT_LRED (ATT_ST + 2 * ATT_STG)     // 73728
#define ATT_MRED (ATT_LRED + 256)
#define ATT_SMEM (ATT_MRED + 256)           // 74240

__global__ __launch_bounds__(256, 2) void attn_mma(
    const __half* __restrict__ Qg,
    const __half* __restrict__ Kh,
    const __half* __restrict__ Vh,
    __half* __restrict__ Oh)
{
    extern __shared__ char sma[];
    const uint32_t smb = smem_u32(sma);
    float* lred = (float*)(sma + ATT_LRED);
    float* mred = (float*)(sma + ATT_MRED);

    const int bid = blockIdx.x;
    const int qt  = 31 - (bid >> 5);          // 64-row q tile, heavy first
    const int bh  = bid & 31;
    const int b   = bh >> 4;
    const int h   = bh & 15;
    const int kdmax = qt >> 1;                // last 128-key tile index

    const int tid  = threadIdx.x;
    const int wid  = tid >> 5;
    const int lane = tid & 31;
    const int wm   = wid & 3;                 // q rows wm*16
    const int wn   = wid >> 2;                // keys wn*64
    const int mat  = lane >> 3;
    const int l7   = lane & 7;
    const int er   = lane >> 2;
    const int ec   = (lane & 3) * 2;

    const size_t rowbase = (size_t)b * SEQ;

    auto prefetch = [&](int kd2, int st) {
        const uint32_t dst = smb + ATT_ST + st * ATT_STG;
        #pragma unroll
        for (int it = 0; it < 4; it++) {
            const int t = tid + it * 256;       // 1024: 128 rows x 8 segs
            const int r = t >> 3, g = t & 7;
            const uint32_t sw = (uint32_t)(r * 128) + (((g ^ (r & 7)) & 7) * 16);
            const size_t go = (rowbase + kd2 * 128 + r) * DMODEL + h * DHEAD + g * 8;
            cp_async16(dst + ST_KH + sw, Kh + go);
            cp_async16(dst + ST_VH + sw, Vh + go);
        }
        cp_commit();
    };

    // ---- Load Q tile (64 rows) ----
    #pragma unroll
    for (int it = 0; it < 2; it++) {
        const int t = tid + it * 256;
        const int r = t >> 3, g = t & 7;
        const uint32_t sw = (uint32_t)(r * 128) + (((g ^ (r & 7)) & 7) * 16);
        uint4 v = *(const uint4*)(Qg + (rowbase + qt * 64 + r) * DMODEL + h * DHEAD + g * 8);
        *(uint4*)(sma + ATT_Q + sw) = v;
    }
    prefetch(0, 0);
    __syncthreads();

    // ---- Q A-fragments (persistent): 16 q-rows per warp ----
    uint32_t qa[4][4];
    #pragma unroll
    for (int k16 = 0; k16 < 4; k16++) {
        const int r  = wm * 16 + ((mat & 1) << 3) + l7;
        const int kc = k16 * 16 + ((mat >> 1) << 3);
        ldsm_x4(qa[k16][0], qa[k16][1], qa[k16][2], qa[k16][3],
                smb + ATT_Q + t128_off(r, kc));
    }

    // ---- Hoisted ldsm base addresses (stage-relative) ----
    uint32_t koff[4];
    #pragma unroll
    for (int p = 0; p < 4; p++) {
        const int r = wn * 64 + p * 16 + ((mat >> 1) << 3) + l7;
        koff[p] = ST_KH + t128_off(r, (mat & 1) << 3);
    }
    const uint32_t voff0 = ST_VH +
        t128_off(wn * 64 + ((mat & 1) << 3) + l7, (mat >> 1) << 3);

    float mst[2], lst[2], oa[8][4];
    #pragma unroll
    for (int h2 = 0; h2 < 2; h2++) { mst[h2] = -1e30f; lst[h2] = 0.0f; }
    #pragma unroll
    for (int nt = 0; nt < 8; nt++)
        #pragma unroll
        for (int j = 0; j < 4; j++) oa[nt][j] = 0.0f;

    for (int kd = 0; kd <= kdmax; kd++) {
        const int st = kd & 1;
        cp_wait<0>();
        __syncthreads();                       // only barrier per tile
        if (kd < kdmax) prefetch(kd + 1, st ^ 1);

        const uint32_t stb = smb + ATT_ST + st * ATT_STG;

        // ---- S = Q @ K^T (warp: 16q x 64k, single product) ----
        float sc[8][4];
        #pragma unroll
        for (int nt = 0; nt < 8; nt++)
            #pragma unroll
            for (int j = 0; j < 4; j++) sc[nt][j] = 0.0f;

        #pragma unroll
        for (int k16 = 0; k16 < 4; k16++) {
            const uint32_t kx = (uint32_t)(k16 << 5);
            uint32_t bf[8][2];
            #pragma unroll
            for (int p = 0; p < 4; p++)
                ldsm_x4(bf[2*p][0], bf[2*p][1], bf[2*p+1][0], bf[2*p+1][1],
                        stb + (koff[p] ^ kx));
            #pragma unroll
            for (int nt = 0; nt < 8; nt++)
                mma_f16(sc[nt][0], sc[nt][1], sc[nt][2], sc[nt][3],
                        qa[k16][0], qa[k16][1], qa[k16][2], qa[k16][3],
                        bf[nt][0], bf[nt][1]);
        }

        // ---- Causal mask (diagonal tile only) ----
        if (kd == kdmax) {
            #pragma unroll
            for (int nt = 0; nt < 8; nt++)
                #pragma unroll
                for (int j = 0; j < 4; j++) {
                    const int grow = qt * 64 + wm * 16 + (j >> 1) * 8 + er;
                    const int gcol = kd * 128 + wn * 64 + nt * 8 + ec + (j & 1);
                    if (gcol > grow) sc[nt][j] = -1e30f;
                }
        }

        // ---- LOCAL row max (intra-warp only, no cross-warp exchange) ----
        float corr[2];
        #pragma unroll
        for (int h2 = 0; h2 < 2; h2++) {
            float mx = -1e30f;
            #pragma unroll
            for (int nt = 0; nt < 8; nt++) {
                mx = fmaxf(mx, sc[nt][2*h2]);
                mx = fmaxf(mx, sc[nt][2*h2+1]);
            }
            mx = fmaxf(mx, __shfl_xor_sync(0xffffffffu, mx, 1));
            mx = fmaxf(mx, __shfl_xor_sync(0xffffffffu, mx, 2));
            const float mnew = fmaxf(mst[h2], mx);
            corr[h2] = ex2f(mst[h2] - mnew);
            mst[h2] = mnew;
        }

        // ---- exp2 + local l ----
        {
            float psum[2] = {0.0f, 0.0f};
            #pragma unroll
            for (int nt = 0; nt < 8; nt++)
                #pragma unroll
                for (int j = 0; j < 4; j++) {
                    const int h2 = j >> 1;
                    const float pv = ex2f(sc[nt][j] - mst[h2]);
                    sc[nt][j] = pv;
                    psum[h2] += pv;
                }
            #pragma unroll
            for (int h2 = 0; h2 < 2; h2++) {
                float s = psum[h2];
                s += __shfl_xor_sync(0xffffffffu, s, 1);
                s += __shfl_xor_sync(0xffffffffu, s, 2);
                lst[h2] = lst[h2] * corr[h2] + s;
            }
            #pragma unroll
            for (int nt = 0; nt < 8; nt++)
                #pragma unroll
                for (int j = 0; j < 4; j++)
                    oa[nt][j] *= corr[j >> 1];
        }

        // ---- PV: P @ V (single product, fp16 P) ----
        #pragma unroll
        for (int kt2 = 0; kt2 < 4; kt2++) {
            uint32_t ah[4];
            #pragma unroll
            for (int q4 = 0; q4 < 4; q4++) {
                const int nt = 2 * kt2 + (q4 >> 1);
                const int j0 = (q4 & 1) * 2;
                ah[q4] = pack_h2(sc[nt][j0], sc[nt][j0 + 1]);
            }
            const uint32_t vb = stb + voff0 + (uint32_t)(kt2 * 2048);
            uint32_t bvh[8][2];
            #pragma unroll
            for (int ntp = 0; ntp < 4; ntp++)
                ldsm_x4_t(bvh[2*ntp][0], bvh[2*ntp][1], bvh[2*ntp+1][0], bvh[2*ntp+1][1],
                          vb ^ (uint32_t)(ntp << 5));
            #pragma unroll
            for (int nt = 0; nt < 8; nt++)
                mma_f16(oa[nt][0], oa[nt][1], oa[nt][2], oa[nt][3],
                        ah[0], ah[1], ah[2], ah[3], bvh[nt][0], bvh[nt][1]);
        }
    }

    // ---- Merge the two n-warp halves (scale by 2^(m_i - m)), write fp16 O --
    __syncthreads();
    float* ored = (float*)(sma + ATT_ST);     // 64 x 64 floats = 16KB
    if (wn == 1) {
        #pragma unroll
        for (int nt = 0; nt < 8; nt++)
            #pragma unroll
            for (int h2 = 0; h2 < 2; h2++) {
                const int row = wm * 16 + h2 * 8 + er;
                *(float2*)&ored[row * 64 + nt * 8 + ec] =
                    make_float2(oa[nt][2*h2], oa[nt][2*h2+1]);
            }
        if ((lane & 3) == 0) {
            #pragma unroll
            for (int h2 = 0; h2 < 2; h2++) {
                const int row = wm * 16 + h2 * 8 + er;
                lred[row] = lst[h2];
                mred[row] = mst[h2];
            }
        }
    }
    __syncthreads();
    if (wn == 0) {
        #pragma unroll
        for (int h2 = 0; h2 < 2; h2++) {
            const int row = wm * 16 + h2 * 8 + er;
            const float m1 = mred[row], l1 = lred[row];
            const float m  = fmaxf(mst[h2], m1);
            const float s0 = ex2f(mst[h2] - m);
            const float s1 = ex2f(m1 - m);
            const float inv = 1.0f / (lst[h2] * s0 + l1 * s1);
            const float f0 = s0 * inv, f1 = s1 * inv;
            const size_t go = (rowbase + qt * 64 + row) * DMODEL + h * DHEAD;
            #pragma unroll
            for (int nt = 0; nt < 8; nt++) {
                const float2 o2 = *(const float2*)&ored[row * 64 + nt * 8 + ec];
                const float wx = oa[nt][2*h2]     * f0 + o2.x * f1;
                const float wy = oa[nt][2*h2 + 1] * f0 + o2.y * f1;
                *(uint32_t*)(Oh + go + nt * 8 + ec) = pack_h2(wx, wy);
            }
        }
    }
}

// ===========================================================================
// kernel_launch
// ===========================================================================
extern "C" void kernel_launch(void* const* d_in, const int* in_sizes, int n_in,
                              void* d_out, int out_size)
{
    const float* hidden = (const float*)d_in[0];
    const float* Wqkv   = (const float*)d_in[2];
    const float* bqkv   = (const float*)d_in[3];
    const float* Wproj  = (const float*)d_in[4];
    const float* bproj  = (const float*)d_in[5];
    float* out = (float*)d_out;

    __half *Wh, *Xh, *Oh, *Q, *Kh, *Vh;
    cudaGetSymbolAddress((void**)&Wh, g_Wh);
    cudaGetSymbolAddress((void**)&Xh, g_Xh);
    cudaGetSymbolAddress((void**)&Oh, g_Oh);
    cudaGetSymbolAddress((void**)&Q,  g_Q);
    cudaGetSymbolAddress((void**)&Kh, g_Kh);
    cudaGetSymbolAddress((void**)&Vh, g_Vh);

    static bool attr_set = false;
    if (!attr_set) {
        cudaFuncSetAttribute(gemm_f16k, cudaFuncAttributeMaxDynamicSharedMemorySize,
                             GEMM_SMEM);
        cudaFuncSetAttribute(attn_mma, cudaFuncAttributeMaxDynamicSharedMemorySize,
                             ATT_SMEM);
        attr_set = true;
    }

    const int act4 = ROWS * DMODEL / 4;

    // ---- QKV projection (epilogue emits attention-native fp16 buffers) ----
    {
        dim3 gw(QKVDIM / 32, DMODEL / 32);
        transpose_h<<<gw, 256>>>(Wqkv, Wh, DMODEL, QKVDIM);
        conv_rows<<<(act4 + 255) / 256, 256>>>(hidden, Xh, act4);
        dim3 grid(QKVDIM / GBN, ROWS / GBM);   // (24, 32)
        gemm_f16k<<<grid, 256, GEMM_SMEM>>>(Xh, Wh, bqkv, nullptr,
                                            ROWS, QKVDIM, DMODEL, 1,
                                            Q, Kh, Vh);
    }

    // ---- Flash causal attention (split softmax, writes fp16 O) ----
    attn_mma<<<1024, 256, ATT_SMEM>>>(Q, Kh, Vh, Oh);

    // ---- Output projection ----
    {
        dim3 gw(DMODEL / 32, DMODEL / 32);
        transpose_h<<<gw, 256>>>(Wproj, Wh, DMODEL, DMODEL);
        dim3 grid(DMODEL / GBN, ROWS / GBM);   // (8, 32)
        gemm_f16k<<<grid, 256, GEMM_SMEM>>>(Oh, Wh, bproj, out,
                                            ROWS, DMODEL, DMODEL, 0,
                                            nullptr, nullptr, nullptr);
    }
}

// round 15
// speedup vs baseline: 20.2182x; 1.0505x over previous
#include <cuda_runtime.h>
#include <cuda_bf16.h>
#include <cuda_fp16.h>
#include <cstdint>

// Problem constants (fixed by the dataset)
#define BATCH 2
#define SEQ   2048
#define DMODEL 1024
#define NHEAD 16
#define DHEAD 64
#define QKVDIM (3 * NHEAD * DHEAD)   // 3072
#define ROWS  (BATCH * SEQ)          // 4096

#define QSCALE (0.125f * 1.44269504088896340736f)   // 1/sqrt(64) * log2(e)

// Scratch (allocation-free rule: __device__ globals)
__device__ __half g_Wh[(size_t)QKVDIM * DMODEL];    // Wqkv^T fp16
__device__ __half g_Wp[(size_t)DMODEL * DMODEL];    // Wproj^T fp16
__device__ __half g_Xh[(size_t)ROWS * DMODEL];      // hidden, fp16
__device__ __half g_Oh[(size_t)ROWS * DMODEL];      // attention out, fp16
__device__ __half g_Q [(size_t)ROWS * DMODEL];      // q, fp16, pre-scaled
__device__ __half g_Kh[(size_t)ROWS * DMODEL];      // k fp16
__device__ __half g_Vh[(size_t)ROWS * DMODEL];      // v fp16

// ===========================================================================
// Helpers
// ===========================================================================
__device__ __forceinline__ uint32_t smem_u32(const void* p) {
    uint32_t a;
    asm("{ .reg .u64 t; cvta.to.shared.u64 t, %1; cvt.u32.u64 %0, t; }"
        : "=r"(a) : "l"(p));
    return a;
}

__device__ __forceinline__ void cp_async16(uint32_t dst, const void* src) {
    asm volatile("cp.async.cg.shared.global [%0], [%1], 16;"
                 :: "r"(dst), "l"(src) : "memory");
}
__device__ __forceinline__ void cp_commit() {
    asm volatile("cp.async.commit_group;" ::: "memory");
}
template <int N>
__device__ __forceinline__ void cp_wait() {
    asm volatile("cp.async.wait_group %0;" :: "n"(N) : "memory");
}

__device__ __forceinline__ void ldsm_x4(uint32_t& r0, uint32_t& r1,
                                        uint32_t& r2, uint32_t& r3,
                                        uint32_t addr) {
    asm volatile("ldmatrix.sync.aligned.m8n8.x4.shared.b16 {%0,%1,%2,%3}, [%4];"
                 : "=r"(r0), "=r"(r1), "=r"(r2), "=r"(r3) : "r"(addr));
}

__device__ __forceinline__ void ldsm_x4_t(uint32_t& r0, uint32_t& r1,
                                          uint32_t& r2, uint32_t& r3,
                                          uint32_t addr) {
    asm volatile("ldmatrix.sync.aligned.m8n8.x4.trans.shared.b16 {%0,%1,%2,%3}, [%4];"
                 : "=r"(r0), "=r"(r1), "=r"(r2), "=r"(r3) : "r"(addr));
}

__device__ __forceinline__ void mma_f16(float& c0, float& c1, float& c2, float& c3,
                                        uint32_t a0, uint32_t a1, uint32_t a2, uint32_t a3,
                                        uint32_t b0, uint32_t b1) {
    asm volatile(
        "mma.sync.aligned.m16n8k16.row.col.f32.f16.f16.f32 "
        "{%0,%1,%2,%3}, {%4,%5,%6,%7}, {%8,%9}, {%0,%1,%2,%3};"
        : "+f"(c0), "+f"(c1), "+f"(c2), "+f"(c3)
        : "r"(a0), "r"(a1), "r"(a2), "r"(a3), "r"(b0), "r"(b1));
}

__device__ __forceinline__ float ex2f(float x) {
    float y;
    asm("ex2.approx.f32 %0, %1;" : "=f"(y) : "f"(x));
    return y;
}

__device__ __forceinline__ uint32_t pack_h2(float lo, float hi) {
    uint32_t d;
    asm("cvt.rn.f16x2.f32 %0, %1, %2;" : "=r"(d) : "f"(hi), "f"(lo));
    return d;
}
__device__ __forceinline__ float2 unpack_h2(uint32_t u) {
    __half2 hh = *reinterpret_cast<__half2*>(&u);
    return __half22float2(hh);
}

// 128B-row swizzled tile offset (row-stride 128B, 16B segs, xor phase r&7)
__device__ __forceinline__ uint32_t t128_off(int r, int c) {
    return (uint32_t)(r * 128 + ((((c >> 3) ^ (r & 7)) & 7) * 16) + ((c & 7) * 2));
}

// ===========================================================================
// Fused pre-processing: one launch.
//   blocks [0, 4096)        : hidden fp32 -> fp16 (Xh)
//   blocks [4096, 7168)     : Wqkv transpose+convert -> Wh [3072,1024]
//   blocks [7168, 8192)     : Wproj transpose+convert -> Wp [1024,1024]
// ===========================================================================
#define PREP_CONV_BLKS 4096
#define PREP_TQKV_BLKS 3072
#define PREP_BLKS (PREP_CONV_BLKS + PREP_TQKV_BLKS + 1024)

__global__ __launch_bounds__(256) void prep_all(
    const float* __restrict__ hidden, const float* __restrict__ Wqkv,
    const float* __restrict__ Wproj,
    __half* __restrict__ Xh, __half* __restrict__ Wh, __half* __restrict__ Wp)
{
    __shared__ float t[32][33];
    const int bid = blockIdx.x;
    const int tid = threadIdx.x;

    if (bid < PREP_CONV_BLKS) {
        const int i = bid * 256 + tid;          // f4 index, total 1048576
        float4 v = ((const float4*)hidden)[i];
        uint2 hh;
        hh.x = pack_h2(v.x, v.y);
        hh.y = pack_h2(v.z, v.w);
        *(uint2*)(Xh + (size_t)i * 4) = hh;
        return;
    }

    const float* in;
    __half* outp;
    int K, N, tb;
    if (bid < PREP_CONV_BLKS + PREP_TQKV_BLKS) {
        tb = bid - PREP_CONV_BLKS;
        in = Wqkv; outp = Wh; K = DMODEL; N = QKVDIM;     // tiles: 96 x 32
    } else {
        tb = bid - PREP_CONV_BLKS - PREP_TQKV_BLKS;
        in = Wproj; outp = Wp; K = DMODEL; N = DMODEL;    // tiles: 32 x 32
    }
    const int ntiles_x = N / 32;
    const int nb = (tb % ntiles_x) * 32;
    const int kb = (tb / ntiles_x) * 32;
    const int x = tid & 31;
    const int y = tid >> 5;
    #pragma unroll
    for (int i = 0; i < 32; i += 8)
        t[y + i][x] = in[(size_t)(kb + y + i) * N + nb + x];
    __syncthreads();
    #pragma unroll
    for (int i = 0; i < 32; i += 8)
        outp[(size_t)(nb + y + i) * K + kb + x] = __float2half(t[x][y + i]);
}

// ===========================================================================
// fp16 tensor-core GEMM: C = A @ B^T + bias (single product)
// CTA tile 128x128, BK=64, 8 warps (4m x 2n), cp.async double buffer,
// hoisted loader pointers + XOR-hoisted ldsm addressing.
// ===========================================================================
#define GBM 128
#define GBN 128
#define GBK 64
#define SB_A  0
#define SB_B  16384
#define SB_BUF 32768
#define GEMM_SMEM (2 * SB_BUF)

__global__ __launch_bounds__(256, 2)
void gemm_f16k(const __half* __restrict__ A, const __half* __restrict__ B,
               const float* __restrict__ bias, float* __restrict__ C,
               int M, int N, int K, int mode,
               __half* __restrict__ Qo,
               __half* __restrict__ Kho, __half* __restrict__ Vho)
{
    extern __shared__ char smg[];
    const uint32_t smb = smem_u32(smg);

    const int tid  = threadIdx.x;
    const int wid  = tid >> 5;
    const int lane = tid & 31;
    const int wm   = wid & 3;
    const int wn   = wid >> 2;
    const int m0 = blockIdx.y * GBM;
    const int n0 = blockIdx.x * GBN;
    const int NCH = K / GBK;

    const int mat = lane >> 3;
    const int l7  = lane & 7;

    // ---- hoisted loader state (row step 32 keeps r&7 invariant) ----
    const int lr0 = tid >> 3, lc0 = (tid & 7) * 8;
    const uint32_t loff0 = t128_off(lr0, lc0);
    const __half* Ap = A + (size_t)(m0 + lr0) * K + lc0;
    const __half* Bp = B + (size_t)(n0 + lr0) * K + lc0;
    const size_t K32 = (size_t)32 * K;

    auto load_chunk = [&](int b) {
        const uint32_t dst = smb + b * SB_BUF;
        #pragma unroll
        for (int t = 0; t < 4; t++) {
            const uint32_t off = loff0 + (uint32_t)(t * 4096);
            cp_async16(dst + SB_A + off, Ap + t * K32);
            cp_async16(dst + SB_B + off, Bp + t * K32);
        }
        cp_commit();
        Ap += GBK;
        Bp += GBK;
    };

    // ---- hoisted ldsm offsets: addr(ks) = base + (off0 ^ (ks<<5)) ----
    uint32_t aoff[2], boff[4];
    #pragma unroll
    for (int mt = 0; mt < 2; mt++) {
        const int r = wm * 32 + mt * 16 + ((mat & 1) << 3) + l7;
        aoff[mt] = SB_A + t128_off(r, (mat >> 1) << 3);
    }
    #pragma unroll
    for (int p = 0; p < 4; p++) {
        const int r = wn * 64 + p * 16 + ((mat >> 1) << 3) + l7;
        boff[p] = SB_B + t128_off(r, (mat & 1) << 3);
    }

    float acc[2][8][4];
    #pragma unroll
    for (int mt = 0; mt < 2; mt++)
        #pragma unroll
        for (int nt = 0; nt < 8; nt++)
            #pragma unroll
            for (int j = 0; j < 4; j++)
                acc[mt][nt][j] = 0.0f;

    load_chunk(0);

    for (int c = 0; c < NCH; c++) {
        const int b = c & 1;
        cp_wait<0>();
        __syncthreads();
        if (c + 1 < NCH) load_chunk(b ^ 1);

        const uint32_t base = smb + b * SB_BUF;

        #pragma unroll
        for (int ks = 0; ks < 4; ks++) {
            const uint32_t kx = (uint32_t)(ks << 5);

            uint32_t ah[2][4];
            #pragma unroll
            for (int mt = 0; mt < 2; mt++)
                ldsm_x4(ah[mt][0], ah[mt][1], ah[mt][2], ah[mt][3],
                        base + (aoff[mt] ^ kx));

            uint32_t bh[8][2];
            #pragma unroll
            for (int p = 0; p < 4; p++)
                ldsm_x4(bh[2*p][0], bh[2*p][1], bh[2*p+1][0], bh[2*p+1][1],
                        base + (boff[p] ^ kx));

            #pragma unroll
            for (int mt = 0; mt < 2; mt++)
                #pragma unroll
                for (int nt = 0; nt < 8; nt++)
                    mma_f16(acc[mt][nt][0], acc[mt][nt][1], acc[mt][nt][2], acc[mt][nt][3],
                            ah[mt][0], ah[mt][1], ah[mt][2], ah[mt][3],
                            bh[nt][0], bh[nt][1]);
        }
    }

    // Epilogue
    const int er = lane >> 2;
    const int ec = (lane & 3) * 2;
    if (mode == 0) {
        #pragma unroll
        for (int mt = 0; mt < 2; mt++) {
            #pragma unroll
            for (int nt = 0; nt < 8; nt++) {
                const int col = n0 + wn * 64 + nt * 8 + ec;
                const float b0 = bias[col], b1 = bias[col + 1];
                const int row0 = m0 + wm * 32 + mt * 16 + er;
                float2 v0 = make_float2(acc[mt][nt][0] + b0, acc[mt][nt][1] + b1);
                float2 v1 = make_float2(acc[mt][nt][2] + b0, acc[mt][nt][3] + b1);
                *(float2*)(C + (size_t)row0 * N + col)       = v0;
                *(float2*)(C + (size_t)(row0 + 8) * N + col) = v1;
            }
        }
    } else {
        const int sec = n0 >> 10;          // 0=Q, 1=K, 2=V
        __half* Ho = (sec == 1) ? Kho : Vho;
        #pragma unroll
        for (int mt = 0; mt < 2; mt++) {
            #pragma unroll
            for (int nt = 0; nt < 8; nt++) {
                const int col = n0 + wn * 64 + nt * 8 + ec;
                const int cloc = col & 1023;
                const float b0 = bias[col], b1 = bias[col + 1];
                const int row0 = m0 + wm * 32 + mt * 16 + er;
                const float x0 = acc[mt][nt][0] + b0, y0 = acc[mt][nt][1] + b1;
                const float x1 = acc[mt][nt][2] + b0, y1 = acc[mt][nt][3] + b1;
                if (sec == 0) {
                    *(uint32_t*)(Qo + (size_t)row0 * DMODEL + cloc)
                        = pack_h2(x0 * QSCALE, y0 * QSCALE);
                    *(uint32_t*)(Qo + (size_t)(row0 + 8) * DMODEL + cloc)
                        = pack_h2(x1 * QSCALE, y1 * QSCALE);
                } else {
                    *(uint32_t*)(Ho + (size_t)row0 * DMODEL + cloc) = pack_h2(x0, y0);
                    *(uint32_t*)(Ho + (size_t)(row0 + 8) * DMODEL + cloc) = pack_h2(x1, y1);
                }
            }
        }
    }
}

// ===========================================================================
// Tensor-core flash attention, 64-q-row CTAs, 2 CTAs/SM, split softmax,
// hoisted prefetch pointers (const-immediate smem/global offsets).
// smem: Q 8K | stage0 32K (K,V) | stage1 32K | lred 256B | mred 256B
// ===========================================================================
#define ATT_Q    0
#define ATT_ST   8192
#define ATT_STG  32768
#define ST_KH    0
#define ST_VH    16384
#define ATT_LRED (ATT_ST + 2 * ATT_STG)     // 73728
#define ATT_MRED (ATT_LRED + 256)
#define ATT_SMEM (ATT_MRED + 256)           // 74240

__global__ __launch_bounds__(256, 2) void attn_mma(
    const __half* __restrict__ Qg,
    const __half* __restrict__ Kh,
    const __half* __restrict__ Vh,
    __half* __restrict__ Oh)
{
    extern __shared__ char sma[];
    const uint32_t smb = smem_u32(sma);
    float* lred = (float*)(sma + ATT_LRED);
    float* mred = (float*)(sma + ATT_MRED);

    const int bid = blockIdx.x;
    const int qt  = 31 - (bid >> 5);          // 64-row q tile, heavy first
    const int bh  = bid & 31;
    const int b   = bh >> 4;
    const int h   = bh & 15;
    const int kdmax = qt >> 1;                // last 128-key tile index

    const int tid  = threadIdx.x;
    const int wid  = tid >> 5;
    const int lane = tid & 31;
    const int wm   = wid & 3;                 // q rows wm*16
    const int wn   = wid >> 2;                // keys wn*64
    const int mat  = lane >> 3;
    const int l7   = lane & 7;
    const int er   = lane >> 2;
    const int ec   = (lane & 3) * 2;

    const size_t rowbase = (size_t)b * SEQ;

    // ---- hoisted prefetch state (row step 32 keeps r&7 invariant) ----
    const int pr0 = tid >> 3, pg0 = tid & 7;
    const uint32_t psw0 = (uint32_t)(pr0 * 128) + (((pg0 ^ (pr0 & 7)) & 7) * 16);
    const __half* kp = Kh + (rowbase + pr0) * DMODEL + h * DHEAD + pg0 * 8;
    const __half* vp = Vh + (rowbase + pr0) * DMODEL + h * DHEAD + pg0 * 8;
    const size_t D32 = (size_t)32 * DMODEL;

    auto prefetch = [&](int st) {
        const uint32_t dst = smb + ATT_ST + st * ATT_STG;
        #pragma unroll
        for (int it = 0; it < 4; it++) {
            const uint32_t sw = psw0 + (uint32_t)(it * 4096);
            cp_async16(dst + ST_KH + sw, kp + it * D32);
            cp_async16(dst + ST_VH + sw, vp + it * D32);
        }
        cp_commit();
        kp += 4 * D32;      // advance 128 key rows
        vp += 4 * D32;
    };

    // ---- Load Q tile (64 rows) ----
    #pragma unroll
    for (int it = 0; it < 2; it++) {
        const int t = tid + it * 256;
        const int r = t >> 3, g = t & 7;
        const uint32_t sw = (uint32_t)(r * 128) + (((g ^ (r & 7)) & 7) * 16);
        uint4 v = *(const uint4*)(Qg + (rowbase + qt * 64 + r) * DMODEL + h * DHEAD + g * 8);
        *(uint4*)(sma + ATT_Q + sw) = v;
    }
    prefetch(0);
    __syncthreads();

    // ---- Q A-fragments (persistent): 16 q-rows per warp ----
    uint32_t qa[4][4];
    #pragma unroll
    for (int k16 = 0; k16 < 4; k16++) {
        const int r  = wm * 16 + ((mat & 1) << 3) + l7;
        const int kc = k16 * 16 + ((mat >> 1) << 3);
        ldsm_x4(qa[k16][0], qa[k16][1], qa[k16][2], qa[k16][3],
                smb + ATT_Q + t128_off(r, kc));
    }

    // ---- Hoisted ldsm base addresses (stage-relative) ----
    uint32_t koff[4];
    #pragma unroll
    for (int p = 0; p < 4; p++) {
        const int r = wn * 64 + p * 16 + ((mat >> 1) << 3) + l7;
        koff[p] = ST_KH + t128_off(r, (mat & 1) << 3);
    }
    const uint32_t voff0 = ST_VH +
        t128_off(wn * 64 + ((mat & 1) << 3) + l7, (mat >> 1) << 3);

    float mst[2], lst[2], oa[8][4];
    #pragma unroll
    for (int h2 = 0; h2 < 2; h2++) { mst[h2] = -1e30f; lst[h2] = 0.0f; }
    #pragma unroll
    for (int nt = 0; nt < 8; nt++)
        #pragma unroll
        for (int j = 0; j < 4; j++) oa[nt][j] = 0.0f;

    for (int kd = 0; kd <= kdmax; kd++) {
        const int st = kd & 1;
        cp_wait<0>();
        __syncthreads();                       // only barrier per tile
        if (kd < kdmax) prefetch(st ^ 1);

        const uint32_t stb = smb + ATT_ST + st * ATT_STG;

        // ---- S = Q @ K^T (warp: 16q x 64k, single product) ----
        float sc[8][4];
        #pragma unroll
        for (int nt = 0; nt < 8; nt++)
            #pragma unroll
            for (int j = 0; j < 4; j++) sc[nt][j] = 0.0f;

        #pragma unroll
        for (int k16 = 0; k16 < 4; k16++) {
            const uint32_t kx = (uint32_t)(k16 << 5);
            uint32_t bf[8][2];
            #pragma unroll
            for (int p = 0; p < 4; p++)
                ldsm_x4(bf[2*p][0], bf[2*p][1], bf[2*p+1][0], bf[2*p+1][1],
                        stb + (koff[p] ^ kx));
            #pragma unroll
            for (int nt = 0; nt < 8; nt++)
                mma_f16(sc[nt][0], sc[nt][1], sc[nt][2], sc[nt][3],
                        qa[k16][0], qa[k16][1], qa[k16][2], qa[k16][3],
                        bf[nt][0], bf[nt][1]);
        }

        // ---- Causal mask (diagonal tile only) ----
        if (kd == kdmax) {
            #pragma unroll
            for (int nt = 0; nt < 8; nt++)
                #pragma unroll
                for (int j = 0; j < 4; j++) {
                    const int grow = qt * 64 + wm * 16 + (j >> 1) * 8 + er;
                    const int gcol = kd * 128 + wn * 64 + nt * 8 + ec + (j & 1);
                    if (gcol > grow) sc[nt][j] = -1e30f;
                }
        }

        // ---- LOCAL row max (intra-warp only) ----
        float corr[2];
        #pragma unroll
        for (int h2 = 0; h2 < 2; h2++) {
            float mx = -1e30f;
            #pragma unroll
            for (int nt = 0; nt < 8; nt++) {
                mx = fmaxf(mx, sc[nt][2*h2]);
                mx = fmaxf(mx, sc[nt][2*h2+1]);
            }
            mx = fmaxf(mx, __shfl_xor_sync(0xffffffffu, mx, 1));
            mx = fmaxf(mx, __shfl_xor_sync(0xffffffffu, mx, 2));
            const float mnew = fmaxf(mst[h2], mx);
            corr[h2] = ex2f(mst[h2] - mnew);
            mst[h2] = mnew;
        }

        // ---- exp2 + local l ----
        {
            float psum[2] = {0.0f, 0.0f};
            #pragma unroll
            for (int nt = 0; nt < 8; nt++)
                #pragma unroll
                for (int j = 0; j < 4; j++) {
                    const int h2 = j >> 1;
                    const float pv = ex2f(sc[nt][j] - mst[h2]);
                    sc[nt][j] = pv;
                    psum[h2] += pv;
                }
            #pragma unroll
            for (int h2 = 0; h2 < 2; h2++) {
                float s = psum[h2];
                s += __shfl_xor_sync(0xffffffffu, s, 1);
                s += __shfl_xor_sync(0xffffffffu, s, 2);
                lst[h2] = lst[h2] * corr[h2] + s;
            }
            #pragma unroll
            for (int nt = 0; nt < 8; nt++)
                #pragma unroll
                for (int j = 0; j < 4; j++)
                    oa[nt][j] *= corr[j >> 1];
        }

        // ---- PV: P @ V (single product, fp16 P) ----
        #pragma unroll
        for (int kt2 = 0; kt2 < 4; kt2++) {
            uint32_t ah[4];
            #pragma unroll
            for (int q4 = 0; q4 < 4; q4++) {
                const int nt = 2 * kt2 + (q4 >> 1);
                const int j0 = (q4 & 1) * 2;
                ah[q4] = pack_h2(sc[nt][j0], sc[nt][j0 + 1]);
            }
            const uint32_t vb = stb + voff0 + (uint32_t)(kt2 * 2048);
            uint32_t bvh[8][2];
            #pragma unroll
            for (int ntp = 0; ntp < 4; ntp++)
                ldsm_x4_t(bvh[2*ntp][0], bvh[2*ntp][1], bvh[2*ntp+1][0], bvh[2*ntp+1][1],
                          vb ^ (uint32_t)(ntp << 5));
            #pragma unroll
            for (int nt = 0; nt < 8; nt++)
                mma_f16(oa[nt][0], oa[nt][1], oa[nt][2], oa[nt][3],
                        ah[0], ah[1], ah[2], ah[3], bvh[nt][0], bvh[nt][1]);
        }
    }

    // ---- Merge the two n-warp halves (scale by 2^(m_i - m)), write fp16 O --
    __syncthreads();
    float* ored = (float*)(sma + ATT_ST);     // 64 x 64 floats = 16KB
    if (wn == 1) {
        #pragma unroll
        for (int nt = 0; nt < 8; nt++)
            #pragma unroll
            for (int h2 = 0; h2 < 2; h2++) {
                const int row = wm * 16 + h2 * 8 + er;
                *(float2*)&ored[row * 64 + nt * 8 + ec] =
                    make_float2(oa[nt][2*h2], oa[nt][2*h2+1]);
            }
        if ((lane & 3) == 0) {
            #pragma unroll
            for (int h2 = 0; h2 < 2; h2++) {
                const int row = wm * 16 + h2 * 8 + er;
                lred[row] = lst[h2];
                mred[row] = mst[h2];
            }
        }
    }
    __syncthreads();
    if (wn == 0) {
        #pragma unroll
        for (int h2 = 0; h2 < 2; h2++) {
            const int row = wm * 16 + h2 * 8 + er;
            const float m1 = mred[row], l1 = lred[row];
            const float m  = fmaxf(mst[h2], m1);
            const float s0 = ex2f(mst[h2] - m);
            const float s1 = ex2f(m1 - m);
            const float inv = 1.0f / (lst[h2] * s0 + l1 * s1);
            const float f0 = s0 * inv, f1 = s1 * inv;
            const size_t go = (rowbase + qt * 64 + row) * DMODEL + h * DHEAD;
            #pragma unroll
            for (int nt = 0; nt < 8; nt++) {
                const float2 o2 = *(const float2*)&ored[row * 64 + nt * 8 + ec];
                const float wx = oa[nt][2*h2]     * f0 + o2.x * f1;
                const float wy = oa[nt][2*h2 + 1] * f0 + o2.y * f1;
                *(uint32_t*)(Oh + go + nt * 8 + ec) = pack_h2(wx, wy);
            }
        }
    }
}

// ===========================================================================
// kernel_launch
// ===========================================================================
extern "C" void kernel_launch(void* const* d_in, const int* in_sizes, int n_in,
                              void* d_out, int out_size)
{
    const float* hidden = (const float*)d_in[0];
    const float* Wqkv   = (const float*)d_in[2];
    const float* bqkv   = (const float*)d_in[3];
    const float* Wproj  = (const float*)d_in[4];
    const float* bproj  = (const float*)d_in[5];
    float* out = (float*)d_out;

    __half *Wh, *Wp, *Xh, *Oh, *Q, *Kh, *Vh;
    cudaGetSymbolAddress((void**)&Wh, g_Wh);
    cudaGetSymbolAddress((void**)&Wp, g_Wp);
    cudaGetSymbolAddress((void**)&Xh, g_Xh);
    cudaGetSymbolAddress((void**)&Oh, g_Oh);
    cudaGetSymbolAddress((void**)&Q,  g_Q);
    cudaGetSymbolAddress((void**)&Kh, g_Kh);
    cudaGetSymbolAddress((void**)&Vh, g_Vh);

    static bool attr_set = false;
    if (!attr_set) {
        cudaFuncSetAttribute(gemm_f16k, cudaFuncAttributeMaxDynamicSharedMemorySize,
                             GEMM_SMEM);
        cudaFuncSetAttribute(attn_mma, cudaFuncAttributeMaxDynamicSharedMemorySize,
                             ATT_SMEM);
        attr_set = true;
    }

    // ---- Fused prep: hidden->fp16, both weight transposes (one launch) ----
    prep_all<<<PREP_BLKS, 256>>>(hidden, Wqkv, Wproj, Xh, Wh, Wp);

    // ---- QKV projection (epilogue emits attention-native fp16 buffers) ----
    {
        dim3 grid(QKVDIM / GBN, ROWS / GBM);   // (24, 32)
        gemm_f16k<<<grid, 256, GEMM_SMEM>>>(Xh, Wh, bqkv, nullptr,
                                            ROWS, QKVDIM, DMODEL, 1,
                                            Q, Kh, Vh);
    }

    // ---- Flash causal attention (split softmax, writes fp16 O) ----
    attn_mma<<<1024, 256, ATT_SMEM>>>(Q, Kh, Vh, Oh);

    // ---- Output projection ----
    {
        dim3 grid(DMODEL / GBN, ROWS / GBM);   // (8, 32)
        gemm_f16k<<<grid, 256, GEMM_SMEM>>>(Oh, Wp, bproj, out,
                                            ROWS, DMODEL, DMODEL, 0,
                                            nullptr, nullptr, nullptr);
    }
}